// round 4
// baseline (speedup 1.0000x reference)
#include <cuda_runtime.h>

#define B_ 8
#define N_ 1024
#define C_ 768
#define H_ 12
#define HD 64
#define M_TOT (B_*N_)    // 8192
#define QKV_N (3*C_)     // 2304
#define EPS 1e-6f
#define EPSN (1e-6f/1024.0f)
#define SC2E 0.18033688011112042f   // (1/sqrt(64)) * log2(e)

// ---------------------------------------------------------------------------
// packed f32x2 helpers (Blackwell fp32x2 pipe — 2 FMA per instruction)
// ---------------------------------------------------------------------------
__device__ __forceinline__ float2 ffma2(float2 a, float2 b, float2 c) {
    union U { float2 f; unsigned long long u; };
    U A, Bx, Cx, D; A.f = a; Bx.f = b; Cx.f = c;
    asm("fma.rn.f32x2 %0, %1, %2, %3;" : "=l"(D.u) : "l"(A.u), "l"(Bx.u), "l"(Cx.u));
    return D.f;
}
__device__ __forceinline__ float2 add2(float2 a, float2 b) {
    union U { float2 f; unsigned long long u; };
    U A, Bx, D; A.f = a; Bx.f = b;
    asm("add.rn.f32x2 %0, %1, %2;" : "=l"(D.u) : "l"(A.u), "l"(Bx.u));
    return D.f;
}
__device__ __forceinline__ float2 mul2(float2 a, float2 b) {
    union U { float2 f; unsigned long long u; };
    U A, Bx, D; A.f = a; Bx.f = b;
    asm("mul.rn.f32x2 %0, %1, %2;" : "=l"(D.u) : "l"(A.u), "l"(Bx.u));
    return D.f;
}

// 2^x via FFMA-pipe polynomial (keeps MUFU free; rel err ~3e-6). x <= ~0.
__device__ __forceinline__ float exp2_fast(float x) {
    float t = fmaxf(x, -80.f);
    float z = t + 12582912.f;              // 1.5*2^23: round-to-nearest trick
    int   n = __float_as_int(z) - 0x4B400000;
    float f = t - (z - 12582912.f);        // f in [-0.5, 0.5]
    float p = 1.3333558e-3f;
    p = fmaf(p, f, 9.618129e-3f);
    p = fmaf(p, f, 5.5504109e-2f);
    p = fmaf(p, f, 2.4022651e-1f);
    p = fmaf(p, f, 6.9314718e-1f);
    p = fmaf(p, f, 1.0f);
    return __int_as_float(__float_as_int(p) + (n << 23));
}

// Scratch
__device__ float g_q[B_*H_*N_*HD];     // (B,H,N,64)
__device__ float g_k[B_*H_*N_*HD];
__device__ float g_v[B_*H_*N_*HD];
__device__ float g_aout[M_TOT*C_];     // (B,N,C)

// ---------------------------------------------------------------------------
// GEMM core: 64x64 tile, BK=16, 256 threads, 4x4 micro (strided tx+16j),
// FFMA2 packed along K. As/Bs pitch 18 -> conflict-free strided row reads.
// ---------------------------------------------------------------------------
#define GP 18

// QKV GEMM + scatter to (B,H,N,64)
__global__ __launch_bounds__(256) void qkv_gemm_kernel(const float* __restrict__ x,
                                                       const float* __restrict__ W) {
    __shared__ float As[64*GP];
    __shared__ float Bs[64*GP];
    const int bm = blockIdx.y * 64;
    const int bn = blockIdx.x * 64;
    const int tid = threadIdx.x;
    const int tx = tid & 15, ty = tid >> 4;
    const int r  = tid >> 2, c4 = tid & 3;          // loader mapping

    const float* gA = x + (bm + r) * C_ + c4 * 4;
    const float* gB = W + (bn + r) * C_ + c4 * 4;
    float4 ra = *(const float4*)gA;
    float4 rb = *(const float4*)gB;

    float2 acc[4][4];
    #pragma unroll
    for (int i = 0; i < 4; i++)
        #pragma unroll
        for (int j = 0; j < 4; j++) acc[i][j] = make_float2(0.f, 0.f);

    for (int k0 = 0; k0 < C_; k0 += 16) {
        const int sb = r * GP + c4 * 4;
        As[sb+0] = ra.x; As[sb+1] = ra.y; As[sb+2] = ra.z; As[sb+3] = ra.w;
        Bs[sb+0] = rb.x; Bs[sb+1] = rb.y; Bs[sb+2] = rb.z; Bs[sb+3] = rb.w;
        __syncthreads();
        if (k0 + 16 < C_) {
            ra = *(const float4*)(gA + k0 + 16);
            rb = *(const float4*)(gB + k0 + 16);
        }
        #pragma unroll
        for (int kk = 0; kk < 8; kk++) {
            float2 a2[4], b2[4];
            #pragma unroll
            for (int i = 0; i < 4; i++) a2[i] = *(const float2*)&As[(ty + 16*i)*GP + kk*2];
            #pragma unroll
            for (int j = 0; j < 4; j++) b2[j] = *(const float2*)&Bs[(tx + 16*j)*GP + kk*2];
            #pragma unroll
            for (int i = 0; i < 4; i++)
                #pragma unroll
                for (int j = 0; j < 4; j++) acc[i][j] = ffma2(a2[i], b2[j], acc[i][j]);
        }
        __syncthreads();
    }

    const int which = bn / C_;                 // 0=q,1=k,2=v
    const int h = (bn - which * C_) >> 6;
    float* dst = (which == 0) ? g_q : (which == 1) ? g_k : g_v;
    #pragma unroll
    for (int i = 0; i < 4; i++) {
        const int m = bm + ty + 16*i;
        const int b = m >> 10, n = m & 1023;
        float* row = dst + (((b*H_ + h) * N_) + n) * HD;
        #pragma unroll
        for (int j = 0; j < 4; j++) row[tx + 16*j] = acc[i][j].x + acc[i][j].y;
    }
}

// Output projection
__global__ __launch_bounds__(256) void proj_gemm_kernel(const float* __restrict__ W,
                                                        const float* __restrict__ bias,
                                                        float* __restrict__ out) {
    __shared__ float As[64*GP];
    __shared__ float Bs[64*GP];
    const int bm = blockIdx.y * 64;
    const int bn = blockIdx.x * 64;
    const int tid = threadIdx.x;
    const int tx = tid & 15, ty = tid >> 4;
    const int r  = tid >> 2, c4 = tid & 3;

    const float* gA = g_aout + (bm + r) * C_ + c4 * 4;
    const float* gB = W + (bn + r) * C_ + c4 * 4;
    float4 ra = *(const float4*)gA;
    float4 rb = *(const float4*)gB;

    float2 acc[4][4];
    #pragma unroll
    for (int i = 0; i < 4; i++)
        #pragma unroll
        for (int j = 0; j < 4; j++) acc[i][j] = make_float2(0.f, 0.f);

    for (int k0 = 0; k0 < C_; k0 += 16) {
        const int sb = r * GP + c4 * 4;
        As[sb+0] = ra.x; As[sb+1] = ra.y; As[sb+2] = ra.z; As[sb+3] = ra.w;
        Bs[sb+0] = rb.x; Bs[sb+1] = rb.y; Bs[sb+2] = rb.z; Bs[sb+3] = rb.w;
        __syncthreads();
        if (k0 + 16 < C_) {
            ra = *(const float4*)(gA + k0 + 16);
            rb = *(const float4*)(gB + k0 + 16);
        }
        #pragma unroll
        for (int kk = 0; kk < 8; kk++) {
            float2 a2[4], b2[4];
            #pragma unroll
            for (int i = 0; i < 4; i++) a2[i] = *(const float2*)&As[(ty + 16*i)*GP + kk*2];
            #pragma unroll
            for (int j = 0; j < 4; j++) b2[j] = *(const float2*)&Bs[(tx + 16*j)*GP + kk*2];
            #pragma unroll
            for (int i = 0; i < 4; i++)
                #pragma unroll
                for (int j = 0; j < 4; j++) acc[i][j] = ffma2(a2[i], b2[j], acc[i][j]);
        }
        __syncthreads();
    }

    #pragma unroll
    for (int i = 0; i < 4; i++) {
        const int m = bm + ty + 16*i;
        #pragma unroll
        for (int j = 0; j < 4; j++) {
            const int col = bn + tx + 16*j;
            out[m * C_ + col] = acc[i][j].x + acc[i][j].y + bias[col];
        }
    }
}

// ---------------------------------------------------------------------------
// Policy-masked flash attention, log2-domain softmax, FFMA2 everywhere.
// Block = (64-query tile, b*H+h). 256 threads: thread = (tx,ty),
//   S phase:  q rows {ty+16i}, keys {tx+16j}   (packed along d)
//   PV phase: q rows {ty+16i}, dims {tx+16j}   (packed along key, V transposed)
// smem (floats): Qs[64*66] Ks[64*66] VsT[64*66] Ps[64*64] = 67072 B dynamic.
// ---------------------------------------------------------------------------
#define AP 66
__global__ __launch_bounds__(256) void attn_kernel(const float* __restrict__ policy) {
    extern __shared__ float smem[];
    float* Qs  = smem;                 // [q][d]   pitch 66
    float* Ks  = smem + 64*AP;         // [key][d] pitch 66
    float* VsT = smem + 2*64*AP;       // [d][key] pitch 66
    float* Ps  = smem + 3*64*AP;       // [q][key] pitch 64

    const int qt = blockIdx.x;         // 0..15
    const int bh = blockIdx.y;         // 0..95
    const int b  = bh / H_;
    const int h  = bh - b * H_;
    const int tid = threadIdx.x;
    const int tx = tid & 15, ty = tid >> 4;

    const int qbase = (bh * N_ + qt * 64) * HD;
    const int lr = tid >> 4;           // 0..15 (loader row base)
    const int ld4 = tid & 15;

    // Q tile (scaled by scale*log2e)
    #pragma unroll
    for (int it = 0; it < 4; it++) {
        const int rr = lr + 16*it;
        float4 v = *(const float4*)(g_q + qbase + rr*HD + ld4*4);
        float* d = &Qs[rr*AP + ld4*4];
        d[0] = v.x*SC2E; d[1] = v.y*SC2E; d[2] = v.z*SC2E; d[3] = v.w*SC2E;
    }

    float polq[4];
    #pragma unroll
    for (int i = 0; i < 4; i++) polq[i] = policy[b*N_ + qt*64 + ty + 16*i];

    float m_[4], l_[4];
    float2 O2[4][4], vsum2[4];
    #pragma unroll
    for (int i = 0; i < 4; i++) { m_[i] = -1e30f; l_[i] = 0.f; }
    #pragma unroll
    for (int i = 0; i < 4; i++)
        #pragma unroll
        for (int j = 0; j < 4; j++) O2[i][j] = make_float2(0.f, 0.f);
    #pragma unroll
    for (int j = 0; j < 4; j++) vsum2[j] = make_float2(0.f, 0.f);

    for (int kt = 0; kt < 16; kt++) {
        const int kbase = (bh * N_ + kt * 64) * HD;
        // K natural, V transposed into smem
        #pragma unroll
        for (int it = 0; it < 4; it++) {
            const int rr = lr + 16*it;
            float4 kv = *(const float4*)(g_k + kbase + rr*HD + ld4*4);
            float* d = &Ks[rr*AP + ld4*4];
            d[0] = kv.x; d[1] = kv.y; d[2] = kv.z; d[3] = kv.w;
            float4 vv = *(const float4*)(g_v + kbase + rr*HD + ld4*4);
            VsT[(ld4*4+0)*AP + rr] = vv.x;
            VsT[(ld4*4+1)*AP + rr] = vv.y;
            VsT[(ld4*4+2)*AP + rr] = vv.z;
            VsT[(ld4*4+3)*AP + rr] = vv.w;
        }
        float polk[4];
        #pragma unroll
        for (int j = 0; j < 4; j++) polk[j] = policy[b*N_ + kt*64 + tx + 16*j];
        __syncthreads();

        // S = Q K^T (log2 units), packed along d
        float2 S2[4][4];
        #pragma unroll
        for (int i = 0; i < 4; i++)
            #pragma unroll
            for (int j = 0; j < 4; j++) S2[i][j] = make_float2(0.f, 0.f);
        #pragma unroll
        for (int d2 = 0; d2 < 32; d2++) {
            float2 q2[4], k2[4];
            #pragma unroll
            for (int i = 0; i < 4; i++) q2[i] = *(const float2*)&Qs[(ty + 16*i)*AP + d2*2];
            #pragma unroll
            for (int j = 0; j < 4; j++) k2[j] = *(const float2*)&Ks[(tx + 16*j)*AP + d2*2];
            #pragma unroll
            for (int i = 0; i < 4; i++)
                #pragma unroll
                for (int j = 0; j < 4; j++) S2[i][j] = ffma2(q2[i], k2[j], S2[i][j]);
        }
        float S[4][4];
        #pragma unroll
        for (int i = 0; i < 4; i++)
            #pragma unroll
            for (int j = 0; j < 4; j++) S[i][j] = S2[i][j].x + S2[i][j].y;

        // unmasked running max (log2 domain), rescale
        float mnew[4], resc[4];
        #pragma unroll
        for (int i = 0; i < 4; i++) {
            float t = fmaxf(fmaxf(S[i][0], S[i][1]), fmaxf(S[i][2], S[i][3]));
            t = fmaxf(t, __shfl_xor_sync(0xffffffffu, t, 1));
            t = fmaxf(t, __shfl_xor_sync(0xffffffffu, t, 2));
            t = fmaxf(t, __shfl_xor_sync(0xffffffffu, t, 4));
            t = fmaxf(t, __shfl_xor_sync(0xffffffffu, t, 8));
            mnew[i] = fmaxf(m_[i], t);
            resc[i] = exp2_fast(m_[i] - mnew[i]);
        }

        // P = 2^(S-m) * mask
        float psum[4];
        #pragma unroll
        for (int i = 0; i < 4; i++) {
            const int nq = qt*64 + ty + 16*i;
            psum[i] = 0.f;
            #pragma unroll
            for (int j = 0; j < 4; j++) {
                const int mk = kt*64 + tx + 16*j;
                const float mask = (mk == nq) ? 1.0f : polq[i] * polk[j];
                const float p = exp2_fast(S[i][j] - mnew[i]) * mask;
                psum[i] += p;
                Ps[(ty + 16*i)*64 + tx + 16*j] = p;
            }
        }
        #pragma unroll
        for (int i = 0; i < 4; i++) {
            float s = psum[i];
            s += __shfl_xor_sync(0xffffffffu, s, 1);
            s += __shfl_xor_sync(0xffffffffu, s, 2);
            s += __shfl_xor_sync(0xffffffffu, s, 4);
            s += __shfl_xor_sync(0xffffffffu, s, 8);
            l_[i] = l_[i] * resc[i] + s;
            m_[i] = mnew[i];
            const float2 r2 = make_float2(resc[i], resc[i]);
            #pragma unroll
            for (int j = 0; j < 4; j++) O2[i][j] = mul2(O2[i][j], r2);
        }
        __syncthreads();   // Ps ready

        // O += P V, packed along key; vsum += V rowsum
        #pragma unroll
        for (int k2i = 0; k2i < 32; k2i++) {
            float2 p2[4], v2[4];
            #pragma unroll
            for (int i = 0; i < 4; i++) p2[i] = *(const float2*)&Ps[(ty + 16*i)*64 + k2i*2];
            #pragma unroll
            for (int j = 0; j < 4; j++) v2[j] = *(const float2*)&VsT[(tx + 16*j)*AP + k2i*2];
            #pragma unroll
            for (int j = 0; j < 4; j++) vsum2[j] = add2(vsum2[j], v2[j]);
            #pragma unroll
            for (int i = 0; i < 4; i++)
                #pragma unroll
                for (int j = 0; j < 4; j++) O2[i][j] = ffma2(p2[i], v2[j], O2[i][j]);
        }
        __syncthreads();   // before tiles/Ps overwritten
    }

    #pragma unroll
    for (int i = 0; i < 4; i++) {
        const float inv = 1.0f / (l_[i] + EPS);
        float* row = g_aout + (b*N_ + qt*64 + ty + 16*i) * C_ + h * HD;
        #pragma unroll
        for (int j = 0; j < 4; j++) {
            const float vs = vsum2[j].x + vsum2[j].y;
            row[tx + 16*j] = (O2[i][j].x + O2[i][j].y + EPSN * vs) * inv;
        }
    }
}

// ---------------------------------------------------------------------------
extern "C" void kernel_launch(void* const* d_in, const int* in_sizes, int n_in,
                              void* d_out, int out_size) {
    const float* x      = (const float*)d_in[0];
    const float* policy = (const float*)d_in[1];
    const float* Wqkv   = (const float*)d_in[2];
    const float* Wproj  = (const float*)d_in[3];
    const float* bproj  = (const float*)d_in[4];
    float* out = (float*)d_out;

    qkv_gemm_kernel<<<dim3(QKV_N/64, M_TOT/64), 256>>>(x, Wqkv);

    cudaFuncSetAttribute(attn_kernel,
                         cudaFuncAttributeMaxDynamicSharedMemorySize, 67072);
    attn_kernel<<<dim3(16, 96), 256, 67072>>>(policy);

    proj_gemm_kernel<<<dim3(C_/64, M_TOT/64), 256>>>(Wproj, bproj, out);
}

// round 6
// speedup vs baseline: 1.5941x; 1.5941x over previous
#include <cuda_runtime.h>
#include <cuda_bf16.h>
#include <cstdint>

#define B_ 8
#define N_ 1024
#define C_ 768
#define H_ 12
#define HD 64
#define M_TOT (B_*N_)
#define QKV_N (3*C_)
#define EPS 1e-6f
#define EPSN (1e-6f/1024.0f)
#define SC2E 0.18033688011112042f
#define SWZ(b) ((b) ^ (((b) >> 3) & 0x70))

__device__ __forceinline__ uint32_t smem_to_u32(const void* p) {
    uint32_t a;
    asm("{ .reg .u64 t; cvta.to.shared.u64 t, %1; cvt.u32.u64 %0, t; }" : "=r"(a) : "l"(p));
    return a;
}
__device__ __forceinline__ void cpa16(uint32_t dst, const void* src) {
    asm volatile("cp.async.cg.shared.global [%0], [%1], 16;" :: "r"(dst), "l"(src));
}
#define LDM4(r, a) \
    asm volatile("ldmatrix.sync.aligned.m8n8.x4.shared.b16 {%0,%1,%2,%3}, [%4];" \
        : "=r"((r)[0]), "=r"((r)[1]), "=r"((r)[2]), "=r"((r)[3]) : "r"(a))
#define MMA16816(d, a, b0, b1) \
    asm volatile("mma.sync.aligned.m16n8k16.row.col.f32.bf16.bf16.f32 " \
        "{%0,%1,%2,%3}, {%4,%5,%6,%7}, {%8,%9}, {%0,%1,%2,%3};" \
        : "+f"((d)[0]), "+f"((d)[1]), "+f"((d)[2]), "+f"((d)[3]) \
        : "r"((a)[0]), "r"((a)[1]), "r"((a)[2]), "r"((a)[3]), "r"(b0), "r"(b1))

// --------------------------- scratch ---------------------------------------
__device__ float g_q[B_*H_*N_*HD];
__device__ float g_k[B_*H_*N_*HD];
__device__ float g_v[B_*H_*N_*HD];
__device__ float g_aout[M_TOT*C_];
__device__ __nv_bfloat16 g_xh[M_TOT*C_],  g_xl[M_TOT*C_];
__device__ __nv_bfloat16 g_wqh[QKV_N*C_], g_wql[QKV_N*C_];
__device__ __nv_bfloat16 g_wph[C_*C_],    g_wpl[C_*C_];
__device__ __nv_bfloat16 g_ah[M_TOT*C_],  g_al[M_TOT*C_];

// ---------------------- fp32 -> bf16 hi/lo split ----------------------------
__global__ __launch_bounds__(256) void split_kernel(const float* __restrict__ in,
                                                    __nv_bfloat16* __restrict__ hi,
                                                    __nv_bfloat16* __restrict__ lo, int n4) {
    int i = blockIdx.x * 256 + threadIdx.x;
    if (i >= n4) return;
    float4 v = ((const float4*)in)[i];
    __nv_bfloat16 h0 = __float2bfloat16(v.x), h1 = __float2bfloat16(v.y);
    __nv_bfloat16 h2 = __float2bfloat16(v.z), h3 = __float2bfloat16(v.w);
    __nv_bfloat16 l0 = __float2bfloat16(v.x - __bfloat162float(h0));
    __nv_bfloat16 l1 = __float2bfloat16(v.y - __bfloat162float(h1));
    __nv_bfloat16 l2 = __float2bfloat16(v.z - __bfloat162float(h2));
    __nv_bfloat16 l3 = __float2bfloat16(v.w - __bfloat162float(h3));
    ((__nv_bfloat162*)hi)[2*i]   = __nv_bfloat162(h0, h1);
    ((__nv_bfloat162*)hi)[2*i+1] = __nv_bfloat162(h2, h3);
    ((__nv_bfloat162*)lo)[2*i]   = __nv_bfloat162(l0, l1);
    ((__nv_bfloat162*)lo)[2*i+1] = __nv_bfloat162(l2, l3);
}

// --------------- split-bf16 tensor-core GEMM (mma.sync path) ----------------
// D[128x128] = A[128,768] * B[n,768]^T, 12 K-chunks of 64, double-buffered.
// Buffers per stage: Ah | Al | Bh | Bl, each 128 rows x 128B, XOR-swizzled.
__device__ __forceinline__ void load_chunk(uint32_t sb,
    const __nv_bfloat16* __restrict__ Ah, const __nv_bfloat16* __restrict__ Al,
    const __nv_bfloat16* __restrict__ Bh, const __nv_bfloat16* __restrict__ Bl,
    int bm, int bn, int kc, int tid)
{
    const int g = tid & 7;
    const int rb = tid >> 3;
    const int koff = kc * 64 + g * 8;
    #pragma unroll
    for (int i = 0; i < 4; i++) {
        const int r = rb + 32 * i;
        const uint32_t d = SWZ((uint32_t)(r * 128 + g * 16));
        cpa16(sb + 0*16384 + d, Ah + (size_t)(bm + r) * C_ + koff);
        cpa16(sb + 1*16384 + d, Al + (size_t)(bm + r) * C_ + koff);
        cpa16(sb + 2*16384 + d, Bh + (size_t)(bn + r) * C_ + koff);
        cpa16(sb + 3*16384 + d, Bl + (size_t)(bn + r) * C_ + koff);
    }
}

__global__ __launch_bounds__(256, 1) void mma_gemm_kernel(
    const __nv_bfloat16* __restrict__ Ah, const __nv_bfloat16* __restrict__ Al,
    const __nv_bfloat16* __restrict__ Bh, const __nv_bfloat16* __restrict__ Bl,
    const float* __restrict__ bias, float* __restrict__ outp, int mode)
{
    extern __shared__ char dsmem[];
    const int tid = threadIdx.x, wid = tid >> 5, lane = tid & 31;
    const int wm = wid >> 2, wn = wid & 3;          // warp tile: 64m x 32n
    const uint32_t sb0 = (smem_to_u32(dsmem) + 1023u) & ~1023u;

    const int bm = blockIdx.y * 128, bn = blockIdx.x * 128;
    const int lrow = (lane & 7) + ((lane >> 3) & 1) * 8;   // ldmatrix row-in-tile
    const int lkb  = (lane >> 4) * 16;                     // ldmatrix k-byte half

    float acc[4][4][4] = {};

    load_chunk(sb0,         Ah, Al, Bh, Bl, bm, bn, 0, tid);
    asm volatile("cp.async.commit_group;" ::: "memory");
    load_chunk(sb0 + 65536, Ah, Al, Bh, Bl, bm, bn, 1, tid);
    asm volatile("cp.async.commit_group;" ::: "memory");

    for (int i = 0; i < 12; i++) {
        asm volatile("cp.async.wait_group 1;" ::: "memory");
        __syncthreads();
        const uint32_t sb = sb0 + (i & 1) * 65536;

        #pragma unroll
        for (int ks = 0; ks < 4; ks++) {
            uint32_t ah[4][4], al[4][4];
            #pragma unroll
            for (int mi = 0; mi < 4; mi++) {
                const uint32_t off =
                    SWZ((uint32_t)((wm*64 + mi*16 + lrow) * 128 + ks*32 + lkb));
                LDM4(ah[mi], sb + 0*16384 + off);
                LDM4(al[mi], sb + 1*16384 + off);
            }
            uint32_t bh[2][4], bl[2][4];
            #pragma unroll
            for (int nb = 0; nb < 2; nb++) {
                const uint32_t off =
                    SWZ((uint32_t)((wn*32 + nb*16 + lrow) * 128 + ks*32 + lkb));
                LDM4(bh[nb], sb + 2*16384 + off);
                LDM4(bl[nb], sb + 3*16384 + off);
            }
            #pragma unroll
            for (int mi = 0; mi < 4; mi++)
                #pragma unroll
                for (int ni = 0; ni < 4; ni++) {
                    const int nb = ni >> 1, hl = ni & 1;
                    MMA16816(acc[mi][ni], ah[mi], bh[nb][hl], bh[nb][2+hl]); // hi*hi
                    MMA16816(acc[mi][ni], ah[mi], bl[nb][hl], bl[nb][2+hl]); // hi*lo
                    MMA16816(acc[mi][ni], al[mi], bh[nb][hl], bh[nb][2+hl]); // lo*hi
                }
        }
        __syncthreads();
        if (i + 2 < 12) load_chunk(sb, Ah, Al, Bh, Bl, bm, bn, i + 2, tid);
        asm volatile("cp.async.commit_group;" ::: "memory");
    }

    // Epilogue. Fragment: rows g=lane>>2 (+8), cols 2*(lane&3) (+1)
    const int g = lane >> 2, c2 = (lane & 3) * 2;
    #pragma unroll
    for (int mi = 0; mi < 4; mi++)
        #pragma unroll
        for (int ni = 0; ni < 4; ni++) {
            const int col = bn + wn*32 + ni*8 + c2;
            #pragma unroll
            for (int half = 0; half < 2; half++) {
                const int m = bm + wm*64 + mi*16 + g + half*8;
                const float d0 = acc[mi][ni][half*2], d1 = acc[mi][ni][half*2+1];
                if (mode == 0) {   // qkv scatter to (B,H,N,64)
                    const int which = col / C_;
                    const int rest = col - which * C_;
                    const int h = rest >> 6, dd = rest & 63;
                    float* dst = (which == 0) ? g_q : (which == 1) ? g_k : g_v;
                    const int b = m >> 10, tok = m & 1023;
                    float* p = dst + ((size_t)(b * H_ + h) * N_ + tok) * HD + dd;
                    p[0] = d0; p[1] = d1;
                } else {           // proj + bias
                    float* p = outp + (size_t)m * C_ + col;
                    p[0] = d0 + bias[col];
                    p[1] = d1 + bias[col + 1];
                }
            }
        }
}

// ---------------- attention (unchanged FFMA2 version, passing) --------------
__device__ __forceinline__ float2 ffma2(float2 a, float2 b, float2 c) {
    union U { float2 f; unsigned long long u; };
    U A, Bx, Cx, D; A.f = a; Bx.f = b; Cx.f = c;
    asm("fma.rn.f32x2 %0, %1, %2, %3;" : "=l"(D.u) : "l"(A.u), "l"(Bx.u), "l"(Cx.u));
    return D.f;
}
__device__ __forceinline__ float2 add2(float2 a, float2 b) {
    union U { float2 f; unsigned long long u; };
    U A, Bx, D; A.f = a; Bx.f = b;
    asm("add.rn.f32x2 %0, %1, %2;" : "=l"(D.u) : "l"(A.u), "l"(Bx.u));
    return D.f;
}
__device__ __forceinline__ float2 mul2(float2 a, float2 b) {
    union U { float2 f; unsigned long long u; };
    U A, Bx, D; A.f = a; Bx.f = b;
    asm("mul.rn.f32x2 %0, %1, %2;" : "=l"(D.u) : "l"(A.u), "l"(Bx.u));
    return D.f;
}
__device__ __forceinline__ float exp2_fast(float x) {
    float t = fmaxf(x, -80.f);
    float z = t + 12582912.f;
    int   n = __float_as_int(z) - 0x4B400000;
    float f = t - (z - 12582912.f);
    float p = 1.3333558e-3f;
    p = fmaf(p, f, 9.618129e-3f);
    p = fmaf(p, f, 5.5504109e-2f);
    p = fmaf(p, f, 2.4022651e-1f);
    p = fmaf(p, f, 6.9314718e-1f);
    p = fmaf(p, f, 1.0f);
    return __int_as_float(__float_as_int(p) + (n << 23));
}

#define AP 66
__global__ __launch_bounds__(256) void attn_kernel(const float* __restrict__ policy) {
    extern __shared__ float smem[];
    float* Qs  = smem;
    float* Ks  = smem + 64*AP;
    float* VsT = smem + 2*64*AP;
    float* Ps  = smem + 3*64*AP;

    const int qt = blockIdx.x;
    const int bh = blockIdx.y;
    const int b  = bh / H_;
    const int h  = bh - b * H_;
    const int tid = threadIdx.x;
    const int tx = tid & 15, ty = tid >> 4;
    const int qbase = (bh * N_ + qt * 64) * HD;
    const int lr = tid >> 4, ld4 = tid & 15;

    #pragma unroll
    for (int it = 0; it < 4; it++) {
        const int rr = lr + 16*it;
        float4 v = *(const float4*)(g_q + qbase + rr*HD + ld4*4);
        float* d = &Qs[rr*AP + ld4*4];
        d[0] = v.x*SC2E; d[1] = v.y*SC2E; d[2] = v.z*SC2E; d[3] = v.w*SC2E;
    }
    float polq[4];
    #pragma unroll
    for (int i = 0; i < 4; i++) polq[i] = policy[b*N_ + qt*64 + ty + 16*i];

    float m_[4], l_[4];
    float2 O2[4][4], vsum2[4];
    #pragma unroll
    for (int i = 0; i < 4; i++) { m_[i] = -1e30f; l_[i] = 0.f; }
    #pragma unroll
    for (int i = 0; i < 4; i++)
        #pragma unroll
        for (int j = 0; j < 4; j++) O2[i][j] = make_float2(0.f, 0.f);
    #pragma unroll
    for (int j = 0; j < 4; j++) vsum2[j] = make_float2(0.f, 0.f);

    for (int kt = 0; kt < 16; kt++) {
        const int kbase = (bh * N_ + kt * 64) * HD;
        #pragma unroll
        for (int it = 0; it < 4; it++) {
            const int rr = lr + 16*it;
            float4 kv = *(const float4*)(g_k + kbase + rr*HD + ld4*4);
            float* d = &Ks[rr*AP + ld4*4];
            d[0] = kv.x; d[1] = kv.y; d[2] = kv.z; d[3] = kv.w;
            float4 vv = *(const float4*)(g_v + kbase + rr*HD + ld4*4);
            VsT[(ld4*4+0)*AP + rr] = vv.x;
            VsT[(ld4*4+1)*AP + rr] = vv.y;
            VsT[(ld4*4+2)*AP + rr] = vv.z;
            VsT[(ld4*4+3)*AP + rr] = vv.w;
        }
        float polk[4];
        #pragma unroll
        for (int j = 0; j < 4; j++) polk[j] = policy[b*N_ + kt*64 + tx + 16*j];
        __syncthreads();

        float2 S2[4][4];
        #pragma unroll
        for (int i = 0; i < 4; i++)
            #pragma unroll
            for (int j = 0; j < 4; j++) S2[i][j] = make_float2(0.f, 0.f);
        #pragma unroll
        for (int d2 = 0; d2 < 32; d2++) {
            float2 q2[4], k2[4];
            #pragma unroll
            for (int i = 0; i < 4; i++) q2[i] = *(const float2*)&Qs[(ty + 16*i)*AP + d2*2];
            #pragma unroll
            for (int j = 0; j < 4; j++) k2[j] = *(const float2*)&Ks[(tx + 16*j)*AP + d2*2];
            #pragma unroll
            for (int i = 0; i < 4; i++)
                #pragma unroll
                for (int j = 0; j < 4; j++) S2[i][j] = ffma2(q2[i], k2[j], S2[i][j]);
        }
        float S[4][4];
        #pragma unroll
        for (int i = 0; i < 4; i++)
            #pragma unroll
            for (int j = 0; j < 4; j++) S[i][j] = S2[i][j].x + S2[i][j].y;

        float mnew[4], resc[4];
        #pragma unroll
        for (int i = 0; i < 4; i++) {
            float t = fmaxf(fmaxf(S[i][0], S[i][1]), fmaxf(S[i][2], S[i][3]));
            t = fmaxf(t, __shfl_xor_sync(0xffffffffu, t, 1));
            t = fmaxf(t, __shfl_xor_sync(0xffffffffu, t, 2));
            t = fmaxf(t, __shfl_xor_sync(0xffffffffu, t, 4));
            t = fmaxf(t, __shfl_xor_sync(0xffffffffu, t, 8));
            mnew[i] = fmaxf(m_[i], t);
            resc[i] = exp2_fast(m_[i] - mnew[i]);
        }
        float psum[4];
        #pragma unroll
        for (int i = 0; i < 4; i++) {
            const int nq = qt*64 + ty + 16*i;
            psum[i] = 0.f;
            #pragma unroll
            for (int j = 0; j < 4; j++) {
                const int mk = kt*64 + tx + 16*j;
                const float mask = (mk == nq) ? 1.0f : polq[i] * polk[j];
                const float p = exp2_fast(S[i][j] - mnew[i]) * mask;
                psum[i] += p;
                Ps[(ty + 16*i)*64 + tx + 16*j] = p;
            }
        }
        #pragma unroll
        for (int i = 0; i < 4; i++) {
            float s = psum[i];
            s += __shfl_xor_sync(0xffffffffu, s, 1);
            s += __shfl_xor_sync(0xffffffffu, s, 2);
            s += __shfl_xor_sync(0xffffffffu, s, 4);
            s += __shfl_xor_sync(0xffffffffu, s, 8);
            l_[i] = l_[i] * resc[i] + s;
            m_[i] = mnew[i];
            const float2 r2 = make_float2(resc[i], resc[i]);
            #pragma unroll
            for (int j = 0; j < 4; j++) O2[i][j] = mul2(O2[i][j], r2);
        }
        __syncthreads();
        #pragma unroll
        for (int k2i = 0; k2i < 32; k2i++) {
            float2 p2[4], v2[4];
            #pragma unroll
            for (int i = 0; i < 4; i++) p2[i] = *(const float2*)&Ps[(ty + 16*i)*64 + k2i*2];
            #pragma unroll
            for (int j = 0; j < 4; j++) v2[j] = *(const float2*)&VsT[(tx + 16*j)*AP + k2i*2];
            #pragma unroll
            for (int j = 0; j < 4; j++) vsum2[j] = add2(vsum2[j], v2[j]);
            #pragma unroll
            for (int i = 0; i < 4; i++)
                #pragma unroll
                for (int j = 0; j < 4; j++) O2[i][j] = ffma2(p2[i], v2[j], O2[i][j]);
        }
        __syncthreads();
    }
    #pragma unroll
    for (int i = 0; i < 4; i++) {
        const float inv = 1.0f / (l_[i] + EPS);
        float* row = g_aout + (b*N_ + qt*64 + ty + 16*i) * C_ + h * HD;
        #pragma unroll
        for (int j = 0; j < 4; j++) {
            const float vs = vsum2[j].x + vsum2[j].y;
            row[tx + 16*j] = (O2[i][j].x + O2[i][j].y + EPSN * vs) * inv;
        }
    }
}

// ---------------------------------------------------------------------------
extern "C" void kernel_launch(void* const* d_in, const int* in_sizes, int n_in,
                              void* d_out, int out_size) {
    const float* x      = (const float*)d_in[0];
    const float* policy = (const float*)d_in[1];
    const float* Wqkv   = (const float*)d_in[2];
    const float* Wproj  = (const float*)d_in[3];
    const float* bproj  = (const float*)d_in[4];
    float* out = (float*)d_out;

    __nv_bfloat16 *xh, *xl, *wqh, *wql, *wph, *wpl, *ah, *al;
    float *aout_p;
    cudaGetSymbolAddress((void**)&xh,  g_xh);  cudaGetSymbolAddress((void**)&xl,  g_xl);
    cudaGetSymbolAddress((void**)&wqh, g_wqh); cudaGetSymbolAddress((void**)&wql, g_wql);
    cudaGetSymbolAddress((void**)&wph, g_wph); cudaGetSymbolAddress((void**)&wpl, g_wpl);
    cudaGetSymbolAddress((void**)&ah,  g_ah);  cudaGetSymbolAddress((void**)&al,  g_al);
    cudaGetSymbolAddress((void**)&aout_p, g_aout);

    cudaFuncSetAttribute(mma_gemm_kernel,
                         cudaFuncAttributeMaxDynamicSharedMemorySize, 132096);
    cudaFuncSetAttribute(attn_kernel,
                         cudaFuncAttributeMaxDynamicSharedMemorySize, 67072);

    split_kernel<<<(M_TOT*C_/4 + 255)/256, 256>>>(x,     xh,  xl,  M_TOT*C_/4);
    split_kernel<<<(QKV_N*C_/4 + 255)/256, 256>>>(Wqkv,  wqh, wql, QKV_N*C_/4);
    split_kernel<<<(C_*C_/4   + 255)/256, 256>>>(Wproj, wph, wpl, C_*C_/4);

    mma_gemm_kernel<<<dim3(QKV_N/128, M_TOT/128), 256, 132096>>>(
        xh, xl, wqh, wql, nullptr, nullptr, 0);

    attn_kernel<<<dim3(16, 96), 256, 67072>>>(policy);

    split_kernel<<<(M_TOT*C_/4 + 255)/256, 256>>>(aout_p, ah, al, M_TOT*C_/4);

    mma_gemm_kernel<<<dim3(C_/128, M_TOT/128), 256, 132096>>>(
        ah, al, wph, wpl, bproj, out, 1);
}

// round 8
// speedup vs baseline: 2.8273x; 1.7735x over previous
#include <cuda_runtime.h>
#include <cuda_bf16.h>
#include <cstdint>

#define B_ 8
#define N_ 1024
#define C_ 768
#define H_ 12
#define HD 64
#define M_TOT (B_*N_)
#define QKV_N (3*C_)
#define EPS 1e-6f
#define EPSN (1e-6f/1024.0f)
#define SC2E 0.18033688011112042f
#define SWZ(b) ((b) ^ (((b) >> 3) & 0x70))

__device__ __forceinline__ uint32_t smem_to_u32(const void* p) {
    uint32_t a;
    asm("{ .reg .u64 t; cvta.to.shared.u64 t, %1; cvt.u32.u64 %0, t; }" : "=r"(a) : "l"(p));
    return a;
}
__device__ __forceinline__ void cpa16(uint32_t dst, const void* src) {
    asm volatile("cp.async.cg.shared.global [%0], [%1], 16;" :: "r"(dst), "l"(src));
}
#define CP_COMMIT() asm volatile("cp.async.commit_group;" ::: "memory")
#define CP_WAIT1()  asm volatile("cp.async.wait_group 1;" ::: "memory")
#define LDM4(r, a) \
    asm volatile("ldmatrix.sync.aligned.m8n8.x4.shared.b16 {%0,%1,%2,%3}, [%4];" \
        : "=r"((r)[0]), "=r"((r)[1]), "=r"((r)[2]), "=r"((r)[3]) : "r"(a))
#define LDM4T(r, a) \
    asm volatile("ldmatrix.sync.aligned.m8n8.x4.trans.shared.b16 {%0,%1,%2,%3}, [%4];" \
        : "=r"((r)[0]), "=r"((r)[1]), "=r"((r)[2]), "=r"((r)[3]) : "r"(a))
#define MMA16816(d, a, b0, b1) \
    asm volatile("mma.sync.aligned.m16n8k16.row.col.f32.bf16.bf16.f32 " \
        "{%0,%1,%2,%3}, {%4,%5,%6,%7}, {%8,%9}, {%0,%1,%2,%3};" \
        : "+f"((d)[0]), "+f"((d)[1]), "+f"((d)[2]), "+f"((d)[3]) \
        : "r"((a)[0]), "r"((a)[1]), "r"((a)[2]), "r"((a)[3]), "r"(b0), "r"(b1))

__device__ __forceinline__ uint32_t pack2(float e0, float e1) {
    uint32_t r;
    asm("cvt.rn.bf16x2.f32 %0, %1, %2;" : "=r"(r) : "f"(e1), "f"(e0));
    return r;
}
__device__ __forceinline__ void split_pair(float v0, float v1, uint32_t& hp, uint32_t& lp) {
    hp = pack2(v0, v1);
    float r0 = __uint_as_float(hp << 16);
    float r1 = __uint_as_float(hp & 0xffff0000u);
    lp = pack2(v0 - r0, v1 - r1);
}
__device__ __forceinline__ float exp2_fast(float x) {
    float t = fmaxf(x, -80.f);
    float z = t + 12582912.f;
    int   n = __float_as_int(z) - 0x4B400000;
    float f = t - (z - 12582912.f);
    float p = 1.3333558e-3f;
    p = fmaf(p, f, 9.618129e-3f);
    p = fmaf(p, f, 5.5504109e-2f);
    p = fmaf(p, f, 2.4022651e-1f);
    p = fmaf(p, f, 6.9314718e-1f);
    p = fmaf(p, f, 1.0f);
    return __int_as_float(__float_as_int(p) + (n << 23));
}

// --------------------------- scratch ---------------------------------------
__device__ __nv_bfloat16 g_xh[M_TOT*C_],  g_xl[M_TOT*C_];
__device__ __nv_bfloat16 g_wqh[QKV_N*C_], g_wql[QKV_N*C_];
__device__ __nv_bfloat16 g_wph[C_*C_],    g_wpl[C_*C_];
__device__ __nv_bfloat16 g_qh[B_*H_*N_*HD], g_ql[B_*H_*N_*HD];   // Q pre-scaled
__device__ __nv_bfloat16 g_kh[B_*H_*N_*HD], g_kl[B_*H_*N_*HD];
__device__ __nv_bfloat16 g_vh[B_*H_*N_*HD], g_vl[B_*H_*N_*HD];
__device__ __nv_bfloat16 g_ah[M_TOT*C_],  g_al[M_TOT*C_];
__device__ float g_vsum[B_*H_*HD];

// ---------------------- fp32 -> bf16 hi/lo split ----------------------------
__global__ __launch_bounds__(256) void split_kernel(const float* __restrict__ in,
                                                    __nv_bfloat16* __restrict__ hi,
                                                    __nv_bfloat16* __restrict__ lo, int n4) {
    int i = blockIdx.x * 256 + threadIdx.x;
    if (i >= n4) return;
    float4 v = ((const float4*)in)[i];
    uint32_t h0, l0, h1, l1;
    split_pair(v.x, v.y, h0, l0);
    split_pair(v.z, v.w, h1, l1);
    ((uint32_t*)hi)[2*i] = h0; ((uint32_t*)hi)[2*i+1] = h1;
    ((uint32_t*)lo)[2*i] = l0; ((uint32_t*)lo)[2*i+1] = l1;
}

// --------------- split-bf16 tensor-core GEMM (qkv / proj) -------------------
__device__ __forceinline__ void load_chunk(uint32_t sb,
    const __nv_bfloat16* __restrict__ Ah, const __nv_bfloat16* __restrict__ Al,
    const __nv_bfloat16* __restrict__ Bh, const __nv_bfloat16* __restrict__ Bl,
    int bm, int bn, int kc, int tid)
{
    const int g = tid & 7;
    const int rb = tid >> 3;
    const int koff = kc * 64 + g * 8;
    #pragma unroll
    for (int i = 0; i < 4; i++) {
        const int r = rb + 32 * i;
        const uint32_t d = SWZ((uint32_t)(r * 128 + g * 16));
        cpa16(sb + 0*16384 + d, Ah + (size_t)(bm + r) * C_ + koff);
        cpa16(sb + 1*16384 + d, Al + (size_t)(bm + r) * C_ + koff);
        cpa16(sb + 2*16384 + d, Bh + (size_t)(bn + r) * C_ + koff);
        cpa16(sb + 3*16384 + d, Bl + (size_t)(bn + r) * C_ + koff);
    }
}

__global__ __launch_bounds__(256, 1) void mma_gemm_kernel(
    const __nv_bfloat16* __restrict__ Ah, const __nv_bfloat16* __restrict__ Al,
    const __nv_bfloat16* __restrict__ Bh, const __nv_bfloat16* __restrict__ Bl,
    const float* __restrict__ bias, float* __restrict__ outp, int mode)
{
    extern __shared__ char dsmem[];
    const int tid = threadIdx.x, wid = tid >> 5, lane = tid & 31;
    const int wm = wid >> 2, wn = wid & 3;
    const uint32_t sb0 = (smem_to_u32(dsmem) + 1023u) & ~1023u;

    const int bm = blockIdx.y * 128, bn = blockIdx.x * 128;
    const int lrow = (lane & 7) + ((lane >> 3) & 1) * 8;
    const int lkb  = (lane >> 4) * 16;

    float acc[4][4][4] = {};

    load_chunk(sb0,         Ah, Al, Bh, Bl, bm, bn, 0, tid);
    CP_COMMIT();
    load_chunk(sb0 + 65536, Ah, Al, Bh, Bl, bm, bn, 1, tid);
    CP_COMMIT();

    for (int i = 0; i < 12; i++) {
        CP_WAIT1();
        __syncthreads();
        const uint32_t sb = sb0 + (i & 1) * 65536;
        #pragma unroll
        for (int ks = 0; ks < 4; ks++) {
            uint32_t ah[4][4], al[4][4];
            #pragma unroll
            for (int mi = 0; mi < 4; mi++) {
                const uint32_t off =
                    SWZ((uint32_t)((wm*64 + mi*16 + lrow) * 128 + ks*32 + lkb));
                LDM4(ah[mi], sb + 0*16384 + off);
                LDM4(al[mi], sb + 1*16384 + off);
            }
            uint32_t bh[2][4], bl[2][4];
            #pragma unroll
            for (int nb = 0; nb < 2; nb++) {
                const uint32_t off =
                    SWZ((uint32_t)((wn*32 + nb*16 + lrow) * 128 + ks*32 + lkb));
                LDM4(bh[nb], sb + 2*16384 + off);
                LDM4(bl[nb], sb + 3*16384 + off);
            }
            #pragma unroll
            for (int mi = 0; mi < 4; mi++)
                #pragma unroll
                for (int ni = 0; ni < 4; ni++) {
                    const int nb = ni >> 1, hl = ni & 1;
                    MMA16816(acc[mi][ni], ah[mi], bh[nb][hl], bh[nb][2+hl]);
                    MMA16816(acc[mi][ni], ah[mi], bl[nb][hl], bl[nb][2+hl]);
                    MMA16816(acc[mi][ni], al[mi], bh[nb][hl], bh[nb][2+hl]);
                }
        }
        __syncthreads();
        if (i + 2 < 12) load_chunk(sb, Ah, Al, Bh, Bl, bm, bn, i + 2, tid);
        CP_COMMIT();
    }

    const int g = lane >> 2, c2 = (lane & 3) * 2;
    #pragma unroll
    for (int mi = 0; mi < 4; mi++)
        #pragma unroll
        for (int ni = 0; ni < 4; ni++) {
            const int col = bn + wn*32 + ni*8 + c2;
            #pragma unroll
            for (int half = 0; half < 2; half++) {
                const int m = bm + wm*64 + mi*16 + g + half*8;
                float d0 = acc[mi][ni][half*2], d1 = acc[mi][ni][half*2+1];
                if (mode == 0) {   // write bf16 hi/lo q (scaled), k, v in (B,H,N,64)
                    const int which = col / C_;
                    const int rest = col - which * C_;
                    const int h = rest >> 6, dd = rest & 63;
                    if (which == 0) { d0 *= SC2E; d1 *= SC2E; }
                    uint32_t hp, lp;
                    split_pair(d0, d1, hp, lp);
                    __nv_bfloat16 *dh = (which == 0) ? g_qh : (which == 1) ? g_kh : g_vh;
                    __nv_bfloat16 *dl = (which == 0) ? g_ql : (which == 1) ? g_kl : g_vl;
                    const int b = m >> 10, tok = m & 1023;
                    const size_t idx = (((size_t)(b * H_ + h) * N_ + tok) * HD + dd) >> 1;
                    ((uint32_t*)dh)[idx] = hp;
                    ((uint32_t*)dl)[idx] = lp;
                } else {
                    float* p = outp + (size_t)m * C_ + col;
                    p[0] = d0 + bias[col];
                    p[1] = d1 + bias[col + 1];
                }
            }
        }
}

// --------------------- V row-sum per (b,h) ----------------------------------
__global__ __launch_bounds__(256) void vsum_kernel() {
    const int bh = blockIdx.x;
    const int wid = threadIdx.x >> 5, lane = threadIdx.x & 31;
    __shared__ float sm[8][64];
    float a0 = 0.f, a1 = 0.f;
    for (int n = wid * 128; n < wid * 128 + 128; n++) {
        const size_t idx = (((size_t)bh * N_ + n) * HD >> 1) + lane;
        uint32_t hv = ((const uint32_t*)g_vh)[idx];
        uint32_t lv = ((const uint32_t*)g_vl)[idx];
        a0 += __uint_as_float(hv << 16) + __uint_as_float(lv << 16);
        a1 += __uint_as_float(hv & 0xffff0000u) + __uint_as_float(lv & 0xffff0000u);
    }
    sm[wid][lane*2] = a0; sm[wid][lane*2+1] = a1;
    __syncthreads();
    if (threadIdx.x < 64) {
        float s = 0.f;
        #pragma unroll
        for (int w = 0; w < 8; w++) s += sm[w][threadIdx.x];
        g_vsum[bh * HD + threadIdx.x] = s;
    }
}

// ------------------ tensor-core flash attention -----------------------------
// CTA = (128-q tile, b*h). 8 warps x 16 q-rows. Keys streamed in 128-key
// tiles, double-buffered. S and PV via split-bf16 mma.sync (3 MMAs each).
__global__ __launch_bounds__(256, 1) void attn_mma_kernel(const float* __restrict__ policy) {
    extern __shared__ char dsmem[];
    const uint32_t dbase = smem_to_u32(dsmem);
    const uint32_t sb0 = (dbase + 1023u) & ~1023u;
    char* sbp = dsmem + (sb0 - dbase);          // host-pointer view of sb0

    const int qt = blockIdx.x;          // 0..7
    const int bh = blockIdx.y;          // 0..95
    const int b  = bh / H_;
    const int h  = bh - b * H_;
    const int tid = threadIdx.x, w = tid >> 5, lane = tid & 31;
    const int lrow = (lane & 7) + ((lane >> 3) & 1) * 8;
    const int lkb  = (lane >> 4) * 16;
    const int c2   = (lane & 3) * 2;
    const int r0   = lane >> 2;

    const uint32_t QH = sb0, QL = sb0 + 16384;
    const uint32_t ST0 = sb0 + 32768;          // per stage: Kh|Kl|Vh|Vl (16K each)
    const uint32_t PK0 = sb0 + 163840;         // polK, 512 B per stage

    const int g8 = tid & 7, rb = tid >> 3;
    const size_t bhN = (size_t)bh * N_;

    // ---- prologue: Q + stage0 | stage1 ----
    {
        #pragma unroll
        for (int i = 0; i < 4; i++) {
            const int r = rb + 32 * i;
            const uint32_t d = SWZ((uint32_t)(r * 128 + g8 * 16));
            const size_t src = (bhN + qt * 128 + r) * HD + g8 * 8;
            cpa16(QH + d, g_qh + src);
            cpa16(QL + d, g_ql + src);
        }
        #pragma unroll
        for (int i = 0; i < 4; i++) {
            const int r = rb + 32 * i;
            const uint32_t d = SWZ((uint32_t)(r * 128 + g8 * 16));
            const size_t src = (bhN + 0 * 128 + r) * HD + g8 * 8;
            cpa16(ST0 + 0*16384 + d, g_kh + src);
            cpa16(ST0 + 1*16384 + d, g_kl + src);
            cpa16(ST0 + 2*16384 + d, g_vh + src);
            cpa16(ST0 + 3*16384 + d, g_vl + src);
        }
        if (tid < 32) cpa16(PK0 + tid * 16, policy + b * N_ + tid * 4);
        CP_COMMIT();
        #pragma unroll
        for (int i = 0; i < 4; i++) {
            const int r = rb + 32 * i;
            const uint32_t d = SWZ((uint32_t)(r * 128 + g8 * 16));
            const size_t src = (bhN + 1 * 128 + r) * HD + g8 * 8;
            cpa16(ST0 + 65536 + 0*16384 + d, g_kh + src);
            cpa16(ST0 + 65536 + 1*16384 + d, g_kl + src);
            cpa16(ST0 + 65536 + 2*16384 + d, g_vh + src);
            cpa16(ST0 + 65536 + 3*16384 + d, g_vl + src);
        }
        if (tid < 32) cpa16(PK0 + 512 + tid * 16, policy + b * N_ + 128 + tid * 4);
        CP_COMMIT();
        CP_WAIT1();
        __syncthreads();
    }

    // Q fragments (held in registers for the whole CTA lifetime)
    uint32_t qh[4][4], ql[4][4];
    #pragma unroll
    for (int ks = 0; ks < 4; ks++) {
        const uint32_t off = SWZ((uint32_t)((w*16 + lrow) * 128 + ks*32 + lkb));
        LDM4(qh[ks], QH + off);
        LDM4(ql[ks], QL + off);
    }

    const int nq0 = qt * 128 + w * 16 + r0;
    const int nq1 = nq0 + 8;
    const float polq0 = policy[b * N_ + nq0];
    const float polq1 = policy[b * N_ + nq1];

    float m0 = -1e30f, m1 = -1e30f, l0 = 0.f, l1 = 0.f;
    float O[8][4] = {};

    for (int kt = 0; kt < 8; kt++) {
        const int s = kt & 1;
        const uint32_t ST = ST0 + s * 65536;
        const float* polKs = (const float*)(sbp + (PK0 - sb0) + s * 512);  // FIXED

        // ---- S = Q K^T (split bf16) ----
        float Sf[16][4] = {};
        #pragma unroll
        for (int ks = 0; ks < 4; ks++) {
            #pragma unroll
            for (int ng = 0; ng < 8; ng++) {
                uint32_t kh4[4], kl4[4];
                const uint32_t off = SWZ((uint32_t)((ng*16 + lrow) * 128 + ks*32 + lkb));
                LDM4(kh4, ST + 0*16384 + off);
                LDM4(kl4, ST + 1*16384 + off);
                #pragma unroll
                for (int hl = 0; hl < 2; hl++) {
                    MMA16816(Sf[2*ng+hl], qh[ks], kh4[hl], kh4[2+hl]);
                    MMA16816(Sf[2*ng+hl], qh[ks], kl4[hl], kl4[2+hl]);
                    MMA16816(Sf[2*ng+hl], ql[ks], kh4[hl], kh4[2+hl]);
                }
            }
        }

        // ---- online softmax (log2 domain; unmasked max per reference) ----
        float t0 = -1e30f, t1 = -1e30f;
        #pragma unroll
        for (int nf = 0; nf < 16; nf++) {
            t0 = fmaxf(t0, fmaxf(Sf[nf][0], Sf[nf][1]));
            t1 = fmaxf(t1, fmaxf(Sf[nf][2], Sf[nf][3]));
        }
        t0 = fmaxf(t0, __shfl_xor_sync(0xffffffffu, t0, 1));
        t0 = fmaxf(t0, __shfl_xor_sync(0xffffffffu, t0, 2));
        t1 = fmaxf(t1, __shfl_xor_sync(0xffffffffu, t1, 1));
        t1 = fmaxf(t1, __shfl_xor_sync(0xffffffffu, t1, 2));
        const float mn0 = fmaxf(m0, t0), mn1 = fmaxf(m1, t1);
        const float rs0 = exp2_fast(m0 - mn0), rs1 = exp2_fast(m1 - mn1);
        m0 = mn0; m1 = mn1;

        uint32_t ph[8][4], pl[8][4];
        float ps0 = 0.f, ps1 = 0.f;
        #pragma unroll
        for (int nf = 0; nf < 16; nf++) {
            const int col = kt * 128 + nf * 8 + c2;
            const float pk0 = polKs[nf * 8 + c2];
            const float pk1 = polKs[nf * 8 + c2 + 1];
            const float mk00 = (col     == nq0) ? 1.f : polq0 * pk0;
            const float mk01 = (col + 1 == nq0) ? 1.f : polq0 * pk1;
            const float mk10 = (col     == nq1) ? 1.f : polq1 * pk0;
            const float mk11 = (col + 1 == nq1) ? 1.f : polq1 * pk1;
            const float p00 = exp2_fast(Sf[nf][0] - m0) * mk00;
            const float p01 = exp2_fast(Sf[nf][1] - m0) * mk01;
            const float p10 = exp2_fast(Sf[nf][2] - m1) * mk10;
            const float p11 = exp2_fast(Sf[nf][3] - m1) * mk11;
            ps0 += p00 + p01; ps1 += p10 + p11;
            const int kc = nf >> 1, base = (nf & 1) * 2;
            split_pair(p00, p01, ph[kc][base],   pl[kc][base]);
            split_pair(p10, p11, ph[kc][base+1], pl[kc][base+1]);
        }
        ps0 += __shfl_xor_sync(0xffffffffu, ps0, 1);
        ps0 += __shfl_xor_sync(0xffffffffu, ps0, 2);
        ps1 += __shfl_xor_sync(0xffffffffu, ps1, 1);
        ps1 += __shfl_xor_sync(0xffffffffu, ps1, 2);
        l0 = l0 * rs0 + ps0;
        l1 = l1 * rs1 + ps1;
        #pragma unroll
        for (int nf = 0; nf < 8; nf++) {
            O[nf][0] *= rs0; O[nf][1] *= rs0;
            O[nf][2] *= rs1; O[nf][3] *= rs1;
        }

        // ---- O += P V (split bf16, V via ldmatrix.trans) ----
        #pragma unroll
        for (int kc = 0; kc < 8; kc++) {
            #pragma unroll
            for (int ng = 0; ng < 4; ng++) {
                uint32_t vh4[4], vl4[4];
                const uint32_t off = SWZ((uint32_t)((kc*16 + lrow) * 128 + ng*32 + lkb));
                LDM4T(vh4, ST + 2*16384 + off);
                LDM4T(vl4, ST + 3*16384 + off);
                #pragma unroll
                for (int hl = 0; hl < 2; hl++) {
                    MMA16816(O[2*ng+hl], ph[kc], vh4[2*hl], vh4[2*hl+1]);
                    MMA16816(O[2*ng+hl], ph[kc], vl4[2*hl], vl4[2*hl+1]);
                    MMA16816(O[2*ng+hl], pl[kc], vh4[2*hl], vh4[2*hl+1]);
                }
            }
        }

        __syncthreads();    // stage consumed
        if (kt + 2 < 8) {
            const int kt2 = kt + 2;
            #pragma unroll
            for (int i = 0; i < 4; i++) {
                const int r = rb + 32 * i;
                const uint32_t d = SWZ((uint32_t)(r * 128 + g8 * 16));
                const size_t src = (bhN + kt2 * 128 + r) * HD + g8 * 8;
                cpa16(ST + 0*16384 + d, g_kh + src);
                cpa16(ST + 1*16384 + d, g_kl + src);
                cpa16(ST + 2*16384 + d, g_vh + src);
                cpa16(ST + 3*16384 + d, g_vl + src);
            }
            if (tid < 32) cpa16(PK0 + s * 512 + tid * 16,
                                policy + b * N_ + kt2 * 128 + tid * 4);
        }
        CP_COMMIT();
        if (kt + 1 < 8) { CP_WAIT1(); __syncthreads(); }
    }

    // ---- epilogue: (O + eps/N * vsum) / (l + eps) -> bf16 hi/lo aout ----
    const float inv0 = 1.f / (l0 + EPS);
    const float inv1 = 1.f / (l1 + EPS);
    #pragma unroll
    for (int nf = 0; nf < 8; nf++) {
        const int col = nf * 8 + c2;
        const float vs0 = g_vsum[bh * HD + col];
        const float vs1 = g_vsum[bh * HD + col + 1];
        const float o00 = (O[nf][0] + EPSN * vs0) * inv0;
        const float o01 = (O[nf][1] + EPSN * vs1) * inv0;
        const float o10 = (O[nf][2] + EPSN * vs0) * inv1;
        const float o11 = (O[nf][3] + EPSN * vs1) * inv1;
        uint32_t hp, lp;
        split_pair(o00, o01, hp, lp);
        const size_t i0 = (((size_t)(b * N_ + nq0)) * C_ + h * HD + col) >> 1;
        ((uint32_t*)g_ah)[i0] = hp; ((uint32_t*)g_al)[i0] = lp;
        split_pair(o10, o11, hp, lp);
        const size_t i1 = (((size_t)(b * N_ + nq1)) * C_ + h * HD + col) >> 1;
        ((uint32_t*)g_ah)[i1] = hp; ((uint32_t*)g_al)[i1] = lp;
    }
}

// ---------------------------------------------------------------------------
extern "C" void kernel_launch(void* const* d_in, const int* in_sizes, int n_in,
                              void* d_out, int out_size) {
    const float* x      = (const float*)d_in[0];
    const float* policy = (const float*)d_in[1];
    const float* Wqkv   = (const float*)d_in[2];
    const float* Wproj  = (const float*)d_in[3];
    const float* bproj  = (const float*)d_in[4];
    float* out = (float*)d_out;

    __nv_bfloat16 *xh, *xl, *wqh, *wql, *wph, *wpl, *ah, *al;
    cudaGetSymbolAddress((void**)&xh,  g_xh);  cudaGetSymbolAddress((void**)&xl,  g_xl);
    cudaGetSymbolAddress((void**)&wqh, g_wqh); cudaGetSymbolAddress((void**)&wql, g_wql);
    cudaGetSymbolAddress((void**)&wph, g_wph); cudaGetSymbolAddress((void**)&wpl, g_wpl);
    cudaGetSymbolAddress((void**)&ah,  g_ah);  cudaGetSymbolAddress((void**)&al,  g_al);

    cudaFuncSetAttribute(mma_gemm_kernel,
                         cudaFuncAttributeMaxDynamicSharedMemorySize, 132096);
    cudaFuncSetAttribute(attn_mma_kernel,
                         cudaFuncAttributeMaxDynamicSharedMemorySize, 165888);

    split_kernel<<<(M_TOT*C_/4 + 255)/256, 256>>>(x,     xh,  xl,  M_TOT*C_/4);
    split_kernel<<<(QKV_N*C_/4 + 255)/256, 256>>>(Wqkv,  wqh, wql, QKV_N*C_/4);
    split_kernel<<<(C_*C_/4   + 255)/256, 256>>>(Wproj, wph, wpl, C_*C_/4);

    mma_gemm_kernel<<<dim3(QKV_N/128, M_TOT/128), 256, 132096>>>(
        xh, xl, wqh, wql, nullptr, nullptr, 0);

    vsum_kernel<<<B_*H_, 256>>>();

    attn_mma_kernel<<<dim3(8, 96), 256, 165888>>>(policy);

    mma_gemm_kernel<<<dim3(C_/128, M_TOT/128), 256, 132096>>>(
        ah, al, wph, wpl, bproj, out, 1);
}

// round 9
// speedup vs baseline: 3.9242x; 1.3880x over previous
#include <cuda_runtime.h>
#include <cuda_fp16.h>
#include <cstdint>

#define B_ 8
#define N_ 1024
#define C_ 768
#define H_ 12
#define HD 64
#define M_TOT (B_*N_)
#define QKV_N (3*C_)
#define EPS 1e-6f
#define EPSN (1e-6f/1024.0f)
#define SC2E 0.18033688011112042f
#define SWZ(b) ((b) ^ (((b) >> 3) & 0x70))

__device__ __forceinline__ uint32_t smem_to_u32(const void* p) {
    uint32_t a;
    asm("{ .reg .u64 t; cvta.to.shared.u64 t, %1; cvt.u32.u64 %0, t; }" : "=r"(a) : "l"(p));
    return a;
}
__device__ __forceinline__ void cpa16(uint32_t dst, const void* src) {
    asm volatile("cp.async.cg.shared.global [%0], [%1], 16;" :: "r"(dst), "l"(src));
}
#define CP_COMMIT() asm volatile("cp.async.commit_group;" ::: "memory")
#define CP_WAIT2()  asm volatile("cp.async.wait_group 2;" ::: "memory")
#define LDM4(r, a) \
    asm volatile("ldmatrix.sync.aligned.m8n8.x4.shared.b16 {%0,%1,%2,%3}, [%4];" \
        : "=r"((r)[0]), "=r"((r)[1]), "=r"((r)[2]), "=r"((r)[3]) : "r"(a))
#define LDM4T(r, a) \
    asm volatile("ldmatrix.sync.aligned.m8n8.x4.trans.shared.b16 {%0,%1,%2,%3}, [%4];" \
        : "=r"((r)[0]), "=r"((r)[1]), "=r"((r)[2]), "=r"((r)[3]) : "r"(a))
#define MMAH(d, a, b0, b1) \
    asm volatile("mma.sync.aligned.m16n8k16.row.col.f32.f16.f16.f32 " \
        "{%0,%1,%2,%3}, {%4,%5,%6,%7}, {%8,%9}, {%0,%1,%2,%3};" \
        : "+f"((d)[0]), "+f"((d)[1]), "+f"((d)[2]), "+f"((d)[3]) \
        : "r"((a)[0]), "r"((a)[1]), "r"((a)[2]), "r"((a)[3]), "r"(b0), "r"(b1))

__device__ __forceinline__ uint32_t pack2h(float e0, float e1) {
    uint32_t r;
    asm("cvt.rn.f16x2.f32 %0, %1, %2;" : "=r"(r) : "f"(e1), "f"(e0));
    return r;
}
__device__ __forceinline__ void split_pair_h(float v0, float v1, uint32_t& hp, uint32_t& lp) {
    hp = pack2h(v0, v1);
    __half2 h = *reinterpret_cast<__half2*>(&hp);
    lp = pack2h(v0 - __low2float(h), v1 - __high2float(h));
}
__device__ __forceinline__ float exp2_fast(float x) {
    float t = fmaxf(x, -80.f);
    float z = t + 12582912.f;
    int   n = __float_as_int(z) - 0x4B400000;
    float f = t - (z - 12582912.f);
    float p = 1.3333558e-3f;
    p = fmaf(p, f, 9.618129e-3f);
    p = fmaf(p, f, 5.5504109e-2f);
    p = fmaf(p, f, 2.4022651e-1f);
    p = fmaf(p, f, 6.9314718e-1f);
    p = fmaf(p, f, 1.0f);
    return __int_as_float(__float_as_int(p) + (n << 23));
}

// --------------------------- scratch ---------------------------------------
__device__ __half g_xh[M_TOT*C_], g_xl[M_TOT*C_];
__device__ __half g_wqh[QKV_N*C_];
__device__ __half g_wph[C_*C_];
__device__ __half g_qh[B_*H_*N_*HD], g_ql[B_*H_*N_*HD];   // Q pre-scaled, 2-term
__device__ __half g_kh[B_*H_*N_*HD];                       // K single fp16
__device__ __half g_vh[B_*H_*N_*HD];                       // V single fp16
__device__ __half g_ah[M_TOT*C_], g_al[M_TOT*C_];
__device__ float g_vsum[B_*H_*HD];

// ---------------------- fp32 -> fp16 hi/lo split / quant --------------------
__global__ __launch_bounds__(256) void split2h_kernel(const float* __restrict__ in,
                                                      __half* __restrict__ hi,
                                                      __half* __restrict__ lo, int n4) {
    int i = blockIdx.x * 256 + threadIdx.x;
    if (i >= n4) return;
    float4 v = ((const float4*)in)[i];
    uint32_t h0, l0, h1, l1;
    split_pair_h(v.x, v.y, h0, l0);
    split_pair_h(v.z, v.w, h1, l1);
    ((uint32_t*)hi)[2*i] = h0; ((uint32_t*)hi)[2*i+1] = h1;
    ((uint32_t*)lo)[2*i] = l0; ((uint32_t*)lo)[2*i+1] = l1;
}
__global__ __launch_bounds__(256) void quanth_kernel(const float* __restrict__ in,
                                                     __half* __restrict__ hi, int n4) {
    int i = blockIdx.x * 256 + threadIdx.x;
    if (i >= n4) return;
    float4 v = ((const float4*)in)[i];
    ((uint32_t*)hi)[2*i]   = pack2h(v.x, v.y);
    ((uint32_t*)hi)[2*i+1] = pack2h(v.z, v.w);
}

// --------------- split-fp16 tensor-core GEMM (qkv / proj) -------------------
// D = (Ah+Al) * Bh^T. 12 K-chunks of 64, 3-stage cp.async pipeline.
// Stage: Ah | Al | Bh, 16 KB each (128 rows x 128 B, XOR-swizzled).
#define GST 49152
__device__ __forceinline__ void load_chunk(uint32_t sb,
    const __half* __restrict__ Ah, const __half* __restrict__ Al,
    const __half* __restrict__ Bh, int bm, int bn, int kc, int tid)
{
    const int g = tid & 7;
    const int rb = tid >> 3;
    const int koff = kc * 64 + g * 8;
    #pragma unroll
    for (int i = 0; i < 4; i++) {
        const int r = rb + 32 * i;
        const uint32_t d = SWZ((uint32_t)(r * 128 + g * 16));
        cpa16(sb + 0*16384 + d, Ah + (size_t)(bm + r) * C_ + koff);
        cpa16(sb + 1*16384 + d, Al + (size_t)(bm + r) * C_ + koff);
        cpa16(sb + 2*16384 + d, Bh + (size_t)(bn + r) * C_ + koff);
    }
}

__global__ __launch_bounds__(256, 1) void mma_gemm_kernel(
    const __half* __restrict__ Ah, const __half* __restrict__ Al,
    const __half* __restrict__ Bh,
    const float* __restrict__ bias, float* __restrict__ outp, int mode)
{
    extern __shared__ char dsmem[];
    const int tid = threadIdx.x, wid = tid >> 5, lane = tid & 31;
    const int wm = wid >> 2, wn = wid & 3;
    const uint32_t sb0 = (smem_to_u32(dsmem) + 1023u) & ~1023u;

    const int bm = blockIdx.y * 128, bn = blockIdx.x * 128;
    const int lrow = (lane & 7) + ((lane >> 3) & 1) * 8;
    const int lkb  = (lane >> 4) * 16;

    float acc[4][4][4] = {};

    load_chunk(sb0,         Ah, Al, Bh, bm, bn, 0, tid); CP_COMMIT();
    load_chunk(sb0 + GST,   Ah, Al, Bh, bm, bn, 1, tid); CP_COMMIT();
    load_chunk(sb0 + 2*GST, Ah, Al, Bh, bm, bn, 2, tid); CP_COMMIT();

    int sidx = 0;
    for (int i = 0; i < 12; i++) {
        CP_WAIT2();
        __syncthreads();
        const uint32_t sb = sb0 + sidx * GST;
        #pragma unroll
        for (int ks = 0; ks < 4; ks++) {
            uint32_t ah[4][4], al[4][4];
            #pragma unroll
            for (int mi = 0; mi < 4; mi++) {
                const uint32_t off =
                    SWZ((uint32_t)((wm*64 + mi*16 + lrow) * 128 + ks*32 + lkb));
                LDM4(ah[mi], sb + 0*16384 + off);
                LDM4(al[mi], sb + 1*16384 + off);
            }
            uint32_t bh[2][4];
            #pragma unroll
            for (int nb = 0; nb < 2; nb++) {
                const uint32_t off =
                    SWZ((uint32_t)((wn*32 + nb*16 + lrow) * 128 + ks*32 + lkb));
                LDM4(bh[nb], sb + 2*16384 + off);
            }
            #pragma unroll
            for (int mi = 0; mi < 4; mi++)
                #pragma unroll
                for (int ni = 0; ni < 4; ni++) {
                    const int nb = ni >> 1, hl = ni & 1;
                    MMAH(acc[mi][ni], ah[mi], bh[nb][hl], bh[nb][2+hl]);
                    MMAH(acc[mi][ni], al[mi], bh[nb][hl], bh[nb][2+hl]);
                }
        }
        __syncthreads();
        if (i + 3 < 12) load_chunk(sb, Ah, Al, Bh, bm, bn, i + 3, tid);
        CP_COMMIT();
        sidx = (sidx == 2) ? 0 : sidx + 1;
    }

    const int g = lane >> 2, c2 = (lane & 3) * 2;
    #pragma unroll
    for (int mi = 0; mi < 4; mi++)
        #pragma unroll
        for (int ni = 0; ni < 4; ni++) {
            const int col = bn + wn*32 + ni*8 + c2;
            #pragma unroll
            for (int half = 0; half < 2; half++) {
                const int m = bm + wm*64 + mi*16 + g + half*8;
                float d0 = acc[mi][ni][half*2], d1 = acc[mi][ni][half*2+1];
                if (mode == 0) {
                    const int which = col / C_;
                    const int rest = col - which * C_;
                    const int h = rest >> 6, dd = rest & 63;
                    const int b = m >> 10, tok = m & 1023;
                    const size_t idx = (((size_t)(b * H_ + h) * N_ + tok) * HD + dd) >> 1;
                    if (which == 0) {        // Q: scale + 2-term split
                        uint32_t hp, lp;
                        split_pair_h(d0 * SC2E, d1 * SC2E, hp, lp);
                        ((uint32_t*)g_qh)[idx] = hp;
                        ((uint32_t*)g_ql)[idx] = lp;
                    } else if (which == 1) { // K: single fp16
                        ((uint32_t*)g_kh)[idx] = pack2h(d0, d1);
                    } else {                 // V: single fp16
                        ((uint32_t*)g_vh)[idx] = pack2h(d0, d1);
                    }
                } else {
                    float* p = outp + (size_t)m * C_ + col;
                    p[0] = d0 + bias[col];
                    p[1] = d1 + bias[col + 1];
                }
            }
        }
}

// --------------------- V row-sum per (b,h) ----------------------------------
__global__ __launch_bounds__(256) void vsum_kernel() {
    const int bh = blockIdx.x;
    const int wid = threadIdx.x >> 5, lane = threadIdx.x & 31;
    __shared__ float sm[8][64];
    float a0 = 0.f, a1 = 0.f;
    for (int n = wid * 128; n < wid * 128 + 128; n++) {
        const size_t idx = (((size_t)bh * N_ + n) * HD >> 1) + lane;
        uint32_t hv = ((const uint32_t*)g_vh)[idx];
        __half2 h = *reinterpret_cast<__half2*>(&hv);
        a0 += __low2float(h);
        a1 += __high2float(h);
    }
    sm[wid][lane*2] = a0; sm[wid][lane*2+1] = a1;
    __syncthreads();
    if (threadIdx.x < 64) {
        float s = 0.f;
        #pragma unroll
        for (int w = 0; w < 8; w++) s += sm[w][threadIdx.x];
        g_vsum[bh * HD + threadIdx.x] = s;
    }
}

// ------------------ tensor-core flash attention -----------------------------
// CTA = (128-q tile, b*h). Keys in 128-key tiles, 3-stage pipeline.
// Stage: Kh | Vh (16 KB each). S: (Qh+Ql)*Kh. PV: (Ph+Pl)*Vh.
#define AST 32768
__global__ __launch_bounds__(256, 1) void attn_mma_kernel(const float* __restrict__ policy) {
    extern __shared__ char dsmem[];
    const uint32_t dbase = smem_to_u32(dsmem);
    const uint32_t sb0 = (dbase + 1023u) & ~1023u;
    char* sbp = dsmem + (sb0 - dbase);

    const int qt = blockIdx.x;          // 0..7
    const int bh = blockIdx.y;          // 0..95
    const int b  = bh / H_;
    const int h  = bh - b * H_;
    const int tid = threadIdx.x, w = tid >> 5, lane = tid & 31;
    const int lrow = (lane & 7) + ((lane >> 3) & 1) * 8;
    const int lkb  = (lane >> 4) * 16;
    const int c2   = (lane & 3) * 2;
    const int r0   = lane >> 2;

    const uint32_t QH = sb0, QL = sb0 + 16384;
    const uint32_t ST0 = sb0 + 32768;           // 3 stages x 32 KB
    const uint32_t PK0 = sb0 + 131072;          // 3 x 512 B policy tiles

    const int g8 = tid & 7, rb = tid >> 3;
    const size_t bhN = (size_t)bh * N_;

    // ---- prologue: Q + stages 0,1,2 ----
    #pragma unroll
    for (int i = 0; i < 4; i++) {
        const int r = rb + 32 * i;
        const uint32_t d = SWZ((uint32_t)(r * 128 + g8 * 16));
        const size_t src = (bhN + qt * 128 + r) * HD + g8 * 8;
        cpa16(QH + d, g_qh + src);
        cpa16(QL + d, g_ql + src);
    }
    #pragma unroll
    for (int st = 0; st < 3; st++) {
        #pragma unroll
        for (int i = 0; i < 4; i++) {
            const int r = rb + 32 * i;
            const uint32_t d = SWZ((uint32_t)(r * 128 + g8 * 16));
            const size_t src = (bhN + st * 128 + r) * HD + g8 * 8;
            cpa16(ST0 + st*AST + 0*16384 + d, g_kh + src);
            cpa16(ST0 + st*AST + 1*16384 + d, g_vh + src);
        }
        if (tid < 32) cpa16(PK0 + st * 512 + tid * 16,
                            policy + b * N_ + st * 128 + tid * 4);
        CP_COMMIT();
    }
    CP_WAIT2();
    __syncthreads();

    // Q fragments (register-resident)
    uint32_t qh[4][4], ql[4][4];
    #pragma unroll
    for (int ks = 0; ks < 4; ks++) {
        const uint32_t off = SWZ((uint32_t)((w*16 + lrow) * 128 + ks*32 + lkb));
        LDM4(qh[ks], QH + off);
        LDM4(ql[ks], QL + off);
    }

    const int nq0 = qt * 128 + w * 16 + r0;
    const int nq1 = nq0 + 8;
    const float polq0 = policy[b * N_ + nq0];
    const float polq1 = policy[b * N_ + nq1];

    float m0 = -1e30f, m1 = -1e30f, l0 = 0.f, l1 = 0.f;
    float O[8][4] = {};

    int sidx = 0;
    for (int kt = 0; kt < 8; kt++) {
        const uint32_t ST = ST0 + sidx * AST;
        const float* polKs = (const float*)(sbp + (PK0 - sb0) + sidx * 512);

        // ---- S = Q K^T ----
        float Sf[16][4] = {};
        #pragma unroll
        for (int ks = 0; ks < 4; ks++) {
            #pragma unroll
            for (int ng = 0; ng < 8; ng++) {
                uint32_t kh4[4];
                const uint32_t off = SWZ((uint32_t)((ng*16 + lrow) * 128 + ks*32 + lkb));
                LDM4(kh4, ST + off);
                #pragma unroll
                for (int hl = 0; hl < 2; hl++) {
                    MMAH(Sf[2*ng+hl], qh[ks], kh4[hl], kh4[2+hl]);
                    MMAH(Sf[2*ng+hl], ql[ks], kh4[hl], kh4[2+hl]);
                }
            }
        }

        // ---- online softmax (log2 domain; unmasked max per reference) ----
        float t0 = -1e30f, t1 = -1e30f;
        #pragma unroll
        for (int nf = 0; nf < 16; nf++) {
            t0 = fmaxf(t0, fmaxf(Sf[nf][0], Sf[nf][1]));
            t1 = fmaxf(t1, fmaxf(Sf[nf][2], Sf[nf][3]));
        }
        t0 = fmaxf(t0, __shfl_xor_sync(0xffffffffu, t0, 1));
        t0 = fmaxf(t0, __shfl_xor_sync(0xffffffffu, t0, 2));
        t1 = fmaxf(t1, __shfl_xor_sync(0xffffffffu, t1, 1));
        t1 = fmaxf(t1, __shfl_xor_sync(0xffffffffu, t1, 2));
        const float mn0 = fmaxf(m0, t0), mn1 = fmaxf(m1, t1);
        const float rs0 = exp2_fast(m0 - mn0), rs1 = exp2_fast(m1 - mn1);
        m0 = mn0; m1 = mn1;

        uint32_t ph[8][4], pl[8][4];
        float ps0 = 0.f, ps1 = 0.f;
        #pragma unroll
        for (int nf = 0; nf < 16; nf++) {
            const int col = kt * 128 + nf * 8 + c2;
            const float pk0 = polKs[nf * 8 + c2];
            const float pk1 = polKs[nf * 8 + c2 + 1];
            const float mk00 = (col     == nq0) ? 1.f : polq0 * pk0;
            const float mk01 = (col + 1 == nq0) ? 1.f : polq0 * pk1;
            const float mk10 = (col     == nq1) ? 1.f : polq1 * pk0;
            const float mk11 = (col + 1 == nq1) ? 1.f : polq1 * pk1;
            const float p00 = exp2_fast(Sf[nf][0] - m0) * mk00;
            const float p01 = exp2_fast(Sf[nf][1] - m0) * mk01;
            const float p10 = exp2_fast(Sf[nf][2] - m1) * mk10;
            const float p11 = exp2_fast(Sf[nf][3] - m1) * mk11;
            ps0 += p00 + p01; ps1 += p10 + p11;
            const int kc = nf >> 1, base = (nf & 1) * 2;
            split_pair_h(p00, p01, ph[kc][base],   pl[kc][base]);
            split_pair_h(p10, p11, ph[kc][base+1], pl[kc][base+1]);
        }
        ps0 += __shfl_xor_sync(0xffffffffu, ps0, 1);
        ps0 += __shfl_xor_sync(0xffffffffu, ps0, 2);
        ps1 += __shfl_xor_sync(0xffffffffu, ps1, 1);
        ps1 += __shfl_xor_sync(0xffffffffu, ps1, 2);
        l0 = l0 * rs0 + ps0;
        l1 = l1 * rs1 + ps1;
        #pragma unroll
        for (int nf = 0; nf < 8; nf++) {
            O[nf][0] *= rs0; O[nf][1] *= rs0;
            O[nf][2] *= rs1; O[nf][3] *= rs1;
        }

        // ---- O += P V ----
        #pragma unroll
        for (int kc = 0; kc < 8; kc++) {
            #pragma unroll
            for (int ng = 0; ng < 4; ng++) {
                uint32_t vh4[4];
                const uint32_t off = SWZ((uint32_t)((kc*16 + lrow) * 128 + ng*32 + lkb));
                LDM4T(vh4, ST + 16384 + off);
                #pragma unroll
                for (int hl = 0; hl < 2; hl++) {
                    MMAH(O[2*ng+hl], ph[kc], vh4[2*hl], vh4[2*hl+1]);
                    MMAH(O[2*ng+hl], pl[kc], vh4[2*hl], vh4[2*hl+1]);
                }
            }
        }

        __syncthreads();    // stage consumed
        if (kt + 3 < 8) {
            const int kt3 = kt + 3;
            #pragma unroll
            for (int i = 0; i < 4; i++) {
                const int r = rb + 32 * i;
                const uint32_t d = SWZ((uint32_t)(r * 128 + g8 * 16));
                const size_t src = (bhN + kt3 * 128 + r) * HD + g8 * 8;
                cpa16(ST + 0*16384 + d, g_kh + src);
                cpa16(ST + 1*16384 + d, g_vh + src);
            }
            if (tid < 32) cpa16(PK0 + sidx * 512 + tid * 16,
                                policy + b * N_ + kt3 * 128 + tid * 4);
        }
        CP_COMMIT();
        if (kt + 1 < 8) { CP_WAIT2(); __syncthreads(); }
        sidx = (sidx == 2) ? 0 : sidx + 1;
    }

    // ---- epilogue: (O + eps/N * vsum) / (l + eps) -> fp16 hi/lo aout ----
    const float inv0 = 1.f / (l0 + EPS);
    const float inv1 = 1.f / (l1 + EPS);
    #pragma unroll
    for (int nf = 0; nf < 8; nf++) {
        const int col = nf * 8 + c2;
        const float vs0 = g_vsum[bh * HD + col];
        const float vs1 = g_vsum[bh * HD + col + 1];
        const float o00 = (O[nf][0] + EPSN * vs0) * inv0;
        const float o01 = (O[nf][1] + EPSN * vs1) * inv0;
        const float o10 = (O[nf][2] + EPSN * vs0) * inv1;
        const float o11 = (O[nf][3] + EPSN * vs1) * inv1;
        uint32_t hp, lp;
        split_pair_h(o00, o01, hp, lp);
        const size_t i0 = (((size_t)(b * N_ + nq0)) * C_ + h * HD + col) >> 1;
        ((uint32_t*)g_ah)[i0] = hp; ((uint32_t*)g_al)[i0] = lp;
        split_pair_h(o10, o11, hp, lp);
        const size_t i1 = (((size_t)(b * N_ + nq1)) * C_ + h * HD + col) >> 1;
        ((uint32_t*)g_ah)[i1] = hp; ((uint32_t*)g_al)[i1] = lp;
    }
}

// ---------------------------------------------------------------------------
extern "C" void kernel_launch(void* const* d_in, const int* in_sizes, int n_in,
                              void* d_out, int out_size) {
    const float* x      = (const float*)d_in[0];
    const float* policy = (const float*)d_in[1];
    const float* Wqkv   = (const float*)d_in[2];
    const float* Wproj  = (const float*)d_in[3];
    const float* bproj  = (const float*)d_in[4];
    float* out = (float*)d_out;

    __half *xh, *xl, *wqh, *wph, *ah, *al;
    cudaGetSymbolAddress((void**)&xh,  g_xh);  cudaGetSymbolAddress((void**)&xl,  g_xl);
    cudaGetSymbolAddress((void**)&wqh, g_wqh);
    cudaGetSymbolAddress((void**)&wph, g_wph);
    cudaGetSymbolAddress((void**)&ah,  g_ah);  cudaGetSymbolAddress((void**)&al,  g_al);

    cudaFuncSetAttribute(mma_gemm_kernel,
                         cudaFuncAttributeMaxDynamicSharedMemorySize, 148480);
    cudaFuncSetAttribute(attn_mma_kernel,
                         cudaFuncAttributeMaxDynamicSharedMemorySize, 133632);

    split2h_kernel<<<(M_TOT*C_/4 + 255)/256, 256>>>(x, xh, xl, M_TOT*C_/4);
    quanth_kernel<<<(QKV_N*C_/4 + 255)/256, 256>>>(Wqkv, wqh, QKV_N*C_/4);
    quanth_kernel<<<(C_*C_/4   + 255)/256, 256>>>(Wproj, wph, C_*C_/4);

    mma_gemm_kernel<<<dim3(QKV_N/128, M_TOT/128), 256, 148480>>>(
        xh, xl, wqh, nullptr, nullptr, 0);

    vsum_kernel<<<B_*H_, 256>>>();

    attn_mma_kernel<<<dim3(8, 96), 256, 133632>>>(policy);

    mma_gemm_kernel<<<dim3(C_/128, M_TOT/128), 256, 148480>>>(
        ah, al, wph, bproj, out, 1);
}

// round 10
// speedup vs baseline: 4.3640x; 1.1121x over previous
#include <cuda_runtime.h>
#include <cuda_fp16.h>
#include <cstdint>

#define B_ 8
#define N_ 1024
#define C_ 768
#define H_ 12
#define HD 64
#define M_TOT (B_*N_)
#define QKV_N (3*C_)
#define EPS 1e-6f
#define EPSN (1e-6f/1024.0f)
#define SC2E 0.18033688011112042f
#define SWZ(b) ((b) ^ (((b) >> 3) & 0x70))

__device__ __forceinline__ uint32_t smem_to_u32(const void* p) {
    uint32_t a;
    asm("{ .reg .u64 t; cvta.to.shared.u64 t, %1; cvt.u32.u64 %0, t; }" : "=r"(a) : "l"(p));
    return a;
}
__device__ __forceinline__ void cpa16(uint32_t dst, const void* src) {
    asm volatile("cp.async.cg.shared.global [%0], [%1], 16;" :: "r"(dst), "l"(src));
}
#define CP_COMMIT() asm volatile("cp.async.commit_group;" ::: "memory")
#define CP_WAIT1()  asm volatile("cp.async.wait_group 1;" ::: "memory")
#define CP_WAIT2()  asm volatile("cp.async.wait_group 2;" ::: "memory")
#define LDM4(r, a) \
    asm volatile("ldmatrix.sync.aligned.m8n8.x4.shared.b16 {%0,%1,%2,%3}, [%4];" \
        : "=r"((r)[0]), "=r"((r)[1]), "=r"((r)[2]), "=r"((r)[3]) : "r"(a))
#define LDM4T(r, a) \
    asm volatile("ldmatrix.sync.aligned.m8n8.x4.trans.shared.b16 {%0,%1,%2,%3}, [%4];" \
        : "=r"((r)[0]), "=r"((r)[1]), "=r"((r)[2]), "=r"((r)[3]) : "r"(a))
#define MMAH(d, a, b0, b1) \
    asm volatile("mma.sync.aligned.m16n8k16.row.col.f32.f16.f16.f32 " \
        "{%0,%1,%2,%3}, {%4,%5,%6,%7}, {%8,%9}, {%0,%1,%2,%3};" \
        : "+f"((d)[0]), "+f"((d)[1]), "+f"((d)[2]), "+f"((d)[3]) \
        : "r"((a)[0]), "r"((a)[1]), "r"((a)[2]), "r"((a)[3]), "r"(b0), "r"(b1))

__device__ __forceinline__ uint32_t pack2h(float e0, float e1) {
    uint32_t r;
    asm("cvt.rn.f16x2.f32 %0, %1, %2;" : "=r"(r) : "f"(e1), "f"(e0));
    return r;
}
__device__ __forceinline__ void split_pair_h(float v0, float v1, uint32_t& hp, uint32_t& lp) {
    hp = pack2h(v0, v1);
    __half2 h = *reinterpret_cast<__half2*>(&hp);
    lp = pack2h(v0 - __low2float(h), v1 - __high2float(h));
}
__device__ __forceinline__ float exp2_fast(float x) {
    float t = fmaxf(x, -80.f);
    float z = t + 12582912.f;
    int   n = __float_as_int(z) - 0x4B400000;
    float f = t - (z - 12582912.f);
    float p = 1.3333558e-3f;
    p = fmaf(p, f, 9.618129e-3f);
    p = fmaf(p, f, 5.5504109e-2f);
    p = fmaf(p, f, 2.4022651e-1f);
    p = fmaf(p, f, 6.9314718e-1f);
    p = fmaf(p, f, 1.0f);
    return __int_as_float(__float_as_int(p) + (n << 23));
}

// --------------------------- scratch ---------------------------------------
__device__ __half g_xh[M_TOT*C_], g_xl[M_TOT*C_];
__device__ __half g_wqh[QKV_N*C_];
__device__ __half g_wph[C_*C_];
__device__ __half g_qh[B_*H_*N_*HD], g_ql[B_*H_*N_*HD];   // Q pre-scaled, 2-term
__device__ __half g_kh[B_*H_*N_*HD];                       // K single fp16
__device__ __half g_vh[B_*H_*N_*HD];                       // V single fp16
__device__ __half g_ah[M_TOT*C_], g_al[M_TOT*C_];
__device__ float g_vsum[B_*H_*HD];

// ---------------------- fp32 -> fp16 hi/lo split / quant --------------------
__global__ __launch_bounds__(256) void split2h_kernel(const float* __restrict__ in,
                                                      __half* __restrict__ hi,
                                                      __half* __restrict__ lo, int n4) {
    int i = blockIdx.x * 256 + threadIdx.x;
    if (i >= n4) return;
    float4 v = ((const float4*)in)[i];
    uint32_t h0, l0, h1, l1;
    split_pair_h(v.x, v.y, h0, l0);
    split_pair_h(v.z, v.w, h1, l1);
    ((uint32_t*)hi)[2*i] = h0; ((uint32_t*)hi)[2*i+1] = h1;
    ((uint32_t*)lo)[2*i] = l0; ((uint32_t*)lo)[2*i+1] = l1;
}
__global__ __launch_bounds__(256) void quanth_kernel(const float* __restrict__ in,
                                                     __half* __restrict__ hi, int n4) {
    int i = blockIdx.x * 256 + threadIdx.x;
    if (i >= n4) return;
    float4 v = ((const float4*)in)[i];
    ((uint32_t*)hi)[2*i]   = pack2h(v.x, v.y);
    ((uint32_t*)hi)[2*i+1] = pack2h(v.z, v.w);
}

// --------------- split-fp16 tensor-core GEMM (qkv / proj) -------------------
// D = (Ah+Al) * Bh^T. 12 K-chunks of 64, 2-stage pipeline, 2 CTAs/SM.
#define GST 49152
__device__ __forceinline__ void load_chunk(uint32_t sb,
    const __half* __restrict__ Ah, const __half* __restrict__ Al,
    const __half* __restrict__ Bh, int bm, int bn, int kc, int tid)
{
    const int g = tid & 7;
    const int rb = tid >> 3;
    const int koff = kc * 64 + g * 8;
    #pragma unroll
    for (int i = 0; i < 4; i++) {
        const int r = rb + 32 * i;
        const uint32_t d = SWZ((uint32_t)(r * 128 + g * 16));
        cpa16(sb + 0*16384 + d, Ah + (size_t)(bm + r) * C_ + koff);
        cpa16(sb + 1*16384 + d, Al + (size_t)(bm + r) * C_ + koff);
        cpa16(sb + 2*16384 + d, Bh + (size_t)(bn + r) * C_ + koff);
    }
}

__global__ __launch_bounds__(256, 2) void mma_gemm_kernel(
    const __half* __restrict__ Ah, const __half* __restrict__ Al,
    const __half* __restrict__ Bh,
    const float* __restrict__ bias, float* __restrict__ outp, int mode)
{
    extern __shared__ char dsmem[];
    const int tid = threadIdx.x, wid = tid >> 5, lane = tid & 31;
    const int wm = wid >> 2, wn = wid & 3;
    const uint32_t sb0 = (smem_to_u32(dsmem) + 1023u) & ~1023u;

    const int bm = blockIdx.y * 128, bn = blockIdx.x * 128;
    const int lrow = (lane & 7) + ((lane >> 3) & 1) * 8;
    const int lkb  = (lane >> 4) * 16;

    float acc[4][4][4] = {};

    load_chunk(sb0,       Ah, Al, Bh, bm, bn, 0, tid); CP_COMMIT();
    load_chunk(sb0 + GST, Ah, Al, Bh, bm, bn, 1, tid); CP_COMMIT();

    for (int i = 0; i < 12; i++) {
        CP_WAIT1();
        __syncthreads();
        const uint32_t sb = sb0 + (i & 1) * GST;
        #pragma unroll
        for (int ks = 0; ks < 4; ks++) {
            uint32_t ah[4][4], al[4][4];
            #pragma unroll
            for (int mi = 0; mi < 4; mi++) {
                const uint32_t off =
                    SWZ((uint32_t)((wm*64 + mi*16 + lrow) * 128 + ks*32 + lkb));
                LDM4(ah[mi], sb + 0*16384 + off);
                LDM4(al[mi], sb + 1*16384 + off);
            }
            uint32_t bh[2][4];
            #pragma unroll
            for (int nb = 0; nb < 2; nb++) {
                const uint32_t off =
                    SWZ((uint32_t)((wn*32 + nb*16 + lrow) * 128 + ks*32 + lkb));
                LDM4(bh[nb], sb + 2*16384 + off);
            }
            #pragma unroll
            for (int mi = 0; mi < 4; mi++)
                #pragma unroll
                for (int ni = 0; ni < 4; ni++) {
                    const int nb = ni >> 1, hl = ni & 1;
                    MMAH(acc[mi][ni], ah[mi], bh[nb][hl], bh[nb][2+hl]);
                    MMAH(acc[mi][ni], al[mi], bh[nb][hl], bh[nb][2+hl]);
                }
        }
        __syncthreads();
        if (i + 2 < 12) load_chunk(sb, Ah, Al, Bh, bm, bn, i + 2, tid);
        CP_COMMIT();
    }

    const int g = lane >> 2, c2 = (lane & 3) * 2;
    #pragma unroll
    for (int mi = 0; mi < 4; mi++)
        #pragma unroll
        for (int ni = 0; ni < 4; ni++) {
            const int col = bn + wn*32 + ni*8 + c2;
            #pragma unroll
            for (int half = 0; half < 2; half++) {
                const int m = bm + wm*64 + mi*16 + g + half*8;
                float d0 = acc[mi][ni][half*2], d1 = acc[mi][ni][half*2+1];
                if (mode == 0) {
                    const int which = col / C_;
                    const int rest = col - which * C_;
                    const int h = rest >> 6, dd = rest & 63;
                    const int b = m >> 10, tok = m & 1023;
                    const size_t idx = (((size_t)(b * H_ + h) * N_ + tok) * HD + dd) >> 1;
                    if (which == 0) {        // Q: scale + 2-term split
                        uint32_t hp, lp;
                        split_pair_h(d0 * SC2E, d1 * SC2E, hp, lp);
                        ((uint32_t*)g_qh)[idx] = hp;
                        ((uint32_t*)g_ql)[idx] = lp;
                    } else if (which == 1) { // K: single fp16
                        ((uint32_t*)g_kh)[idx] = pack2h(d0, d1);
                    } else {                 // V: single fp16
                        ((uint32_t*)g_vh)[idx] = pack2h(d0, d1);
                    }
                } else {
                    float* p = outp + (size_t)m * C_ + col;
                    p[0] = d0 + bias[col];
                    p[1] = d1 + bias[col + 1];
                }
            }
        }
}

// --------------------- V row-sum per (b,h) ----------------------------------
__global__ __launch_bounds__(256) void vsum_kernel() {
    const int bh = blockIdx.x;
    const int wid = threadIdx.x >> 5, lane = threadIdx.x & 31;
    __shared__ float sm[8][64];
    float a0 = 0.f, a1 = 0.f;
    for (int n = wid * 128; n < wid * 128 + 128; n++) {
        const size_t idx = (((size_t)bh * N_ + n) * HD >> 1) + lane;
        uint32_t hv = ((const uint32_t*)g_vh)[idx];
        __half2 h = *reinterpret_cast<__half2*>(&hv);
        a0 += __low2float(h);
        a1 += __high2float(h);
    }
    sm[wid][lane*2] = a0; sm[wid][lane*2+1] = a1;
    __syncthreads();
    if (threadIdx.x < 64) {
        float s = 0.f;
        #pragma unroll
        for (int w = 0; w < 8; w++) s += sm[w][threadIdx.x];
        g_vsum[bh * HD + threadIdx.x] = s;
    }
}

// ------------------ tensor-core flash attention -----------------------------
// CTA = (128-q tile, b*h). Keys in 128-key tiles, 3-stage pipeline.
// S: (Qh+Ql)*Kh (2 MMAs). PV: Ph*Vh (1 MMA, P single fp16).
#define AST 32768
__global__ __launch_bounds__(256, 1) void attn_mma_kernel(const float* __restrict__ policy) {
    extern __shared__ char dsmem[];
    const uint32_t dbase = smem_to_u32(dsmem);
    const uint32_t sb0 = (dbase + 1023u) & ~1023u;
    char* sbp = dsmem + (sb0 - dbase);

    const int qt = blockIdx.x;          // 0..7
    const int bh = blockIdx.y;          // 0..95
    const int b  = bh / H_;
    const int h  = bh - b * H_;
    const int tid = threadIdx.x, w = tid >> 5, lane = tid & 31;
    const int lrow = (lane & 7) + ((lane >> 3) & 1) * 8;
    const int lkb  = (lane >> 4) * 16;
    const int c2   = (lane & 3) * 2;
    const int r0   = lane >> 2;

    const uint32_t QH = sb0, QL = sb0 + 16384;
    const uint32_t ST0 = sb0 + 32768;           // 3 stages x 32 KB
    const uint32_t PK0 = sb0 + 131072;          // 3 x 512 B policy tiles

    const int g8 = tid & 7, rb = tid >> 3;
    const size_t bhN = (size_t)bh * N_;

    // ---- prologue: Q + stages 0,1,2 ----
    #pragma unroll
    for (int i = 0; i < 4; i++) {
        const int r = rb + 32 * i;
        const uint32_t d = SWZ((uint32_t)(r * 128 + g8 * 16));
        const size_t src = (bhN + qt * 128 + r) * HD + g8 * 8;
        cpa16(QH + d, g_qh + src);
        cpa16(QL + d, g_ql + src);
    }
    #pragma unroll
    for (int st = 0; st < 3; st++) {
        #pragma unroll
        for (int i = 0; i < 4; i++) {
            const int r = rb + 32 * i;
            const uint32_t d = SWZ((uint32_t)(r * 128 + g8 * 16));
            const size_t src = (bhN + st * 128 + r) * HD + g8 * 8;
            cpa16(ST0 + st*AST + 0*16384 + d, g_kh + src);
            cpa16(ST0 + st*AST + 1*16384 + d, g_vh + src);
        }
        if (tid < 32) cpa16(PK0 + st * 512 + tid * 16,
                            policy + b * N_ + st * 128 + tid * 4);
        CP_COMMIT();
    }
    CP_WAIT2();
    __syncthreads();

    // Q fragments (register-resident)
    uint32_t qh[4][4], ql[4][4];
    #pragma unroll
    for (int ks = 0; ks < 4; ks++) {
        const uint32_t off = SWZ((uint32_t)((w*16 + lrow) * 128 + ks*32 + lkb));
        LDM4(qh[ks], QH + off);
        LDM4(ql[ks], QL + off);
    }

    const int nq0 = qt * 128 + w * 16 + r0;
    const int nq1 = nq0 + 8;
    const float polq0 = policy[b * N_ + nq0];
    const float polq1 = policy[b * N_ + nq1];

    float m0 = -1e30f, m1 = -1e30f, l0 = 0.f, l1 = 0.f;
    float O[8][4] = {};

    int sidx = 0;
    for (int kt = 0; kt < 8; kt++) {
        const uint32_t ST = ST0 + sidx * AST;
        const float* polKs = (const float*)(sbp + (PK0 - sb0) + sidx * 512);

        // ---- S = Q K^T ----
        float Sf[16][4] = {};
        #pragma unroll
        for (int ks = 0; ks < 4; ks++) {
            #pragma unroll
            for (int ng = 0; ng < 8; ng++) {
                uint32_t kh4[4];
                const uint32_t off = SWZ((uint32_t)((ng*16 + lrow) * 128 + ks*32 + lkb));
                LDM4(kh4, ST + off);
                #pragma unroll
                for (int hl = 0; hl < 2; hl++) {
                    MMAH(Sf[2*ng+hl], qh[ks], kh4[hl], kh4[2+hl]);
                    MMAH(Sf[2*ng+hl], ql[ks], kh4[hl], kh4[2+hl]);
                }
            }
        }

        // ---- online softmax (log2 domain; unmasked max per reference) ----
        float t0 = -1e30f, t1 = -1e30f;
        #pragma unroll
        for (int nf = 0; nf < 16; nf++) {
            t0 = fmaxf(t0, fmaxf(Sf[nf][0], Sf[nf][1]));
            t1 = fmaxf(t1, fmaxf(Sf[nf][2], Sf[nf][3]));
        }
        t0 = fmaxf(t0, __shfl_xor_sync(0xffffffffu, t0, 1));
        t0 = fmaxf(t0, __shfl_xor_sync(0xffffffffu, t0, 2));
        t1 = fmaxf(t1, __shfl_xor_sync(0xffffffffu, t1, 1));
        t1 = fmaxf(t1, __shfl_xor_sync(0xffffffffu, t1, 2));
        const float mn0 = fmaxf(m0, t0), mn1 = fmaxf(m1, t1);
        const float rs0 = exp2_fast(m0 - mn0), rs1 = exp2_fast(m1 - mn1);
        m0 = mn0; m1 = mn1;

        uint32_t ph[8][4];
        float ps0 = 0.f, ps1 = 0.f;
        #pragma unroll
        for (int nf = 0; nf < 16; nf++) {
            const int col = kt * 128 + nf * 8 + c2;
            const float pk0 = polKs[nf * 8 + c2];
            const float pk1 = polKs[nf * 8 + c2 + 1];
            const float mk00 = (col     == nq0) ? 1.f : polq0 * pk0;
            const float mk01 = (col + 1 == nq0) ? 1.f : polq0 * pk1;
            const float mk10 = (col     == nq1) ? 1.f : polq1 * pk0;
            const float mk11 = (col + 1 == nq1) ? 1.f : polq1 * pk1;
            const float p00 = exp2_fast(Sf[nf][0] - m0) * mk00;
            const float p01 = exp2_fast(Sf[nf][1] - m0) * mk01;
            const float p10 = exp2_fast(Sf[nf][2] - m1) * mk10;
            const float p11 = exp2_fast(Sf[nf][3] - m1) * mk11;
            ps0 += p00 + p01; ps1 += p10 + p11;
            const int kc = nf >> 1, base = (nf & 1) * 2;
            ph[kc][base]   = pack2h(p00, p01);
            ph[kc][base+1] = pack2h(p10, p11);
        }
        ps0 += __shfl_xor_sync(0xffffffffu, ps0, 1);
        ps0 += __shfl_xor_sync(0xffffffffu, ps0, 2);
        ps1 += __shfl_xor_sync(0xffffffffu, ps1, 1);
        ps1 += __shfl_xor_sync(0xffffffffu, ps1, 2);
        l0 = l0 * rs0 + ps0;
        l1 = l1 * rs1 + ps1;
        #pragma unroll
        for (int nf = 0; nf < 8; nf++) {
            O[nf][0] *= rs0; O[nf][1] *= rs0;
            O[nf][2] *= rs1; O[nf][3] *= rs1;
        }

        // ---- O += P V (P single fp16) ----
        #pragma unroll
        for (int kc = 0; kc < 8; kc++) {
            #pragma unroll
            for (int ng = 0; ng < 4; ng++) {
                uint32_t vh4[4];
                const uint32_t off = SWZ((uint32_t)((kc*16 + lrow) * 128 + ng*32 + lkb));
                LDM4T(vh4, ST + 16384 + off);
                #pragma unroll
                for (int hl = 0; hl < 2; hl++)
                    MMAH(O[2*ng+hl], ph[kc], vh4[2*hl], vh4[2*hl+1]);
            }
        }

        __syncthreads();    // stage consumed
        if (kt + 3 < 8) {
            const int kt3 = kt + 3;
            #pragma unroll
            for (int i = 0; i < 4; i++) {
                const int r = rb + 32 * i;
                const uint32_t d = SWZ((uint32_t)(r * 128 + g8 * 16));
                const size_t src = (bhN + kt3 * 128 + r) * HD + g8 * 8;
                cpa16(ST + 0*16384 + d, g_kh + src);
                cpa16(ST + 1*16384 + d, g_vh + src);
            }
            if (tid < 32) cpa16(PK0 + sidx * 512 + tid * 16,
                                policy + b * N_ + kt3 * 128 + tid * 4);
        }
        CP_COMMIT();
        if (kt + 1 < 8) { CP_WAIT2(); __syncthreads(); }
        sidx = (sidx == 2) ? 0 : sidx + 1;
    }

    // ---- epilogue: (O + eps/N * vsum) / (l + eps) -> fp16 hi/lo aout ----
    const float inv0 = 1.f / (l0 + EPS);
    const float inv1 = 1.f / (l1 + EPS);
    #pragma unroll
    for (int nf = 0; nf < 8; nf++) {
        const int col = nf * 8 + c2;
        const float vs0 = g_vsum[bh * HD + col];
        const float vs1 = g_vsum[bh * HD + col + 1];
        const float o00 = (O[nf][0] + EPSN * vs0) * inv0;
        const float o01 = (O[nf][1] + EPSN * vs1) * inv0;
        const float o10 = (O[nf][2] + EPSN * vs0) * inv1;
        const float o11 = (O[nf][3] + EPSN * vs1) * inv1;
        uint32_t hp, lp;
        split_pair_h(o00, o01, hp, lp);
        const size_t i0 = (((size_t)(b * N_ + nq0)) * C_ + h * HD + col) >> 1;
        ((uint32_t*)g_ah)[i0] = hp; ((uint32_t*)g_al)[i0] = lp;
        split_pair_h(o10, o11, hp, lp);
        const size_t i1 = (((size_t)(b * N_ + nq1)) * C_ + h * HD + col) >> 1;
        ((uint32_t*)g_ah)[i1] = hp; ((uint32_t*)g_al)[i1] = lp;
    }
}

// ---------------------------------------------------------------------------
extern "C" void kernel_launch(void* const* d_in, const int* in_sizes, int n_in,
                              void* d_out, int out_size) {
    const float* x      = (const float*)d_in[0];
    const float* policy = (const float*)d_in[1];
    const float* Wqkv   = (const float*)d_in[2];
    const float* Wproj  = (const float*)d_in[3];
    const float* bproj  = (const float*)d_in[4];
    float* out = (float*)d_out;

    __half *xh, *xl, *wqh, *wph, *ah, *al;
    cudaGetSymbolAddress((void**)&xh,  g_xh);  cudaGetSymbolAddress((void**)&xl,  g_xl);
    cudaGetSymbolAddress((void**)&wqh, g_wqh);
    cudaGetSymbolAddress((void**)&wph, g_wph);
    cudaGetSymbolAddress((void**)&ah,  g_ah);  cudaGetSymbolAddress((void**)&al,  g_al);

    cudaFuncSetAttribute(mma_gemm_kernel,
                         cudaFuncAttributeMaxDynamicSharedMemorySize, 99328);
    cudaFuncSetAttribute(attn_mma_kernel,
                         cudaFuncAttributeMaxDynamicSharedMemorySize, 133632);

    split2h_kernel<<<(M_TOT*C_/4 + 255)/256, 256>>>(x, xh, xl, M_TOT*C_/4);
    quanth_kernel<<<(QKV_N*C_/4 + 255)/256, 256>>>(Wqkv, wqh, QKV_N*C_/4);
    quanth_kernel<<<(C_*C_/4   + 255)/256, 256>>>(Wproj, wph, C_*C_/4);

    mma_gemm_kernel<<<dim3(QKV_N/128, M_TOT/128), 256, 99328>>>(
        xh, xl, wqh, nullptr, nullptr, 0);

    vsum_kernel<<<B_*H_, 256>>>();

    attn_mma_kernel<<<dim3(8, 96), 256, 133632>>>(policy);

    mma_gemm_kernel<<<dim3(C_/128, M_TOT/128), 256, 99328>>>(
        ah, al, wph, bproj, out, 1);
}

// round 11
// speedup vs baseline: 5.7498x; 1.3175x over previous
#include <cuda_runtime.h>
#include <cuda_fp16.h>
#include <cstdint>

#define B_ 8
#define N_ 1024
#define C_ 768
#define H_ 12
#define HD 64
#define M_TOT (B_*N_)
#define QKV_N (3*C_)
#define EPS 1e-6f
#define EPSN (1e-6f/1024.0f)
#define SC2E 0.18033688011112042f
#define SWZ(b) ((b) ^ (((b) >> 3) & 0x70))

__device__ __forceinline__ uint32_t smem_to_u32(const void* p) {
    uint32_t a;
    asm("{ .reg .u64 t; cvta.to.shared.u64 t, %1; cvt.u32.u64 %0, t; }" : "=r"(a) : "l"(p));
    return a;
}
__device__ __forceinline__ void cpa16(uint32_t dst, const void* src) {
    asm volatile("cp.async.cg.shared.global [%0], [%1], 16;" :: "r"(dst), "l"(src));
}
#define CP_COMMIT() asm volatile("cp.async.commit_group;" ::: "memory")
#define CP_WAIT2()  asm volatile("cp.async.wait_group 2;" ::: "memory")
#define LDM4(r, a) \
    asm volatile("ldmatrix.sync.aligned.m8n8.x4.shared.b16 {%0,%1,%2,%3}, [%4];" \
        : "=r"((r)[0]), "=r"((r)[1]), "=r"((r)[2]), "=r"((r)[3]) : "r"(a))
#define LDM4T(r, a) \
    asm volatile("ldmatrix.sync.aligned.m8n8.x4.trans.shared.b16 {%0,%1,%2,%3}, [%4];" \
        : "=r"((r)[0]), "=r"((r)[1]), "=r"((r)[2]), "=r"((r)[3]) : "r"(a))
#define MMAH(d, a, b0, b1) \
    asm volatile("mma.sync.aligned.m16n8k16.row.col.f32.f16.f16.f32 " \
        "{%0,%1,%2,%3}, {%4,%5,%6,%7}, {%8,%9}, {%0,%1,%2,%3};" \
        : "+f"((d)[0]), "+f"((d)[1]), "+f"((d)[2]), "+f"((d)[3]) \
        : "r"((a)[0]), "r"((a)[1]), "r"((a)[2]), "r"((a)[3]), "r"(b0), "r"(b1))

__device__ __forceinline__ uint32_t pack2h(float e0, float e1) {
    uint32_t r;
    asm("cvt.rn.f16x2.f32 %0, %1, %2;" : "=r"(r) : "f"(e1), "f"(e0));
    return r;
}
__device__ __forceinline__ void split_pair_h(float v0, float v1, uint32_t& hp, uint32_t& lp) {
    hp = pack2h(v0, v1);
    __half2 h = *reinterpret_cast<__half2*>(&hp);
    lp = pack2h(v0 - __low2float(h), v1 - __high2float(h));
}
__device__ __forceinline__ float exp2_fast(float x) {
    float t = fmaxf(x, -80.f);
    float z = t + 12582912.f;
    int   n = __float_as_int(z) - 0x4B400000;
    float f = t - (z - 12582912.f);
    float p = 1.3333558e-3f;
    p = fmaf(p, f, 9.618129e-3f);
    p = fmaf(p, f, 5.5504109e-2f);
    p = fmaf(p, f, 2.4022651e-1f);
    p = fmaf(p, f, 6.9314718e-1f);
    p = fmaf(p, f, 1.0f);
    return __int_as_float(__float_as_int(p) + (n << 23));
}

// --------------------------- scratch ---------------------------------------
__device__ __half g_xh[M_TOT*C_];
__device__ __half g_wqh[QKV_N*C_];
__device__ __half g_wph[C_*C_];
__device__ __half g_qh[B_*H_*N_*HD], g_ql[B_*H_*N_*HD];   // Q pre-scaled, 2-term
__device__ __half g_kh[B_*H_*N_*HD];                       // K single fp16
__device__ __half g_vh[B_*H_*N_*HD];                       // V single fp16
__device__ __half g_ah[M_TOT*C_];                          // aout single fp16
__device__ float g_vsum[B_*H_*HD];

// ---------------------- fp32 -> fp16 quant ----------------------------------
__global__ __launch_bounds__(256) void quanth_kernel(const float* __restrict__ in,
                                                     __half* __restrict__ hi, int n4) {
    int i = blockIdx.x * 256 + threadIdx.x;
    if (i >= n4) return;
    float4 v = ((const float4*)in)[i];
    ((uint32_t*)hi)[2*i]   = pack2h(v.x, v.y);
    ((uint32_t*)hi)[2*i+1] = pack2h(v.z, v.w);
}

// --------------- fp16 tensor-core GEMM (qkv / proj) -------------------------
// D = A * B^T. 12 K-chunks of 64, 3-stage pipeline, 2 CTAs/SM.
// Stage: A | B, 16 KB each (128 rows x 128 B, XOR-swizzled).
#define GST 32768
__device__ __forceinline__ void load_chunk(uint32_t sb,
    const __half* __restrict__ Ah, const __half* __restrict__ Bh,
    int bm, int bn, int kc, int tid)
{
    const int g = tid & 7;
    const int rb = tid >> 3;
    const int koff = kc * 64 + g * 8;
    #pragma unroll
    for (int i = 0; i < 4; i++) {
        const int r = rb + 32 * i;
        const uint32_t d = SWZ((uint32_t)(r * 128 + g * 16));
        cpa16(sb + 0*16384 + d, Ah + (size_t)(bm + r) * C_ + koff);
        cpa16(sb + 1*16384 + d, Bh + (size_t)(bn + r) * C_ + koff);
    }
}

__global__ __launch_bounds__(256, 2) void mma_gemm_kernel(
    const __half* __restrict__ Ah, const __half* __restrict__ Bh,
    const float* __restrict__ bias, float* __restrict__ outp, int mode)
{
    extern __shared__ char dsmem[];
    const int tid = threadIdx.x, wid = tid >> 5, lane = tid & 31;
    const int wm = wid >> 2, wn = wid & 3;
    const uint32_t sb0 = (smem_to_u32(dsmem) + 1023u) & ~1023u;

    const int bm = blockIdx.y * 128, bn = blockIdx.x * 128;
    const int lrow = (lane & 7) + ((lane >> 3) & 1) * 8;
    const int lkb  = (lane >> 4) * 16;

    float acc[4][4][4] = {};

    load_chunk(sb0,         Ah, Bh, bm, bn, 0, tid); CP_COMMIT();
    load_chunk(sb0 + GST,   Ah, Bh, bm, bn, 1, tid); CP_COMMIT();
    load_chunk(sb0 + 2*GST, Ah, Bh, bm, bn, 2, tid); CP_COMMIT();

    int sidx = 0;
    for (int i = 0; i < 12; i++) {
        CP_WAIT2();
        __syncthreads();
        const uint32_t sb = sb0 + sidx * GST;
        #pragma unroll
        for (int ks = 0; ks < 4; ks++) {
            uint32_t ah[4][4];
            #pragma unroll
            for (int mi = 0; mi < 4; mi++) {
                const uint32_t off =
                    SWZ((uint32_t)((wm*64 + mi*16 + lrow) * 128 + ks*32 + lkb));
                LDM4(ah[mi], sb + 0*16384 + off);
            }
            uint32_t bh[2][4];
            #pragma unroll
            for (int nb = 0; nb < 2; nb++) {
                const uint32_t off =
                    SWZ((uint32_t)((wn*32 + nb*16 + lrow) * 128 + ks*32 + lkb));
                LDM4(bh[nb], sb + 1*16384 + off);
            }
            #pragma unroll
            for (int mi = 0; mi < 4; mi++)
                #pragma unroll
                for (int ni = 0; ni < 4; ni++) {
                    const int nb = ni >> 1, hl = ni & 1;
                    MMAH(acc[mi][ni], ah[mi], bh[nb][hl], bh[nb][2+hl]);
                }
        }
        __syncthreads();
        if (i + 3 < 12) load_chunk(sb, Ah, Bh, bm, bn, i + 3, tid);
        CP_COMMIT();
        sidx = (sidx == 2) ? 0 : sidx + 1;
    }

    const int g = lane >> 2, c2 = (lane & 3) * 2;
    #pragma unroll
    for (int mi = 0; mi < 4; mi++)
        #pragma unroll
        for (int ni = 0; ni < 4; ni++) {
            const int col = bn + wn*32 + ni*8 + c2;
            #pragma unroll
            for (int half = 0; half < 2; half++) {
                const int m = bm + wm*64 + mi*16 + g + half*8;
                float d0 = acc[mi][ni][half*2], d1 = acc[mi][ni][half*2+1];
                if (mode == 0) {
                    const int which = col / C_;
                    const int rest = col - which * C_;
                    const int h = rest >> 6, dd = rest & 63;
                    const int b = m >> 10, tok = m & 1023;
                    const size_t idx = (((size_t)(b * H_ + h) * N_ + tok) * HD + dd) >> 1;
                    if (which == 0) {        // Q: scale + 2-term split (exact from fp32 acc)
                        uint32_t hp, lp;
                        split_pair_h(d0 * SC2E, d1 * SC2E, hp, lp);
                        ((uint32_t*)g_qh)[idx] = hp;
                        ((uint32_t*)g_ql)[idx] = lp;
                    } else if (which == 1) { // K: single fp16
                        ((uint32_t*)g_kh)[idx] = pack2h(d0, d1);
                    } else {                 // V: single fp16
                        ((uint32_t*)g_vh)[idx] = pack2h(d0, d1);
                    }
                } else {
                    float* p = outp + (size_t)m * C_ + col;
                    p[0] = d0 + bias[col];
                    p[1] = d1 + bias[col + 1];
                }
            }
        }
}

// --------------------- V row-sum per (b,h) ----------------------------------
__global__ __launch_bounds__(256) void vsum_kernel() {
    const int bh = blockIdx.x;
    const int wid = threadIdx.x >> 5, lane = threadIdx.x & 31;
    __shared__ float sm[8][64];
    float a0 = 0.f, a1 = 0.f;
    for (int n = wid * 128; n < wid * 128 + 128; n++) {
        const size_t idx = (((size_t)bh * N_ + n) * HD >> 1) + lane;
        uint32_t hv = ((const uint32_t*)g_vh)[idx];
        __half2 h = *reinterpret_cast<__half2*>(&hv);
        a0 += __low2float(h);
        a1 += __high2float(h);
    }
    sm[wid][lane*2] = a0; sm[wid][lane*2+1] = a1;
    __syncthreads();
    if (threadIdx.x < 64) {
        float s = 0.f;
        #pragma unroll
        for (int w = 0; w < 8; w++) s += sm[w][threadIdx.x];
        g_vsum[bh * HD + threadIdx.x] = s;
    }
}

// ------------------ tensor-core flash attention -----------------------------
// CTA = (128-q tile, b*h). Keys in 128-key tiles, 3-stage pipeline.
// S: (Qh+Ql)*Kh (2 MMAs). PV: Ph*Vh (1 MMA, P single fp16).
#define AST 32768
__global__ __launch_bounds__(256, 1) void attn_mma_kernel(const float* __restrict__ policy) {
    extern __shared__ char dsmem[];
    const uint32_t dbase = smem_to_u32(dsmem);
    const uint32_t sb0 = (dbase + 1023u) & ~1023u;
    char* sbp = dsmem + (sb0 - dbase);

    const int qt = blockIdx.x;          // 0..7
    const int bh = blockIdx.y;          // 0..95
    const int b  = bh / H_;
    const int h  = bh - b * H_;
    const int tid = threadIdx.x, w = tid >> 5, lane = tid & 31;
    const int lrow = (lane & 7) + ((lane >> 3) & 1) * 8;
    const int lkb  = (lane >> 4) * 16;
    const int c2   = (lane & 3) * 2;
    const int r0   = lane >> 2;

    const uint32_t QH = sb0, QL = sb0 + 16384;
    const uint32_t ST0 = sb0 + 32768;           // 3 stages x 32 KB
    const uint32_t PK0 = sb0 + 131072;          // 3 x 512 B policy tiles

    const int g8 = tid & 7, rb = tid >> 3;
    const size_t bhN = (size_t)bh * N_;

    // ---- prologue: Q + stages 0,1,2 ----
    #pragma unroll
    for (int i = 0; i < 4; i++) {
        const int r = rb + 32 * i;
        const uint32_t d = SWZ((uint32_t)(r * 128 + g8 * 16));
        const size_t src = (bhN + qt * 128 + r) * HD + g8 * 8;
        cpa16(QH + d, g_qh + src);
        cpa16(QL + d, g_ql + src);
    }
    #pragma unroll
    for (int st = 0; st < 3; st++) {
        #pragma unroll
        for (int i = 0; i < 4; i++) {
            const int r = rb + 32 * i;
            const uint32_t d = SWZ((uint32_t)(r * 128 + g8 * 16));
            const size_t src = (bhN + st * 128 + r) * HD + g8 * 8;
            cpa16(ST0 + st*AST + 0*16384 + d, g_kh + src);
            cpa16(ST0 + st*AST + 1*16384 + d, g_vh + src);
        }
        if (tid < 32) cpa16(PK0 + st * 512 + tid * 16,
                            policy + b * N_ + st * 128 + tid * 4);
        CP_COMMIT();
    }
    CP_WAIT2();
    __syncthreads();

    // Q fragments (register-resident)
    uint32_t qh[4][4], ql[4][4];
    #pragma unroll
    for (int ks = 0; ks < 4; ks++) {
        const uint32_t off = SWZ((uint32_t)((w*16 + lrow) * 128 + ks*32 + lkb));
        LDM4(qh[ks], QH + off);
        LDM4(ql[ks], QL + off);
    }

    const int nq0 = qt * 128 + w * 16 + r0;
    const int nq1 = nq0 + 8;
    const float polq0 = policy[b * N_ + nq0];
    const float polq1 = policy[b * N_ + nq1];

    float m0 = -1e30f, m1 = -1e30f, l0 = 0.f, l1 = 0.f;
    float O[8][4] = {};

    int sidx = 0;
    for (int kt = 0; kt < 8; kt++) {
        const uint32_t ST = ST0 + sidx * AST;
        const float* polKs = (const float*)(sbp + (PK0 - sb0) + sidx * 512);

        // ---- S = Q K^T ----
        float Sf[16][4] = {};
        #pragma unroll
        for (int ks = 0; ks < 4; ks++) {
            #pragma unroll
            for (int ng = 0; ng < 8; ng++) {
                uint32_t kh4[4];
                const uint32_t off = SWZ((uint32_t)((ng*16 + lrow) * 128 + ks*32 + lkb));
                LDM4(kh4, ST + off);
                #pragma unroll
                for (int hl = 0; hl < 2; hl++) {
                    MMAH(Sf[2*ng+hl], qh[ks], kh4[hl], kh4[2+hl]);
                    MMAH(Sf[2*ng+hl], ql[ks], kh4[hl], kh4[2+hl]);
                }
            }
        }

        // ---- online softmax (log2 domain; unmasked max per reference) ----
        float t0 = -1e30f, t1 = -1e30f;
        #pragma unroll
        for (int nf = 0; nf < 16; nf++) {
            t0 = fmaxf(t0, fmaxf(Sf[nf][0], Sf[nf][1]));
            t1 = fmaxf(t1, fmaxf(Sf[nf][2], Sf[nf][3]));
        }
        t0 = fmaxf(t0, __shfl_xor_sync(0xffffffffu, t0, 1));
        t0 = fmaxf(t0, __shfl_xor_sync(0xffffffffu, t0, 2));
        t1 = fmaxf(t1, __shfl_xor_sync(0xffffffffu, t1, 1));
        t1 = fmaxf(t1, __shfl_xor_sync(0xffffffffu, t1, 2));
        const float mn0 = fmaxf(m0, t0), mn1 = fmaxf(m1, t1);
        const float rs0 = exp2_fast(m0 - mn0), rs1 = exp2_fast(m1 - mn1);
        m0 = mn0; m1 = mn1;

        uint32_t ph[8][4];
        float ps0 = 0.f, ps1 = 0.f;
        #pragma unroll
        for (int nf = 0; nf < 16; nf++) {
            const int col = kt * 128 + nf * 8 + c2;
            const float pk0 = polKs[nf * 8 + c2];
            const float pk1 = polKs[nf * 8 + c2 + 1];
            const float mk00 = (col     == nq0) ? 1.f : polq0 * pk0;
            const float mk01 = (col + 1 == nq0) ? 1.f : polq0 * pk1;
            const float mk10 = (col     == nq1) ? 1.f : polq1 * pk0;
            const float mk11 = (col + 1 == nq1) ? 1.f : polq1 * pk1;
            const float p00 = exp2_fast(Sf[nf][0] - m0) * mk00;
            const float p01 = exp2_fast(Sf[nf][1] - m0) * mk01;
            const float p10 = exp2_fast(Sf[nf][2] - m1) * mk10;
            const float p11 = exp2_fast(Sf[nf][3] - m1) * mk11;
            ps0 += p00 + p01; ps1 += p10 + p11;
            const int kc = nf >> 1, base = (nf & 1) * 2;
            ph[kc][base]   = pack2h(p00, p01);
            ph[kc][base+1] = pack2h(p10, p11);
        }
        ps0 += __shfl_xor_sync(0xffffffffu, ps0, 1);
        ps0 += __shfl_xor_sync(0xffffffffu, ps0, 2);
        ps1 += __shfl_xor_sync(0xffffffffu, ps1, 1);
        ps1 += __shfl_xor_sync(0xffffffffu, ps1, 2);
        l0 = l0 * rs0 + ps0;
        l1 = l1 * rs1 + ps1;
        #pragma unroll
        for (int nf = 0; nf < 8; nf++) {
            O[nf][0] *= rs0; O[nf][1] *= rs0;
            O[nf][2] *= rs1; O[nf][3] *= rs1;
        }

        // ---- O += P V (P single fp16) ----
        #pragma unroll
        for (int kc = 0; kc < 8; kc++) {
            #pragma unroll
            for (int ng = 0; ng < 4; ng++) {
                uint32_t vh4[4];
                const uint32_t off = SWZ((uint32_t)((kc*16 + lrow) * 128 + ng*32 + lkb));
                LDM4T(vh4, ST + 16384 + off);
                #pragma unroll
                for (int hl = 0; hl < 2; hl++)
                    MMAH(O[2*ng+hl], ph[kc], vh4[2*hl], vh4[2*hl+1]);
            }
        }

        __syncthreads();    // stage consumed
        if (kt + 3 < 8) {
            const int kt3 = kt + 3;
            #pragma unroll
            for (int i = 0; i < 4; i++) {
                const int r = rb + 32 * i;
                const uint32_t d = SWZ((uint32_t)(r * 128 + g8 * 16));
                const size_t src = (bhN + kt3 * 128 + r) * HD + g8 * 8;
                cpa16(ST + 0*16384 + d, g_kh + src);
                cpa16(ST + 1*16384 + d, g_vh + src);
            }
            if (tid < 32) cpa16(PK0 + sidx * 512 + tid * 16,
                                policy + b * N_ + kt3 * 128 + tid * 4);
        }
        CP_COMMIT();
        if (kt + 1 < 8) { CP_WAIT2(); __syncthreads(); }
        sidx = (sidx == 2) ? 0 : sidx + 1;
    }

    // ---- epilogue: (O + eps/N * vsum) / (l + eps) -> fp16 aout ----
    const float inv0 = 1.f / (l0 + EPS);
    const float inv1 = 1.f / (l1 + EPS);
    #pragma unroll
    for (int nf = 0; nf < 8; nf++) {
        const int col = nf * 8 + c2;
        const float vs0 = g_vsum[bh * HD + col];
        const float vs1 = g_vsum[bh * HD + col + 1];
        const float o00 = (O[nf][0] + EPSN * vs0) * inv0;
        const float o01 = (O[nf][1] + EPSN * vs1) * inv0;
        const float o10 = (O[nf][2] + EPSN * vs0) * inv1;
        const float o11 = (O[nf][3] + EPSN * vs1) * inv1;
        const size_t i0 = (((size_t)(b * N_ + nq0)) * C_ + h * HD + col) >> 1;
        ((uint32_t*)g_ah)[i0] = pack2h(o00, o01);
        const size_t i1 = (((size_t)(b * N_ + nq1)) * C_ + h * HD + col) >> 1;
        ((uint32_t*)g_ah)[i1] = pack2h(o10, o11);
    }
}

// ---------------------------------------------------------------------------
extern "C" void kernel_launch(void* const* d_in, const int* in_sizes, int n_in,
                              void* d_out, int out_size) {
    const float* x      = (const float*)d_in[0];
    const float* policy = (const float*)d_in[1];
    const float* Wqkv   = (const float*)d_in[2];
    const float* Wproj  = (const float*)d_in[3];
    const float* bproj  = (const float*)d_in[4];
    float* out = (float*)d_out;

    __half *xh, *wqh, *wph, *ah;
    cudaGetSymbolAddress((void**)&xh,  g_xh);
    cudaGetSymbolAddress((void**)&wqh, g_wqh);
    cudaGetSymbolAddress((void**)&wph, g_wph);
    cudaGetSymbolAddress((void**)&ah,  g_ah);

    cudaFuncSetAttribute(mma_gemm_kernel,
                         cudaFuncAttributeMaxDynamicSharedMemorySize, 99328);
    cudaFuncSetAttribute(attn_mma_kernel,
                         cudaFuncAttributeMaxDynamicSharedMemorySize, 133632);

    quanth_kernel<<<(M_TOT*C_/4 + 255)/256, 256>>>(x, xh, M_TOT*C_/4);
    quanth_kernel<<<(QKV_N*C_/4 + 255)/256, 256>>>(Wqkv, wqh, QKV_N*C_/4);
    quanth_kernel<<<(C_*C_/4   + 255)/256, 256>>>(Wproj, wph, C_*C_/4);

    mma_gemm_kernel<<<dim3(QKV_N/128, M_TOT/128), 256, 99328>>>(
        xh, wqh, nullptr, nullptr, 0);

    vsum_kernel<<<B_*H_, 256>>>();

    attn_mma_kernel<<<dim3(8, 96), 256, 133632>>>(policy);

    mma_gemm_kernel<<<dim3(C_/128, M_TOT/128), 256, 99328>>>(
        ah, wph, bproj, out, 1);
}

// round 12
// speedup vs baseline: 6.4511x; 1.1220x over previous
#include <cuda_runtime.h>
#include <cuda_fp16.h>
#include <cstdint>

#define B_ 8
#define N_ 1024
#define C_ 768
#define H_ 12
#define HD 64
#define M_TOT (B_*N_)
#define QKV_N (3*C_)
#define EPS 1e-6f
#define EPSN (1e-6f/1024.0f)
#define SC2E 0.18033688011112042f
#define SWZ(b) ((b) ^ (((b) >> 3) & 0x70))

__device__ __forceinline__ uint32_t smem_to_u32(const void* p) {
    uint32_t a;
    asm("{ .reg .u64 t; cvta.to.shared.u64 t, %1; cvt.u32.u64 %0, t; }" : "=r"(a) : "l"(p));
    return a;
}
__device__ __forceinline__ void cpa16(uint32_t dst, const void* src) {
    asm volatile("cp.async.cg.shared.global [%0], [%1], 16;" :: "r"(dst), "l"(src));
}
#define CP_COMMIT() asm volatile("cp.async.commit_group;" ::: "memory")
#define CP_WAIT2()  asm volatile("cp.async.wait_group 2;" ::: "memory")
#define LDM4(r, a) \
    asm volatile("ldmatrix.sync.aligned.m8n8.x4.shared.b16 {%0,%1,%2,%3}, [%4];" \
        : "=r"((r)[0]), "=r"((r)[1]), "=r"((r)[2]), "=r"((r)[3]) : "r"(a))
#define LDM4T(r, a) \
    asm volatile("ldmatrix.sync.aligned.m8n8.x4.trans.shared.b16 {%0,%1,%2,%3}, [%4];" \
        : "=r"((r)[0]), "=r"((r)[1]), "=r"((r)[2]), "=r"((r)[3]) : "r"(a))
#define MMAH(d, a, b0, b1) \
    asm volatile("mma.sync.aligned.m16n8k16.row.col.f32.f16.f16.f32 " \
        "{%0,%1,%2,%3}, {%4,%5,%6,%7}, {%8,%9}, {%0,%1,%2,%3};" \
        : "+f"((d)[0]), "+f"((d)[1]), "+f"((d)[2]), "+f"((d)[3]) \
        : "r"((a)[0]), "r"((a)[1]), "r"((a)[2]), "r"((a)[3]), "r"(b0), "r"(b1))

__device__ __forceinline__ uint32_t pack2h(float e0, float e1) {
    uint32_t r;
    asm("cvt.rn.f16x2.f32 %0, %1, %2;" : "=r"(r) : "f"(e1), "f"(e0));
    return r;
}
__device__ __forceinline__ float exp2_fast(float x) {
    float t = fmaxf(x, -80.f);
    float z = t + 12582912.f;
    int   n = __float_as_int(z) - 0x4B400000;
    float f = t - (z - 12582912.f);
    float p = 1.3333558e-3f;
    p = fmaf(p, f, 9.618129e-3f);
    p = fmaf(p, f, 5.5504109e-2f);
    p = fmaf(p, f, 2.4022651e-1f);
    p = fmaf(p, f, 6.9314718e-1f);
    p = fmaf(p, f, 1.0f);
    return __int_as_float(__float_as_int(p) + (n << 23));
}

// --------------------------- scratch ---------------------------------------
__device__ __half g_xh[M_TOT*C_];
__device__ __half g_wqh[QKV_N*C_];
__device__ __half g_wph[C_*C_];
__device__ __half g_qh[B_*H_*N_*HD];                       // Q pre-scaled fp16
__device__ __half g_kh[B_*H_*N_*HD];                       // K fp16
__device__ __half g_vh[B_*H_*N_*HD];                       // V fp16
__device__ __half g_ah[M_TOT*C_];                          // aout fp16
__device__ float g_vsum[B_*H_*HD];

// ---------------------- fp32 -> fp16 quant ----------------------------------
__global__ __launch_bounds__(256) void quanth_kernel(const float* __restrict__ in,
                                                     __half* __restrict__ hi, int n4) {
    int i = blockIdx.x * 256 + threadIdx.x;
    if (i >= n4) return;
    float4 v = ((const float4*)in)[i];
    ((uint32_t*)hi)[2*i]   = pack2h(v.x, v.y);
    ((uint32_t*)hi)[2*i+1] = pack2h(v.z, v.w);
}

// --------------- fp16 tensor-core GEMM (qkv / proj) -------------------------
// D = A * B^T. 12 K-chunks of 64, 3-stage pipeline, 2 CTAs/SM.
#define GST 32768
__device__ __forceinline__ void load_chunk(uint32_t sb,
    const __half* __restrict__ Ah, const __half* __restrict__ Bh,
    int bm, int bn, int kc, int tid)
{
    const int g = tid & 7;
    const int rb = tid >> 3;
    const int koff = kc * 64 + g * 8;
    #pragma unroll
    for (int i = 0; i < 4; i++) {
        const int r = rb + 32 * i;
        const uint32_t d = SWZ((uint32_t)(r * 128 + g * 16));
        cpa16(sb + 0*16384 + d, Ah + (size_t)(bm + r) * C_ + koff);
        cpa16(sb + 1*16384 + d, Bh + (size_t)(bn + r) * C_ + koff);
    }
}

__global__ __launch_bounds__(256, 2) void mma_gemm_kernel(
    const __half* __restrict__ Ah, const __half* __restrict__ Bh,
    const float* __restrict__ bias, float* __restrict__ outp, int mode)
{
    extern __shared__ char dsmem[];
    const int tid = threadIdx.x, wid = tid >> 5, lane = tid & 31;
    const int wm = wid >> 2, wn = wid & 3;
    const uint32_t sb0 = (smem_to_u32(dsmem) + 1023u) & ~1023u;

    const int bm = blockIdx.y * 128, bn = blockIdx.x * 128;
    const int lrow = (lane & 7) + ((lane >> 3) & 1) * 8;
    const int lkb  = (lane >> 4) * 16;

    float acc[4][4][4] = {};

    load_chunk(sb0,         Ah, Bh, bm, bn, 0, tid); CP_COMMIT();
    load_chunk(sb0 + GST,   Ah, Bh, bm, bn, 1, tid); CP_COMMIT();
    load_chunk(sb0 + 2*GST, Ah, Bh, bm, bn, 2, tid); CP_COMMIT();

    int sidx = 0;
    for (int i = 0; i < 12; i++) {
        CP_WAIT2();
        __syncthreads();
        const uint32_t sb = sb0 + sidx * GST;
        #pragma unroll
        for (int ks = 0; ks < 4; ks++) {
            uint32_t ah[4][4];
            #pragma unroll
            for (int mi = 0; mi < 4; mi++) {
                const uint32_t off =
                    SWZ((uint32_t)((wm*64 + mi*16 + lrow) * 128 + ks*32 + lkb));
                LDM4(ah[mi], sb + 0*16384 + off);
            }
            uint32_t bh[2][4];
            #pragma unroll
            for (int nb = 0; nb < 2; nb++) {
                const uint32_t off =
                    SWZ((uint32_t)((wn*32 + nb*16 + lrow) * 128 + ks*32 + lkb));
                LDM4(bh[nb], sb + 1*16384 + off);
            }
            #pragma unroll
            for (int mi = 0; mi < 4; mi++)
                #pragma unroll
                for (int ni = 0; ni < 4; ni++) {
                    const int nb = ni >> 1, hl = ni & 1;
                    MMAH(acc[mi][ni], ah[mi], bh[nb][hl], bh[nb][2+hl]);
                }
        }
        __syncthreads();
        if (i + 3 < 12) load_chunk(sb, Ah, Bh, bm, bn, i + 3, tid);
        CP_COMMIT();
        sidx = (sidx == 2) ? 0 : sidx + 1;
    }

    const int g = lane >> 2, c2 = (lane & 3) * 2;
    #pragma unroll
    for (int mi = 0; mi < 4; mi++)
        #pragma unroll
        for (int ni = 0; ni < 4; ni++) {
            const int col = bn + wn*32 + ni*8 + c2;
            #pragma unroll
            for (int half = 0; half < 2; half++) {
                const int m = bm + wm*64 + mi*16 + g + half*8;
                float d0 = acc[mi][ni][half*2], d1 = acc[mi][ni][half*2+1];
                if (mode == 0) {
                    const int which = col / C_;
                    const int rest = col - which * C_;
                    const int h = rest >> 6, dd = rest & 63;
                    const int b = m >> 10, tok = m & 1023;
                    const size_t idx = (((size_t)(b * H_ + h) * N_ + tok) * HD + dd) >> 1;
                    if (which == 0) {        // Q: scaled single fp16
                        ((uint32_t*)g_qh)[idx] = pack2h(d0 * SC2E, d1 * SC2E);
                    } else if (which == 1) { // K
                        ((uint32_t*)g_kh)[idx] = pack2h(d0, d1);
                    } else {                 // V
                        ((uint32_t*)g_vh)[idx] = pack2h(d0, d1);
                    }
                } else {
                    float* p = outp + (size_t)m * C_ + col;
                    p[0] = d0 + bias[col];
                    p[1] = d1 + bias[col + 1];
                }
            }
        }
}

// --------------------- V row-sum per (b,h) ----------------------------------
__global__ __launch_bounds__(256) void vsum_kernel() {
    const int bh = blockIdx.x;
    const int wid = threadIdx.x >> 5, lane = threadIdx.x & 31;
    __shared__ float sm[8][64];
    float a0 = 0.f, a1 = 0.f;
    for (int n = wid * 128; n < wid * 128 + 128; n++) {
        const size_t idx = (((size_t)bh * N_ + n) * HD >> 1) + lane;
        uint32_t hv = ((const uint32_t*)g_vh)[idx];
        __half2 h = *reinterpret_cast<__half2*>(&hv);
        a0 += __low2float(h);
        a1 += __high2float(h);
    }
    sm[wid][lane*2] = a0; sm[wid][lane*2+1] = a1;
    __syncthreads();
    if (threadIdx.x < 64) {
        float s = 0.f;
        #pragma unroll
        for (int w = 0; w < 8; w++) s += sm[w][threadIdx.x];
        g_vsum[bh * HD + threadIdx.x] = s;
    }
}

// ------------------ tensor-core flash attention -----------------------------
// CTA = (128-q tile, b*h). Keys in 128-key tiles, 3-stage pipeline.
// S: Qh*Kh (1 MMA). PV: Ph*Vh + ones-MMA row-sum for l.
#define AST 32768
__global__ __launch_bounds__(256, 1) void attn_mma_kernel(const float* __restrict__ policy) {
    extern __shared__ char dsmem[];
    const uint32_t dbase = smem_to_u32(dsmem);
    const uint32_t sb0 = (dbase + 1023u) & ~1023u;
    char* sbp = dsmem + (sb0 - dbase);

    const int qt = blockIdx.x;          // 0..7
    const int bh = blockIdx.y;          // 0..95
    const int b  = bh / H_;
    const int h  = bh - b * H_;
    const int tid = threadIdx.x, w = tid >> 5, lane = tid & 31;
    const int lrow = (lane & 7) + ((lane >> 3) & 1) * 8;
    const int lkb  = (lane >> 4) * 16;
    const int c2   = (lane & 3) * 2;
    const int r0   = lane >> 2;

    const uint32_t QH = sb0;
    const uint32_t ST0 = sb0 + 16384;           // 3 stages x 32 KB
    const uint32_t PK0 = sb0 + 16384 + 3*AST;   // 3 x 512 B policy tiles

    const int g8 = tid & 7, rb = tid >> 3;
    const size_t bhN = (size_t)bh * N_;
    const uint32_t ONESH = 0x3C003C00u;         // half2(1,1)

    // ---- prologue: Q + stages 0,1,2 ----
    #pragma unroll
    for (int i = 0; i < 4; i++) {
        const int r = rb + 32 * i;
        const uint32_t d = SWZ((uint32_t)(r * 128 + g8 * 16));
        const size_t src = (bhN + qt * 128 + r) * HD + g8 * 8;
        cpa16(QH + d, g_qh + src);
    }
    #pragma unroll
    for (int st = 0; st < 3; st++) {
        #pragma unroll
        for (int i = 0; i < 4; i++) {
            const int r = rb + 32 * i;
            const uint32_t d = SWZ((uint32_t)(r * 128 + g8 * 16));
            const size_t src = (bhN + st * 128 + r) * HD + g8 * 8;
            cpa16(ST0 + st*AST + 0*16384 + d, g_kh + src);
            cpa16(ST0 + st*AST + 1*16384 + d, g_vh + src);
        }
        if (tid < 32) cpa16(PK0 + st * 512 + tid * 16,
                            policy + b * N_ + st * 128 + tid * 4);
        CP_COMMIT();
    }
    CP_WAIT2();
    __syncthreads();

    // Q fragments (register-resident)
    uint32_t qh[4][4];
    #pragma unroll
    for (int ks = 0; ks < 4; ks++) {
        const uint32_t off = SWZ((uint32_t)((w*16 + lrow) * 128 + ks*32 + lkb));
        LDM4(qh[ks], QH + off);
    }

    const int nq0 = qt * 128 + w * 16 + r0;
    const int nq1 = nq0 + 8;
    const float polq0 = policy[b * N_ + nq0];
    const float polq1 = policy[b * N_ + nq1];

    float m0 = -1e30f, m1 = -1e30f;
    float lacc[4] = {};                 // ones-MMA row sums: [0]=row0, [2]=row1
    float O[8][4] = {};

    int sidx = 0;
    for (int kt = 0; kt < 8; kt++) {
        const uint32_t ST = ST0 + sidx * AST;
        const float* polKs = (const float*)(sbp + (PK0 - sb0) + sidx * 512);

        // ---- S = Q K^T ----
        float Sf[16][4] = {};
        #pragma unroll
        for (int ks = 0; ks < 4; ks++) {
            #pragma unroll
            for (int ng = 0; ng < 8; ng++) {
                uint32_t kh4[4];
                const uint32_t off = SWZ((uint32_t)((ng*16 + lrow) * 128 + ks*32 + lkb));
                LDM4(kh4, ST + off);
                #pragma unroll
                for (int hl = 0; hl < 2; hl++)
                    MMAH(Sf[2*ng+hl], qh[ks], kh4[hl], kh4[2+hl]);
            }
        }

        // ---- online softmax (log2 domain; unmasked max per reference) ----
        float t0 = -1e30f, t1 = -1e30f;
        #pragma unroll
        for (int nf = 0; nf < 16; nf++) {
            t0 = fmaxf(t0, fmaxf(Sf[nf][0], Sf[nf][1]));
            t1 = fmaxf(t1, fmaxf(Sf[nf][2], Sf[nf][3]));
        }
        t0 = fmaxf(t0, __shfl_xor_sync(0xffffffffu, t0, 1));
        t0 = fmaxf(t0, __shfl_xor_sync(0xffffffffu, t0, 2));
        t1 = fmaxf(t1, __shfl_xor_sync(0xffffffffu, t1, 1));
        t1 = fmaxf(t1, __shfl_xor_sync(0xffffffffu, t1, 2));
        const float mn0 = fmaxf(m0, t0), mn1 = fmaxf(m1, t1);
        const float rs0 = exp2_fast(m0 - mn0), rs1 = exp2_fast(m1 - mn1);
        m0 = mn0; m1 = mn1;

        uint32_t ph[8][4];
        #pragma unroll
        for (int nf = 0; nf < 16; nf++) {
            const int col = kt * 128 + nf * 8 + c2;
            const float pk0 = polKs[nf * 8 + c2];
            const float pk1 = polKs[nf * 8 + c2 + 1];
            const float mk00 = (col     == nq0) ? 1.f : polq0 * pk0;
            const float mk01 = (col + 1 == nq0) ? 1.f : polq0 * pk1;
            const float mk10 = (col     == nq1) ? 1.f : polq1 * pk0;
            const float mk11 = (col + 1 == nq1) ? 1.f : polq1 * pk1;
            const float p00 = exp2_fast(Sf[nf][0] - m0) * mk00;
            const float p01 = exp2_fast(Sf[nf][1] - m0) * mk01;
            const float p10 = exp2_fast(Sf[nf][2] - m1) * mk10;
            const float p11 = exp2_fast(Sf[nf][3] - m1) * mk11;
            const int kc = nf >> 1, base = (nf & 1) * 2;
            ph[kc][base]   = pack2h(p00, p01);
            ph[kc][base+1] = pack2h(p10, p11);
        }
        // rescale running state
        lacc[0] *= rs0; lacc[1] *= rs0; lacc[2] *= rs1; lacc[3] *= rs1;
        #pragma unroll
        for (int nf = 0; nf < 8; nf++) {
            O[nf][0] *= rs0; O[nf][1] *= rs0;
            O[nf][2] *= rs1; O[nf][3] *= rs1;
        }

        // ---- O += P V ; l += P * ones ----
        #pragma unroll
        for (int kc = 0; kc < 8; kc++) {
            MMAH(lacc, ph[kc], ONESH, ONESH);
            #pragma unroll
            for (int ng = 0; ng < 4; ng++) {
                uint32_t vh4[4];
                const uint32_t off = SWZ((uint32_t)((kc*16 + lrow) * 128 + ng*32 + lkb));
                LDM4T(vh4, ST + 16384 + off);
                #pragma unroll
                for (int hl = 0; hl < 2; hl++)
                    MMAH(O[2*ng+hl], ph[kc], vh4[2*hl], vh4[2*hl+1]);
            }
        }

        __syncthreads();    // stage consumed
        if (kt + 3 < 8) {
            const int kt3 = kt + 3;
            #pragma unroll
            for (int i = 0; i < 4; i++) {
                const int r = rb + 32 * i;
                const uint32_t d = SWZ((uint32_t)(r * 128 + g8 * 16));
                const size_t src = (bhN + kt3 * 128 + r) * HD + g8 * 8;
                cpa16(ST + 0*16384 + d, g_kh + src);
                cpa16(ST + 1*16384 + d, g_vh + src);
            }
            if (tid < 32) cpa16(PK0 + sidx * 512 + tid * 16,
                                policy + b * N_ + kt3 * 128 + tid * 4);
        }
        CP_COMMIT();
        if (kt + 1 < 8) { CP_WAIT2(); __syncthreads(); }
        sidx = (sidx == 2) ? 0 : sidx + 1;
    }

    // ---- epilogue: (O + eps/N * vsum) / (l + eps) -> fp16 aout ----
    const float inv0 = 1.f / (lacc[0] + EPS);
    const float inv1 = 1.f / (lacc[2] + EPS);
    #pragma unroll
    for (int nf = 0; nf < 8; nf++) {
        const int col = nf * 8 + c2;
        const float vs0 = g_vsum[bh * HD + col];
        const float vs1 = g_vsum[bh * HD + col + 1];
        const float o00 = (O[nf][0] + EPSN * vs0) * inv0;
        const float o01 = (O[nf][1] + EPSN * vs1) * inv0;
        const float o10 = (O[nf][2] + EPSN * vs0) * inv1;
        const float o11 = (O[nf][3] + EPSN * vs1) * inv1;
        const size_t i0 = (((size_t)(b * N_ + nq0)) * C_ + h * HD + col) >> 1;
        ((uint32_t*)g_ah)[i0] = pack2h(o00, o01);
        const size_t i1 = (((size_t)(b * N_ + nq1)) * C_ + h * HD + col) >> 1;
        ((uint32_t*)g_ah)[i1] = pack2h(o10, o11);
    }
}

// ---------------------------------------------------------------------------
extern "C" void kernel_launch(void* const* d_in, const int* in_sizes, int n_in,
                              void* d_out, int out_size) {
    const float* x      = (const float*)d_in[0];
    const float* policy = (const float*)d_in[1];
    const float* Wqkv   = (const float*)d_in[2];
    const float* Wproj  = (const float*)d_in[3];
    const float* bproj  = (const float*)d_in[4];
    float* out = (float*)d_out;

    __half *xh, *wqh, *wph, *ah;
    cudaGetSymbolAddress((void**)&xh,  g_xh);
    cudaGetSymbolAddress((void**)&wqh, g_wqh);
    cudaGetSymbolAddress((void**)&wph, g_wph);
    cudaGetSymbolAddress((void**)&ah,  g_ah);

    cudaFuncSetAttribute(mma_gemm_kernel,
                         cudaFuncAttributeMaxDynamicSharedMemorySize, 99328);
    cudaFuncSetAttribute(attn_mma_kernel,
                         cudaFuncAttributeMaxDynamicSharedMemorySize, 118784);

    quanth_kernel<<<(M_TOT*C_/4 + 255)/256, 256>>>(x, xh, M_TOT*C_/4);
    quanth_kernel<<<(QKV_N*C_/4 + 255)/256, 256>>>(Wqkv, wqh, QKV_N*C_/4);
    quanth_kernel<<<(C_*C_/4   + 255)/256, 256>>>(Wproj, wph, C_*C_/4);

    mma_gemm_kernel<<<dim3(QKV_N/128, M_TOT/128), 256, 99328>>>(
        xh, wqh, nullptr, nullptr, 0);

    vsum_kernel<<<B_*H_, 256>>>();

    attn_mma_kernel<<<dim3(8, 96), 256, 118784>>>(policy);

    mma_gemm_kernel<<<dim3(C_/128, M_TOT/128), 256, 99328>>>(
        ah, wph, bproj, out, 1);
}

// round 13
// speedup vs baseline: 6.5615x; 1.0171x over previous
#include <cuda_runtime.h>
#include <cuda_fp16.h>
#include <cstdint>

#define B_ 8
#define N_ 1024
#define C_ 768
#define H_ 12
#define HD 64
#define M_TOT (B_*N_)
#define QKV_N (3*C_)
#define EPS 1e-6f
#define EPSN (1e-6f/1024.0f)
#define SC2E 0.18033688011112042f
#define SWZ(b) ((b) ^ (((b) >> 3) & 0x70))

__device__ __forceinline__ uint32_t smem_to_u32(const void* p) {
    uint32_t a;
    asm("{ .reg .u64 t; cvta.to.shared.u64 t, %1; cvt.u32.u64 %0, t; }" : "=r"(a) : "l"(p));
    return a;
}
__device__ __forceinline__ void cpa16(uint32_t dst, const void* src) {
    asm volatile("cp.async.cg.shared.global [%0], [%1], 16;" :: "r"(dst), "l"(src));
}
#define CP_COMMIT() asm volatile("cp.async.commit_group;" ::: "memory")
#define CP_WAIT1()  asm volatile("cp.async.wait_group 1;" ::: "memory")
#define CP_WAIT2()  asm volatile("cp.async.wait_group 2;" ::: "memory")
#define LDM4(r, a) \
    asm volatile("ldmatrix.sync.aligned.m8n8.x4.shared.b16 {%0,%1,%2,%3}, [%4];" \
        : "=r"((r)[0]), "=r"((r)[1]), "=r"((r)[2]), "=r"((r)[3]) : "r"(a))
#define LDM4T(r, a) \
    asm volatile("ldmatrix.sync.aligned.m8n8.x4.trans.shared.b16 {%0,%1,%2,%3}, [%4];" \
        : "=r"((r)[0]), "=r"((r)[1]), "=r"((r)[2]), "=r"((r)[3]) : "r"(a))
#define MMAH(d, a, b0, b1) \
    asm volatile("mma.sync.aligned.m16n8k16.row.col.f32.f16.f16.f32 " \
        "{%0,%1,%2,%3}, {%4,%5,%6,%7}, {%8,%9}, {%0,%1,%2,%3};" \
        : "+f"((d)[0]), "+f"((d)[1]), "+f"((d)[2]), "+f"((d)[3]) \
        : "r"((a)[0]), "r"((a)[1]), "r"((a)[2]), "r"((a)[3]), "r"(b0), "r"(b1))

__device__ __forceinline__ uint32_t pack2h(float e0, float e1) {
    uint32_t r;
    asm("cvt.rn.f16x2.f32 %0, %1, %2;" : "=r"(r) : "f"(e1), "f"(e0));
    return r;
}
__device__ __forceinline__ float exp2_fast(float x) {
    float t = fmaxf(x, -80.f);
    float z = t + 12582912.f;
    int   n = __float_as_int(z) - 0x4B400000;
    float f = t - (z - 12582912.f);
    float p = 1.3333558e-3f;
    p = fmaf(p, f, 9.618129e-3f);
    p = fmaf(p, f, 5.5504109e-2f);
    p = fmaf(p, f, 2.4022651e-1f);
    p = fmaf(p, f, 6.9314718e-1f);
    p = fmaf(p, f, 1.0f);
    return __int_as_float(__float_as_int(p) + (n << 23));
}

// --------------------------- scratch ---------------------------------------
__device__ __half g_xh[M_TOT*C_];
__device__ __half g_wqh[QKV_N*C_];
__device__ __half g_wph[C_*C_];
__device__ __half g_qh[B_*H_*N_*HD];                       // Q pre-scaled fp16
__device__ __half g_kh[B_*H_*N_*HD];                       // K fp16
__device__ __half g_vh[B_*H_*N_*HD];                       // V fp16
__device__ __half g_ah[M_TOT*C_];                          // aout fp16
__device__ float g_vsum[B_*H_*HD];

// ------------- fused fp32 -> fp16 quant (x | Wqkv | Wproj) ------------------
#define NX4  (M_TOT*C_/4)
#define NWQ4 (QKV_N*C_/4)
#define NWP4 (C_*C_/4)
__global__ __launch_bounds__(256) void quant_all_kernel(const float* __restrict__ x,
                                                        const float* __restrict__ wq,
                                                        const float* __restrict__ wp) {
    int i = blockIdx.x * 256 + threadIdx.x;
    const float* in; __half* outp; int j = i;
    if (j < NX4) { in = x; outp = g_xh; }
    else if ((j -= NX4) < NWQ4) { in = wq; outp = g_wqh; }
    else if ((j -= NWQ4) < NWP4) { in = wp; outp = g_wph; }
    else return;
    float4 v = ((const float4*)in)[j];
    ((uint32_t*)outp)[2*j]   = pack2h(v.x, v.y);
    ((uint32_t*)outp)[2*j+1] = pack2h(v.z, v.w);
}

// --------------- fp16 tensor-core GEMM (qkv / proj) -------------------------
// D = A * B^T. 12 K-chunks of 64, 3-stage pipeline, 2 CTAs/SM.
#define GST 32768
__device__ __forceinline__ void load_chunk(uint32_t sb,
    const __half* __restrict__ Ah, const __half* __restrict__ Bh,
    int bm, int bn, int kc, int tid)
{
    const int g = tid & 7;
    const int rb = tid >> 3;
    const int koff = kc * 64 + g * 8;
    #pragma unroll
    for (int i = 0; i < 4; i++) {
        const int r = rb + 32 * i;
        const uint32_t d = SWZ((uint32_t)(r * 128 + g * 16));
        cpa16(sb + 0*16384 + d, Ah + (size_t)(bm + r) * C_ + koff);
        cpa16(sb + 1*16384 + d, Bh + (size_t)(bn + r) * C_ + koff);
    }
}

__global__ __launch_bounds__(256, 2) void mma_gemm_kernel(
    const __half* __restrict__ Ah, const __half* __restrict__ Bh,
    const float* __restrict__ bias, float* __restrict__ outp, int mode)
{
    extern __shared__ char dsmem[];
    const int tid = threadIdx.x, wid = tid >> 5, lane = tid & 31;
    const int wm = wid >> 2, wn = wid & 3;
    const uint32_t sb0 = (smem_to_u32(dsmem) + 1023u) & ~1023u;

    const int bm = blockIdx.y * 128, bn = blockIdx.x * 128;
    const int lrow = (lane & 7) + ((lane >> 3) & 1) * 8;
    const int lkb  = (lane >> 4) * 16;

    float acc[4][4][4] = {};

    load_chunk(sb0,         Ah, Bh, bm, bn, 0, tid); CP_COMMIT();
    load_chunk(sb0 + GST,   Ah, Bh, bm, bn, 1, tid); CP_COMMIT();
    load_chunk(sb0 + 2*GST, Ah, Bh, bm, bn, 2, tid); CP_COMMIT();

    int sidx = 0;
    for (int i = 0; i < 12; i++) {
        CP_WAIT2();
        __syncthreads();
        const uint32_t sb = sb0 + sidx * GST;
        #pragma unroll
        for (int ks = 0; ks < 4; ks++) {
            uint32_t ah[4][4];
            #pragma unroll
            for (int mi = 0; mi < 4; mi++) {
                const uint32_t off =
                    SWZ((uint32_t)((wm*64 + mi*16 + lrow) * 128 + ks*32 + lkb));
                LDM4(ah[mi], sb + 0*16384 + off);
            }
            uint32_t bh[2][4];
            #pragma unroll
            for (int nb = 0; nb < 2; nb++) {
                const uint32_t off =
                    SWZ((uint32_t)((wn*32 + nb*16 + lrow) * 128 + ks*32 + lkb));
                LDM4(bh[nb], sb + 1*16384 + off);
            }
            #pragma unroll
            for (int mi = 0; mi < 4; mi++)
                #pragma unroll
                for (int ni = 0; ni < 4; ni++) {
                    const int nb = ni >> 1, hl = ni & 1;
                    MMAH(acc[mi][ni], ah[mi], bh[nb][hl], bh[nb][2+hl]);
                }
        }
        __syncthreads();
        if (i + 3 < 12) load_chunk(sb, Ah, Bh, bm, bn, i + 3, tid);
        CP_COMMIT();
        sidx = (sidx == 2) ? 0 : sidx + 1;
    }

    const int g = lane >> 2, c2 = (lane & 3) * 2;
    #pragma unroll
    for (int mi = 0; mi < 4; mi++)
        #pragma unroll
        for (int ni = 0; ni < 4; ni++) {
            const int col = bn + wn*32 + ni*8 + c2;
            #pragma unroll
            for (int half = 0; half < 2; half++) {
                const int m = bm + wm*64 + mi*16 + g + half*8;
                float d0 = acc[mi][ni][half*2], d1 = acc[mi][ni][half*2+1];
                if (mode == 0) {
                    const int which = col / C_;
                    const int rest = col - which * C_;
                    const int h = rest >> 6, dd = rest & 63;
                    const int b = m >> 10, tok = m & 1023;
                    const size_t idx = (((size_t)(b * H_ + h) * N_ + tok) * HD + dd) >> 1;
                    if (which == 0) {        // Q: scaled single fp16
                        ((uint32_t*)g_qh)[idx] = pack2h(d0 * SC2E, d1 * SC2E);
                    } else if (which == 1) { // K
                        ((uint32_t*)g_kh)[idx] = pack2h(d0, d1);
                    } else {                 // V
                        ((uint32_t*)g_vh)[idx] = pack2h(d0, d1);
                    }
                } else {
                    float* p = outp + (size_t)m * C_ + col;
                    p[0] = d0 + bias[col];
                    p[1] = d1 + bias[col + 1];
                }
            }
        }
}

// --------------------- V row-sum per (b,h) ----------------------------------
__global__ __launch_bounds__(256) void vsum_kernel() {
    const int bh = blockIdx.x;
    const int wid = threadIdx.x >> 5, lane = threadIdx.x & 31;
    __shared__ float sm[8][64];
    float a0 = 0.f, a1 = 0.f;
    for (int n = wid * 128; n < wid * 128 + 128; n++) {
        const size_t idx = (((size_t)bh * N_ + n) * HD >> 1) + lane;
        uint32_t hv = ((const uint32_t*)g_vh)[idx];
        __half2 h = *reinterpret_cast<__half2*>(&hv);
        a0 += __low2float(h);
        a1 += __high2float(h);
    }
    sm[wid][lane*2] = a0; sm[wid][lane*2+1] = a1;
    __syncthreads();
    if (threadIdx.x < 64) {
        float s = 0.f;
        #pragma unroll
        for (int w = 0; w < 8; w++) s += sm[w][threadIdx.x];
        g_vsum[bh * HD + threadIdx.x] = s;
    }
}

// ------------------ tensor-core flash attention -----------------------------
// CTA = (128-q tile, b*h). 128-key tiles, 2-stage pipeline, 2 CTAs/SM.
// Softmax processed in two 64-key halves to cap live registers at 128.
#define AST 32768
__global__ __launch_bounds__(256, 2) void attn_mma_kernel(const float* __restrict__ policy) {
    extern __shared__ char dsmem[];
    const uint32_t dbase = smem_to_u32(dsmem);
    const uint32_t sb0 = (dbase + 1023u) & ~1023u;
    char* sbp = dsmem + (sb0 - dbase);

    const int qt = blockIdx.x;          // 0..7
    const int bh = blockIdx.y;          // 0..95
    const int b  = bh / H_;
    const int h  = bh - b * H_;
    const int tid = threadIdx.x, w = tid >> 5, lane = tid & 31;
    const int lrow = (lane & 7) + ((lane >> 3) & 1) * 8;
    const int lkb  = (lane >> 4) * 16;
    const int c2   = (lane & 3) * 2;
    const int r0   = lane >> 2;

    const uint32_t QH = sb0;
    const uint32_t ST0 = sb0 + 16384;            // 2 stages x 32 KB
    const uint32_t PK0 = sb0 + 16384 + 2*AST;    // 2 x 512 B policy tiles

    const int g8 = tid & 7, rb = tid >> 3;
    const size_t bhN = (size_t)bh * N_;
    const uint32_t ONESH = 0x3C003C00u;          // half2(1,1)

    // ---- prologue: (Q + stage0) | stage1 ----
    #pragma unroll
    for (int i = 0; i < 4; i++) {
        const int r = rb + 32 * i;
        const uint32_t d = SWZ((uint32_t)(r * 128 + g8 * 16));
        cpa16(QH + d, g_qh + (bhN + qt * 128 + r) * HD + g8 * 8);
        const size_t src = (bhN + r) * HD + g8 * 8;
        cpa16(ST0 + 0*16384 + d, g_kh + src);
        cpa16(ST0 + 1*16384 + d, g_vh + src);
    }
    if (tid < 32) cpa16(PK0 + tid * 16, policy + b * N_ + tid * 4);
    CP_COMMIT();
    #pragma unroll
    for (int i = 0; i < 4; i++) {
        const int r = rb + 32 * i;
        const uint32_t d = SWZ((uint32_t)(r * 128 + g8 * 16));
        const size_t src = (bhN + 128 + r) * HD + g8 * 8;
        cpa16(ST0 + AST + 0*16384 + d, g_kh + src);
        cpa16(ST0 + AST + 1*16384 + d, g_vh + src);
    }
    if (tid < 32) cpa16(PK0 + 512 + tid * 16, policy + b * N_ + 128 + tid * 4);
    CP_COMMIT();
    CP_WAIT1();
    __syncthreads();

    // Q fragments (register-resident)
    uint32_t qh[4][4];
    #pragma unroll
    for (int ks = 0; ks < 4; ks++) {
        const uint32_t off = SWZ((uint32_t)((w*16 + lrow) * 128 + ks*32 + lkb));
        LDM4(qh[ks], QH + off);
    }

    const int nq0 = qt * 128 + w * 16 + r0;
    const int nq1 = nq0 + 8;
    const float polq0 = policy[b * N_ + nq0];
    const float polq1 = policy[b * N_ + nq1];

    float m0 = -1e30f, m1 = -1e30f;
    float lacc[4] = {};
    float O[8][4] = {};

    int sidx = 0;
    for (int kt = 0; kt < 8; kt++) {
        const uint32_t ST = ST0 + sidx * AST;
        const float* polKs = (const float*)(sbp + (PK0 - sb0) + sidx * 512);

        #pragma unroll
        for (int half = 0; half < 2; half++) {
            // ---- S = Q K^T for this 64-key half ----
            float Sf[8][4] = {};
            #pragma unroll
            for (int ks = 0; ks < 4; ks++) {
                #pragma unroll
                for (int ng = 0; ng < 4; ng++) {
                    uint32_t kh4[4];
                    const int row = half*64 + ng*16 + lrow;
                    const uint32_t off = SWZ((uint32_t)(row * 128 + ks*32 + lkb));
                    LDM4(kh4, ST + off);
                    #pragma unroll
                    for (int hl = 0; hl < 2; hl++)
                        MMAH(Sf[2*ng+hl], qh[ks], kh4[hl], kh4[2+hl]);
                }
            }

            // ---- online softmax update (log2 domain) ----
            float t0 = -1e30f, t1 = -1e30f;
            #pragma unroll
            for (int nf = 0; nf < 8; nf++) {
                t0 = fmaxf(t0, fmaxf(Sf[nf][0], Sf[nf][1]));
                t1 = fmaxf(t1, fmaxf(Sf[nf][2], Sf[nf][3]));
            }
            t0 = fmaxf(t0, __shfl_xor_sync(0xffffffffu, t0, 1));
            t0 = fmaxf(t0, __shfl_xor_sync(0xffffffffu, t0, 2));
            t1 = fmaxf(t1, __shfl_xor_sync(0xffffffffu, t1, 1));
            t1 = fmaxf(t1, __shfl_xor_sync(0xffffffffu, t1, 2));
            const float mn0 = fmaxf(m0, t0), mn1 = fmaxf(m1, t1);
            const float rs0 = exp2_fast(m0 - mn0), rs1 = exp2_fast(m1 - mn1);
            m0 = mn0; m1 = mn1;

            uint32_t ph[4][4];
            #pragma unroll
            for (int nf = 0; nf < 8; nf++) {
                const int col = kt * 128 + half*64 + nf * 8 + c2;
                const float pk0 = polKs[half*64 + nf * 8 + c2];
                const float pk1 = polKs[half*64 + nf * 8 + c2 + 1];
                const float mk00 = (col     == nq0) ? 1.f : polq0 * pk0;
                const float mk01 = (col + 1 == nq0) ? 1.f : polq0 * pk1;
                const float mk10 = (col     == nq1) ? 1.f : polq1 * pk0;
                const float mk11 = (col + 1 == nq1) ? 1.f : polq1 * pk1;
                const float p00 = exp2_fast(Sf[nf][0] - m0) * mk00;
                const float p01 = exp2_fast(Sf[nf][1] - m0) * mk01;
                const float p10 = exp2_fast(Sf[nf][2] - m1) * mk10;
                const float p11 = exp2_fast(Sf[nf][3] - m1) * mk11;
                const int kc = nf >> 1, base = (nf & 1) * 2;
                ph[kc][base]   = pack2h(p00, p01);
                ph[kc][base+1] = pack2h(p10, p11);
            }
            lacc[0] *= rs0; lacc[1] *= rs0; lacc[2] *= rs1; lacc[3] *= rs1;
            #pragma unroll
            for (int nf = 0; nf < 8; nf++) {
                O[nf][0] *= rs0; O[nf][1] *= rs0;
                O[nf][2] *= rs1; O[nf][3] *= rs1;
            }

            // ---- O += P V ; l += P * ones ----
            #pragma unroll
            for (int kc = 0; kc < 4; kc++) {
                MMAH(lacc, ph[kc], ONESH, ONESH);
                #pragma unroll
                for (int ng = 0; ng < 4; ng++) {
                    uint32_t vh4[4];
                    const int vrow = half*64 + kc*16 + lrow;
                    const uint32_t off = SWZ((uint32_t)(vrow * 128 + ng*32 + lkb));
                    LDM4T(vh4, ST + 16384 + off);
                    #pragma unroll
                    for (int hl = 0; hl < 2; hl++)
                        MMAH(O[2*ng+hl], ph[kc], vh4[2*hl], vh4[2*hl+1]);
                }
            }
        }

        __syncthreads();    // stage consumed
        if (kt + 2 < 8) {
            const int kt2 = kt + 2;
            #pragma unroll
            for (int i = 0; i < 4; i++) {
                const int r = rb + 32 * i;
                const uint32_t d = SWZ((uint32_t)(r * 128 + g8 * 16));
                const size_t src = (bhN + kt2 * 128 + r) * HD + g8 * 8;
                cpa16(ST + 0*16384 + d, g_kh + src);
                cpa16(ST + 1*16384 + d, g_vh + src);
            }
            if (tid < 32) cpa16(PK0 + sidx * 512 + tid * 16,
                                policy + b * N_ + kt2 * 128 + tid * 4);
        }
        CP_COMMIT();
        if (kt + 1 < 8) { CP_WAIT1(); __syncthreads(); }
        sidx ^= 1;
    }

    // ---- epilogue: (O + eps/N * vsum) / (l + eps) -> fp16 aout ----
    const float inv0 = 1.f / (lacc[0] + EPS);
    const float inv1 = 1.f / (lacc[2] + EPS);
    #pragma unroll
    for (int nf = 0; nf < 8; nf++) {
        const int col = nf * 8 + c2;
        const float vs0 = g_vsum[bh * HD + col];
        const float vs1 = g_vsum[bh * HD + col + 1];
        const float o00 = (O[nf][0] + EPSN * vs0) * inv0;
        const float o01 = (O[nf][1] + EPSN * vs1) * inv0;
        const float o10 = (O[nf][2] + EPSN * vs0) * inv1;
        const float o11 = (O[nf][3] + EPSN * vs1) * inv1;
        const size_t i0 = (((size_t)(b * N_ + nq0)) * C_ + h * HD + col) >> 1;
        ((uint32_t*)g_ah)[i0] = pack2h(o00, o01);
        const size_t i1 = (((size_t)(b * N_ + nq1)) * C_ + h * HD + col) >> 1;
        ((uint32_t*)g_ah)[i1] = pack2h(o10, o11);
    }
}

// ---------------------------------------------------------------------------
extern "C" void kernel_launch(void* const* d_in, const int* in_sizes, int n_in,
                              void* d_out, int out_size) {
    const float* x      = (const float*)d_in[0];
    const float* policy = (const float*)d_in[1];
    const float* Wqkv   = (const float*)d_in[2];
    const float* Wproj  = (const float*)d_in[3];
    const float* bproj  = (const float*)d_in[4];
    float* out = (float*)d_out;

    __half *xh, *wqh, *wph, *ah;
    cudaGetSymbolAddress((void**)&xh,  g_xh);
    cudaGetSymbolAddress((void**)&wqh, g_wqh);
    cudaGetSymbolAddress((void**)&wph, g_wph);
    cudaGetSymbolAddress((void**)&ah,  g_ah);

    cudaFuncSetAttribute(mma_gemm_kernel,
                         cudaFuncAttributeMaxDynamicSharedMemorySize, 99328);
    cudaFuncSetAttribute(attn_mma_kernel,
                         cudaFuncAttributeMaxDynamicSharedMemorySize, 83968);

    const int qtotal = NX4 + NWQ4 + NWP4;
    quant_all_kernel<<<(qtotal + 255)/256, 256>>>(x, Wqkv, Wproj);

    mma_gemm_kernel<<<dim3(QKV_N/128, M_TOT/128), 256, 99328>>>(
        xh, wqh, nullptr, nullptr, 0);

    vsum_kernel<<<B_*H_, 256>>>();

    attn_mma_kernel<<<dim3(8, 96), 256, 83968>>>(policy);

    mma_gemm_kernel<<<dim3(C_/128, M_TOT/128), 256, 99328>>>(
        ah, wph, bproj, out, 1);
}

// round 14
// speedup vs baseline: 7.0606x; 1.0761x over previous
#include <cuda_runtime.h>
#include <cuda_fp16.h>
#include <cstdint>

#define B_ 8
#define N_ 1024
#define C_ 768
#define H_ 12
#define HD 64
#define M_TOT (B_*N_)
#define QKV_N (3*C_)
#define EPS 1e-6f
#define EPSN (1e-6f/1024.0f)
#define SC2E 0.18033688011112042f
#define SWZ(b) ((b) ^ (((b) >> 3) & 0x70))

__device__ __forceinline__ uint32_t smem_to_u32(const void* p) {
    uint32_t a;
    asm("{ .reg .u64 t; cvta.to.shared.u64 t, %1; cvt.u32.u64 %0, t; }" : "=r"(a) : "l"(p));
    return a;
}
__device__ __forceinline__ void cpa16(uint32_t dst, const void* src) {
    asm volatile("cp.async.cg.shared.global [%0], [%1], 16;" :: "r"(dst), "l"(src));
}
#define CP_COMMIT() asm volatile("cp.async.commit_group;" ::: "memory")
#define CP_WAIT1()  asm volatile("cp.async.wait_group 1;" ::: "memory")
#define CP_WAIT2()  asm volatile("cp.async.wait_group 2;" ::: "memory")
#define LDM4(r, a) \
    asm volatile("ldmatrix.sync.aligned.m8n8.x4.shared.b16 {%0,%1,%2,%3}, [%4];" \
        : "=r"((r)[0]), "=r"((r)[1]), "=r"((r)[2]), "=r"((r)[3]) : "r"(a))
#define LDM4T(r, a) \
    asm volatile("ldmatrix.sync.aligned.m8n8.x4.trans.shared.b16 {%0,%1,%2,%3}, [%4];" \
        : "=r"((r)[0]), "=r"((r)[1]), "=r"((r)[2]), "=r"((r)[3]) : "r"(a))
#define MMAH(d, a, b0, b1) \
    asm volatile("mma.sync.aligned.m16n8k16.row.col.f32.f16.f16.f32 " \
        "{%0,%1,%2,%3}, {%4,%5,%6,%7}, {%8,%9}, {%0,%1,%2,%3};" \
        : "+f"((d)[0]), "+f"((d)[1]), "+f"((d)[2]), "+f"((d)[3]) \
        : "r"((a)[0]), "r"((a)[1]), "r"((a)[2]), "r"((a)[3]), "r"(b0), "r"(b1))

__device__ __forceinline__ uint32_t pack2h(float e0, float e1) {
    uint32_t r;
    asm("cvt.rn.f16x2.f32 %0, %1, %2;" : "=r"(r) : "f"(e1), "f"(e0));
    return r;
}
// MUFU exp2 (2-ulp fp32; frees the FMA pipe)
__device__ __forceinline__ float ex2(float x) {
    float y; asm("ex2.approx.f32 %0, %1;" : "=f"(y) : "f"(x)); return y;
}

// --------------------------- scratch ---------------------------------------
__device__ __half g_xh[M_TOT*C_];
__device__ __half g_wqh[QKV_N*C_];
__device__ __half g_wph[C_*C_];
__device__ __half g_qh[B_*H_*N_*HD];                       // Q pre-scaled fp16
__device__ __half g_kh[B_*H_*N_*HD];                       // K fp16
__device__ __half g_vh[B_*H_*N_*HD];                       // V fp16
__device__ __half g_ah[M_TOT*C_];                          // aout fp16
__device__ float g_vsum[B_*H_*HD];

// ------------- fused fp32 -> fp16 quant (x | Wqkv | Wproj) ------------------
#define NX4  (M_TOT*C_/4)
#define NWQ4 (QKV_N*C_/4)
#define NWP4 (C_*C_/4)
__global__ __launch_bounds__(256) void quant_all_kernel(const float* __restrict__ x,
                                                        const float* __restrict__ wq,
                                                        const float* __restrict__ wp) {
    int i = blockIdx.x * 256 + threadIdx.x;
    const float* in; __half* outp; int j = i;
    if (j < NX4) { in = x; outp = g_xh; }
    else if ((j -= NX4) < NWQ4) { in = wq; outp = g_wqh; }
    else if ((j -= NWQ4) < NWP4) { in = wp; outp = g_wph; }
    else return;
    float4 v = ((const float4*)in)[j];
    ((uint32_t*)outp)[2*j]   = pack2h(v.x, v.y);
    ((uint32_t*)outp)[2*j+1] = pack2h(v.z, v.w);
}

// --------------- fp16 tensor-core GEMM (qkv / proj) -------------------------
// D = A * B^T. 12 K-chunks of 64, 3-stage pipeline, 2 CTAs/SM.
#define GST 32768
__device__ __forceinline__ void load_chunk(uint32_t sb,
    const __half* __restrict__ Ah, const __half* __restrict__ Bh,
    int bm, int bn, int kc, int tid)
{
    const int g = tid & 7;
    const int rb = tid >> 3;
    const int koff = kc * 64 + g * 8;
    #pragma unroll
    for (int i = 0; i < 4; i++) {
        const int r = rb + 32 * i;
        const uint32_t d = SWZ((uint32_t)(r * 128 + g * 16));
        cpa16(sb + 0*16384 + d, Ah + (size_t)(bm + r) * C_ + koff);
        cpa16(sb + 1*16384 + d, Bh + (size_t)(bn + r) * C_ + koff);
    }
}

__global__ __launch_bounds__(256, 2) void mma_gemm_kernel(
    const __half* __restrict__ Ah, const __half* __restrict__ Bh,
    const float* __restrict__ bias, float* __restrict__ outp, int mode)
{
    extern __shared__ char dsmem[];
    const int tid = threadIdx.x, wid = tid >> 5, lane = tid & 31;
    const int wm = wid >> 2, wn = wid & 3;
    const uint32_t sb0 = (smem_to_u32(dsmem) + 1023u) & ~1023u;

    const int bm = blockIdx.y * 128, bn = blockIdx.x * 128;
    const int lrow = (lane & 7) + ((lane >> 3) & 1) * 8;
    const int lkb  = (lane >> 4) * 16;

    float acc[4][4][4] = {};

    load_chunk(sb0,         Ah, Bh, bm, bn, 0, tid); CP_COMMIT();
    load_chunk(sb0 + GST,   Ah, Bh, bm, bn, 1, tid); CP_COMMIT();
    load_chunk(sb0 + 2*GST, Ah, Bh, bm, bn, 2, tid); CP_COMMIT();

    int sidx = 0;
    for (int i = 0; i < 12; i++) {
        CP_WAIT2();
        __syncthreads();
        const uint32_t sb = sb0 + sidx * GST;
        #pragma unroll
        for (int ks = 0; ks < 4; ks++) {
            uint32_t ah[4][4];
            #pragma unroll
            for (int mi = 0; mi < 4; mi++) {
                const uint32_t off =
                    SWZ((uint32_t)((wm*64 + mi*16 + lrow) * 128 + ks*32 + lkb));
                LDM4(ah[mi], sb + 0*16384 + off);
            }
            uint32_t bh[2][4];
            #pragma unroll
            for (int nb = 0; nb < 2; nb++) {
                const uint32_t off =
                    SWZ((uint32_t)((wn*32 + nb*16 + lrow) * 128 + ks*32 + lkb));
                LDM4(bh[nb], sb + 1*16384 + off);
            }
            #pragma unroll
            for (int mi = 0; mi < 4; mi++)
                #pragma unroll
                for (int ni = 0; ni < 4; ni++) {
                    const int nb = ni >> 1, hl = ni & 1;
                    MMAH(acc[mi][ni], ah[mi], bh[nb][hl], bh[nb][2+hl]);
                }
        }
        __syncthreads();
        if (i + 3 < 12) load_chunk(sb, Ah, Bh, bm, bn, i + 3, tid);
        CP_COMMIT();
        sidx = (sidx == 2) ? 0 : sidx + 1;
    }

    const int g = lane >> 2, c2 = (lane & 3) * 2;
    #pragma unroll
    for (int mi = 0; mi < 4; mi++)
        #pragma unroll
        for (int ni = 0; ni < 4; ni++) {
            const int col = bn + wn*32 + ni*8 + c2;
            #pragma unroll
            for (int half = 0; half < 2; half++) {
                const int m = bm + wm*64 + mi*16 + g + half*8;
                float d0 = acc[mi][ni][half*2], d1 = acc[mi][ni][half*2+1];
                if (mode == 0) {
                    const int which = col / C_;
                    const int rest = col - which * C_;
                    const int h = rest >> 6, dd = rest & 63;
                    const int b = m >> 10, tok = m & 1023;
                    const size_t idx = (((size_t)(b * H_ + h) * N_ + tok) * HD + dd) >> 1;
                    if (which == 0) {        // Q: scaled single fp16
                        ((uint32_t*)g_qh)[idx] = pack2h(d0 * SC2E, d1 * SC2E);
                    } else if (which == 1) { // K
                        ((uint32_t*)g_kh)[idx] = pack2h(d0, d1);
                    } else {                 // V
                        ((uint32_t*)g_vh)[idx] = pack2h(d0, d1);
                    }
                } else {
                    float* p = outp + (size_t)m * C_ + col;
                    p[0] = d0 + bias[col];
                    p[1] = d1 + bias[col + 1];
                }
            }
        }
}

// --------------------- V row-sum per (b,h) ----------------------------------
__global__ __launch_bounds__(256) void vsum_kernel() {
    const int bh = blockIdx.x;
    const int wid = threadIdx.x >> 5, lane = threadIdx.x & 31;
    __shared__ float sm[8][64];
    float a0 = 0.f, a1 = 0.f;
    for (int n = wid * 128; n < wid * 128 + 128; n++) {
        const size_t idx = (((size_t)bh * N_ + n) * HD >> 1) + lane;
        uint32_t hv = ((const uint32_t*)g_vh)[idx];
        __half2 h = *reinterpret_cast<__half2*>(&hv);
        a0 += __low2float(h);
        a1 += __high2float(h);
    }
    sm[wid][lane*2] = a0; sm[wid][lane*2+1] = a1;
    __syncthreads();
    if (threadIdx.x < 64) {
        float s = 0.f;
        #pragma unroll
        for (int w = 0; w < 8; w++) s += sm[w][threadIdx.x];
        g_vsum[bh * HD + threadIdx.x] = s;
    }
}

// ------------------ tensor-core flash attention -----------------------------
// CTA = (128-q tile, b*h). 128-key tiles, 2-stage pipeline, 2 CTAs/SM.
// Binary-policy algebra: mask == polq*polK except on the kt==qt tile (diag=1).
#define AST 32768
__global__ __launch_bounds__(256, 2) void attn_mma_kernel(const float* __restrict__ policy) {
    extern __shared__ char dsmem[];
    const uint32_t dbase = smem_to_u32(dsmem);
    const uint32_t sb0 = (dbase + 1023u) & ~1023u;
    char* sbp = dsmem + (sb0 - dbase);

    const int qt = blockIdx.x;          // 0..7
    const int bh = blockIdx.y;          // 0..95
    const int b  = bh / H_;
    const int h  = bh - b * H_;
    const int tid = threadIdx.x, w = tid >> 5, lane = tid & 31;
    const int lrow = (lane & 7) + ((lane >> 3) & 1) * 8;
    const int lkb  = (lane >> 4) * 16;
    const int c2   = (lane & 3) * 2;
    const int r0   = lane >> 2;

    const uint32_t QH = sb0;
    const uint32_t ST0 = sb0 + 16384;            // 2 stages x 32 KB
    const uint32_t PK0 = sb0 + 16384 + 2*AST;    // 2 x 512 B policy tiles

    const int g8 = tid & 7, rb = tid >> 3;
    const size_t bhN = (size_t)bh * N_;
    const uint32_t ONESH = 0x3C003C00u;          // half2(1,1)

    // ---- prologue: (Q + stage0) | stage1 ----
    #pragma unroll
    for (int i = 0; i < 4; i++) {
        const int r = rb + 32 * i;
        const uint32_t d = SWZ((uint32_t)(r * 128 + g8 * 16));
        cpa16(QH + d, g_qh + (bhN + qt * 128 + r) * HD + g8 * 8);
        const size_t src = (bhN + r) * HD + g8 * 8;
        cpa16(ST0 + 0*16384 + d, g_kh + src);
        cpa16(ST0 + 1*16384 + d, g_vh + src);
    }
    if (tid < 32) cpa16(PK0 + tid * 16, policy + b * N_ + tid * 4);
    CP_COMMIT();
    #pragma unroll
    for (int i = 0; i < 4; i++) {
        const int r = rb + 32 * i;
        const uint32_t d = SWZ((uint32_t)(r * 128 + g8 * 16));
        const size_t src = (bhN + 128 + r) * HD + g8 * 8;
        cpa16(ST0 + AST + 0*16384 + d, g_kh + src);
        cpa16(ST0 + AST + 1*16384 + d, g_vh + src);
    }
    if (tid < 32) cpa16(PK0 + 512 + tid * 16, policy + b * N_ + 128 + tid * 4);
    CP_COMMIT();
    CP_WAIT1();
    __syncthreads();

    // Q fragments (register-resident)
    uint32_t qh[4][4];
    #pragma unroll
    for (int ks = 0; ks < 4; ks++) {
        const uint32_t off = SWZ((uint32_t)((w*16 + lrow) * 128 + ks*32 + lkb));
        LDM4(qh[ks], QH + off);
    }

    const int nq0 = qt * 128 + w * 16 + r0;
    const int nq1 = nq0 + 8;
    const float polq0 = policy[b * N_ + nq0];
    const float polq1 = policy[b * N_ + nq1];

    float m0 = -1e30f, m1 = -1e30f;
    float lacc[4] = {};
    float O[8][4] = {};

    int sidx = 0;
    for (int kt = 0; kt < 8; kt++) {
        const uint32_t ST = ST0 + sidx * AST;
        const float* polKs = (const float*)(sbp + (PK0 - sb0) + sidx * 512);
        const bool diag = (kt == qt);

        #pragma unroll
        for (int half = 0; half < 2; half++) {
            // ---- S = Q K^T for this 64-key half ----
            float Sf[8][4] = {};
            #pragma unroll
            for (int ks = 0; ks < 4; ks++) {
                #pragma unroll
                for (int ng = 0; ng < 4; ng++) {
                    uint32_t kh4[4];
                    const int row = half*64 + ng*16 + lrow;
                    const uint32_t off = SWZ((uint32_t)(row * 128 + ks*32 + lkb));
                    LDM4(kh4, ST + off);
                    #pragma unroll
                    for (int hl = 0; hl < 2; hl++)
                        MMAH(Sf[2*ng+hl], qh[ks], kh4[hl], kh4[2+hl]);
                }
            }

            // ---- online softmax update (log2 domain) ----
            float t0 = -1e30f, t1 = -1e30f;
            #pragma unroll
            for (int nf = 0; nf < 8; nf++) {
                t0 = fmaxf(t0, fmaxf(Sf[nf][0], Sf[nf][1]));
                t1 = fmaxf(t1, fmaxf(Sf[nf][2], Sf[nf][3]));
            }
            t0 = fmaxf(t0, __shfl_xor_sync(0xffffffffu, t0, 1));
            t0 = fmaxf(t0, __shfl_xor_sync(0xffffffffu, t0, 2));
            t1 = fmaxf(t1, __shfl_xor_sync(0xffffffffu, t1, 1));
            t1 = fmaxf(t1, __shfl_xor_sync(0xffffffffu, t1, 2));
            const float mn0 = fmaxf(m0, t0), mn1 = fmaxf(m1, t1);
            // ballot-gated rescale (rs==1 when max unchanged)
            const bool upd = (mn0 > m0) || (mn1 > m1);
            if (__ballot_sync(0xffffffffu, upd)) {
                const float rs0 = ex2(m0 - mn0), rs1 = ex2(m1 - mn1);
                lacc[0] *= rs0; lacc[1] *= rs0; lacc[2] *= rs1; lacc[3] *= rs1;
                #pragma unroll
                for (int nf = 0; nf < 8; nf++) {
                    O[nf][0] *= rs0; O[nf][1] *= rs0;
                    O[nf][2] *= rs1; O[nf][3] *= rs1;
                }
            }
            m0 = mn0; m1 = mn1;

            uint32_t ph[4][4];
            #pragma unroll
            for (int nf = 0; nf < 8; nf++) {
                const float pk0 = polKs[half*64 + nf * 8 + c2];
                const float pk1 = polKs[half*64 + nf * 8 + c2 + 1];
                float mk00 = polq0 * pk0;
                float mk01 = polq0 * pk1;
                float mk10 = polq1 * pk0;
                float mk11 = polq1 * pk1;
                if (diag) {     // only the kt==qt tile contains diagonal cells
                    const int col = kt * 128 + half*64 + nf * 8 + c2;
                    if (col     == nq0) mk00 = 1.f;
                    if (col + 1 == nq0) mk01 = 1.f;
                    if (col     == nq1) mk10 = 1.f;
                    if (col + 1 == nq1) mk11 = 1.f;
                }
                const float p00 = ex2(Sf[nf][0] - m0) * mk00;
                const float p01 = ex2(Sf[nf][1] - m0) * mk01;
                const float p10 = ex2(Sf[nf][2] - m1) * mk10;
                const float p11 = ex2(Sf[nf][3] - m1) * mk11;
                const int kc = nf >> 1, base = (nf & 1) * 2;
                ph[kc][base]   = pack2h(p00, p01);
                ph[kc][base+1] = pack2h(p10, p11);
            }

            // ---- O += P V ; l += P * ones ----
            #pragma unroll
            for (int kc = 0; kc < 4; kc++) {
                MMAH(lacc, ph[kc], ONESH, ONESH);
                #pragma unroll
                for (int ng = 0; ng < 4; ng++) {
                    uint32_t vh4[4];
                    const int vrow = half*64 + kc*16 + lrow;
                    const uint32_t off = SWZ((uint32_t)(vrow * 128 + ng*32 + lkb));
                    LDM4T(vh4, ST + 16384 + off);
                    #pragma unroll
                    for (int hl = 0; hl < 2; hl++)
                        MMAH(O[2*ng+hl], ph[kc], vh4[2*hl], vh4[2*hl+1]);
                }
            }
        }

        __syncthreads();    // stage consumed
        if (kt + 2 < 8) {
            const int kt2 = kt + 2;
            #pragma unroll
            for (int i = 0; i < 4; i++) {
                const int r = rb + 32 * i;
                const uint32_t d = SWZ((uint32_t)(r * 128 + g8 * 16));
                const size_t src = (bhN + kt2 * 128 + r) * HD + g8 * 8;
                cpa16(ST + 0*16384 + d, g_kh + src);
                cpa16(ST + 1*16384 + d, g_vh + src);
            }
            if (tid < 32) cpa16(PK0 + sidx * 512 + tid * 16,
                                policy + b * N_ + kt2 * 128 + tid * 4);
        }
        CP_COMMIT();
        if (kt + 1 < 8) { CP_WAIT1(); __syncthreads(); }
        sidx ^= 1;
    }

    // ---- epilogue: (O + eps/N * vsum) / (l + eps) -> fp16 aout ----
    const float inv0 = 1.f / (lacc[0] + EPS);
    const float inv1 = 1.f / (lacc[2] + EPS);
    #pragma unroll
    for (int nf = 0; nf < 8; nf++) {
        const int col = nf * 8 + c2;
        const float vs0 = g_vsum[bh * HD + col];
        const float vs1 = g_vsum[bh * HD + col + 1];
        const float o00 = (O[nf][0] + EPSN * vs0) * inv0;
        const float o01 = (O[nf][1] + EPSN * vs1) * inv0;
        const float o10 = (O[nf][2] + EPSN * vs0) * inv1;
        const float o11 = (O[nf][3] + EPSN * vs1) * inv1;
        const size_t i0 = (((size_t)(b * N_ + nq0)) * C_ + h * HD + col) >> 1;
        ((uint32_t*)g_ah)[i0] = pack2h(o00, o01);
        const size_t i1 = (((size_t)(b * N_ + nq1)) * C_ + h * HD + col) >> 1;
        ((uint32_t*)g_ah)[i1] = pack2h(o10, o11);
    }
}

// ---------------------------------------------------------------------------
extern "C" void kernel_launch(void* const* d_in, const int* in_sizes, int n_in,
                              void* d_out, int out_size) {
    const float* x      = (const float*)d_in[0];
    const float* policy = (const float*)d_in[1];
    const float* Wqkv   = (const float*)d_in[2];
    const float* Wproj  = (const float*)d_in[3];
    const float* bproj  = (const float*)d_in[4];
    float* out = (float*)d_out;

    __half *xh, *wqh, *wph, *ah;
    cudaGetSymbolAddress((void**)&xh,  g_xh);
    cudaGetSymbolAddress((void**)&wqh, g_wqh);
    cudaGetSymbolAddress((void**)&wph, g_wph);
    cudaGetSymbolAddress((void**)&ah,  g_ah);

    cudaFuncSetAttribute(mma_gemm_kernel,
                         cudaFuncAttributeMaxDynamicSharedMemorySize, 99328);
    cudaFuncSetAttribute(attn_mma_kernel,
                         cudaFuncAttributeMaxDynamicSharedMemorySize, 83968);

    const int qtotal = NX4 + NWQ4 + NWP4;
    quant_all_kernel<<<(qtotal + 255)/256, 256>>>(x, Wqkv, Wproj);

    mma_gemm_kernel<<<dim3(QKV_N/128, M_TOT/128), 256, 99328>>>(
        xh, wqh, nullptr, nullptr, 0);

    vsum_kernel<<<B_*H_, 256>>>();

    attn_mma_kernel<<<dim3(8, 96), 256, 83968>>>(policy);

    mma_gemm_kernel<<<dim3(C_/128, M_TOT/128), 256, 99328>>>(
        ah, wph, bproj, out, 1);
}

// round 15
// speedup vs baseline: 7.4088x; 1.0493x over previous
#include <cuda_runtime.h>
#include <cuda_fp16.h>
#include <cstdint>

#define B_ 8
#define N_ 1024
#define C_ 768
#define H_ 12
#define HD 64
#define M_TOT (B_*N_)
#define QKV_N (3*C_)
#define EPS 1e-6f
#define EPSN (1e-6f/1024.0f)
#define SC2E 0.18033688011112042f
#define SWZ(b) ((b) ^ (((b) >> 3) & 0x70))

__device__ __forceinline__ uint32_t smem_to_u32(const void* p) {
    uint32_t a;
    asm("{ .reg .u64 t; cvta.to.shared.u64 t, %1; cvt.u32.u64 %0, t; }" : "=r"(a) : "l"(p));
    return a;
}
__device__ __forceinline__ void cpa16(uint32_t dst, const void* src) {
    asm volatile("cp.async.cg.shared.global [%0], [%1], 16;" :: "r"(dst), "l"(src));
}
#define CP_COMMIT() asm volatile("cp.async.commit_group;" ::: "memory")
#define CP_WAIT1()  asm volatile("cp.async.wait_group 1;" ::: "memory")
#define CP_WAIT2()  asm volatile("cp.async.wait_group 2;" ::: "memory")
#define LDM4(r, a) \
    asm volatile("ldmatrix.sync.aligned.m8n8.x4.shared.b16 {%0,%1,%2,%3}, [%4];" \
        : "=r"((r)[0]), "=r"((r)[1]), "=r"((r)[2]), "=r"((r)[3]) : "r"(a))
#define LDM4T(r, a) \
    asm volatile("ldmatrix.sync.aligned.m8n8.x4.trans.shared.b16 {%0,%1,%2,%3}, [%4];" \
        : "=r"((r)[0]), "=r"((r)[1]), "=r"((r)[2]), "=r"((r)[3]) : "r"(a))
#define MMAH(d, a, b0, b1) \
    asm volatile("mma.sync.aligned.m16n8k16.row.col.f32.f16.f16.f32 " \
        "{%0,%1,%2,%3}, {%4,%5,%6,%7}, {%8,%9}, {%0,%1,%2,%3};" \
        : "+f"((d)[0]), "+f"((d)[1]), "+f"((d)[2]), "+f"((d)[3]) \
        : "r"((a)[0]), "r"((a)[1]), "r"((a)[2]), "r"((a)[3]), "r"(b0), "r"(b1))

__device__ __forceinline__ uint32_t pack2h(float e0, float e1) {
    uint32_t r;
    asm("cvt.rn.f16x2.f32 %0, %1, %2;" : "=r"(r) : "f"(e1), "f"(e0));
    return r;
}
__device__ __forceinline__ float ex2(float x) {
    float y; asm("ex2.approx.f32 %0, %1;" : "=f"(y) : "f"(x)); return y;
}
__device__ __forceinline__ uint32_t ex2h2(uint32_t x) {
    uint32_t y; asm("ex2.approx.f16x2 %0, %1;" : "=r"(y) : "r"(x)); return y;
}
__device__ __forceinline__ uint32_t hmul2(uint32_t a, uint32_t b) {
    uint32_t y; asm("mul.f16x2 %0, %1, %2;" : "=r"(y) : "r"(a), "r"(b)); return y;
}

// --------------------------- scratch ---------------------------------------
__device__ __half g_xh[M_TOT*C_];
__device__ __half g_wqh[QKV_N*C_];
__device__ __half g_wph[C_*C_];
__device__ __half g_polh[B_*N_];                           // policy fp16
__device__ __half g_qh[B_*H_*N_*HD];                       // Q pre-scaled fp16
__device__ __half g_kh[B_*H_*N_*HD];                       // K fp16
__device__ __half g_vh[B_*H_*N_*HD];                       // V fp16
__device__ __half g_ah[M_TOT*C_];                          // aout fp16
__device__ float g_vsum[B_*H_*HD];

// -------- fused fp32 -> fp16 quant (x | Wqkv | Wproj | policy) --------------
#define NX4  (M_TOT*C_/4)
#define NWQ4 (QKV_N*C_/4)
#define NWP4 (C_*C_/4)
#define NP4  (B_*N_/4)
__global__ __launch_bounds__(256) void quant_all_kernel(const float* __restrict__ x,
                                                        const float* __restrict__ wq,
                                                        const float* __restrict__ wp,
                                                        const float* __restrict__ pol) {
    int i = blockIdx.x * 256 + threadIdx.x;
    const float* in; __half* outp; int j = i;
    if (j < NX4) { in = x; outp = g_xh; }
    else if ((j -= NX4) < NWQ4) { in = wq; outp = g_wqh; }
    else if ((j -= NWQ4) < NWP4) { in = wp; outp = g_wph; }
    else if ((j -= NWP4) < NP4) { in = pol; outp = g_polh; }
    else return;
    float4 v = ((const float4*)in)[j];
    ((uint32_t*)outp)[2*j]   = pack2h(v.x, v.y);
    ((uint32_t*)outp)[2*j+1] = pack2h(v.z, v.w);
}

// --------------- fp16 tensor-core GEMM (qkv / proj) -------------------------
// D = A * B^T. 12 K-chunks of 64, 3-stage pipeline, 2 CTAs/SM.
#define GST 32768
__device__ __forceinline__ void load_chunk(uint32_t sb,
    const __half* __restrict__ Ah, const __half* __restrict__ Bh,
    int bm, int bn, int kc, int tid)
{
    const int g = tid & 7;
    const int rb = tid >> 3;
    const int koff = kc * 64 + g * 8;
    #pragma unroll
    for (int i = 0; i < 4; i++) {
        const int r = rb + 32 * i;
        const uint32_t d = SWZ((uint32_t)(r * 128 + g * 16));
        cpa16(sb + 0*16384 + d, Ah + (size_t)(bm + r) * C_ + koff);
        cpa16(sb + 1*16384 + d, Bh + (size_t)(bn + r) * C_ + koff);
    }
}

__global__ __launch_bounds__(256, 2) void mma_gemm_kernel(
    const __half* __restrict__ Ah, const __half* __restrict__ Bh,
    const float* __restrict__ bias, float* __restrict__ outp, int mode)
{
    extern __shared__ char dsmem[];
    const int tid = threadIdx.x, wid = tid >> 5, lane = tid & 31;
    const int wm = wid >> 2, wn = wid & 3;
    const uint32_t sb0 = (smem_to_u32(dsmem) + 1023u) & ~1023u;

    const int bm = blockIdx.y * 128, bn = blockIdx.x * 128;
    const int lrow = (lane & 7) + ((lane >> 3) & 1) * 8;
    const int lkb  = (lane >> 4) * 16;

    float acc[4][4][4] = {};

    load_chunk(sb0,         Ah, Bh, bm, bn, 0, tid); CP_COMMIT();
    load_chunk(sb0 + GST,   Ah, Bh, bm, bn, 1, tid); CP_COMMIT();
    load_chunk(sb0 + 2*GST, Ah, Bh, bm, bn, 2, tid); CP_COMMIT();

    int sidx = 0;
    for (int i = 0; i < 12; i++) {
        CP_WAIT2();
        __syncthreads();
        const uint32_t sb = sb0 + sidx * GST;
        #pragma unroll
        for (int ks = 0; ks < 4; ks++) {
            uint32_t ah[4][4];
            #pragma unroll
            for (int mi = 0; mi < 4; mi++) {
                const uint32_t off =
                    SWZ((uint32_t)((wm*64 + mi*16 + lrow) * 128 + ks*32 + lkb));
                LDM4(ah[mi], sb + 0*16384 + off);
            }
            uint32_t bh[2][4];
            #pragma unroll
            for (int nb = 0; nb < 2; nb++) {
                const uint32_t off =
                    SWZ((uint32_t)((wn*32 + nb*16 + lrow) * 128 + ks*32 + lkb));
                LDM4(bh[nb], sb + 1*16384 + off);
            }
            #pragma unroll
            for (int mi = 0; mi < 4; mi++)
                #pragma unroll
                for (int ni = 0; ni < 4; ni++) {
                    const int nb = ni >> 1, hl = ni & 1;
                    MMAH(acc[mi][ni], ah[mi], bh[nb][hl], bh[nb][2+hl]);
                }
        }
        __syncthreads();
        if (i + 3 < 12) load_chunk(sb, Ah, Bh, bm, bn, i + 3, tid);
        CP_COMMIT();
        sidx = (sidx == 2) ? 0 : sidx + 1;
    }

    const int g = lane >> 2, c2 = (lane & 3) * 2;
    #pragma unroll
    for (int mi = 0; mi < 4; mi++)
        #pragma unroll
        for (int ni = 0; ni < 4; ni++) {
            const int col = bn + wn*32 + ni*8 + c2;
            #pragma unroll
            for (int half = 0; half < 2; half++) {
                const int m = bm + wm*64 + mi*16 + g + half*8;
                float d0 = acc[mi][ni][half*2], d1 = acc[mi][ni][half*2+1];
                if (mode == 0) {
                    const int which = col / C_;
                    const int rest = col - which * C_;
                    const int h = rest >> 6, dd = rest & 63;
                    const int b = m >> 10, tok = m & 1023;
                    const size_t idx = (((size_t)(b * H_ + h) * N_ + tok) * HD + dd) >> 1;
                    if (which == 0) {        // Q: scaled single fp16
                        ((uint32_t*)g_qh)[idx] = pack2h(d0 * SC2E, d1 * SC2E);
                    } else if (which == 1) { // K
                        ((uint32_t*)g_kh)[idx] = pack2h(d0, d1);
                    } else {                 // V
                        ((uint32_t*)g_vh)[idx] = pack2h(d0, d1);
                    }
                } else {
                    float* p = outp + (size_t)m * C_ + col;
                    p[0] = d0 + bias[col];
                    p[1] = d1 + bias[col + 1];
                }
            }
        }
}

// --------------------- V row-sum per (b,h) ----------------------------------
__global__ __launch_bounds__(256) void vsum_kernel() {
    const int bh = blockIdx.x;
    const int wid = threadIdx.x >> 5, lane = threadIdx.x & 31;
    __shared__ float sm[8][64];
    float a0 = 0.f, a1 = 0.f;
    for (int n = wid * 128; n < wid * 128 + 128; n++) {
        const size_t idx = (((size_t)bh * N_ + n) * HD >> 1) + lane;
        uint32_t hv = ((const uint32_t*)g_vh)[idx];
        __half2 h = *reinterpret_cast<__half2*>(&hv);
        a0 += __low2float(h);
        a1 += __high2float(h);
    }
    sm[wid][lane*2] = a0; sm[wid][lane*2+1] = a1;
    __syncthreads();
    if (threadIdx.x < 64) {
        float s = 0.f;
        #pragma unroll
        for (int w = 0; w < 8; w++) s += sm[w][threadIdx.x];
        g_vsum[bh * HD + threadIdx.x] = s;
    }
}

// ------------------ tensor-core flash attention -----------------------------
// CTA = (128-q tile, b*h). 128-key tiles, 2-stage pipeline, 2 CTAs/SM.
// Softmax in f16x2 (ex2.approx.f16x2); diag tile uses exact fp32 path.
#define AST 32768
__global__ __launch_bounds__(256, 2) void attn_mma_kernel(const float* __restrict__ policy) {
    extern __shared__ char dsmem[];
    const uint32_t dbase = smem_to_u32(dsmem);
    const uint32_t sb0 = (dbase + 1023u) & ~1023u;
    char* sbp = dsmem + (sb0 - dbase);

    const int qt = blockIdx.x;          // 0..7
    const int bh = blockIdx.y;          // 0..95
    const int b  = bh / H_;
    const int h  = bh - b * H_;
    const int tid = threadIdx.x, w = tid >> 5, lane = tid & 31;
    const int lrow = (lane & 7) + ((lane >> 3) & 1) * 8;
    const int lkb  = (lane >> 4) * 16;
    const int c2   = (lane & 3) * 2;
    const int r0   = lane >> 2;

    const uint32_t QH = sb0;
    const uint32_t ST0 = sb0 + 16384;            // 2 stages x 32 KB
    const uint32_t PK0 = sb0 + 16384 + 2*AST;    // 2 x 256 B fp16 policy tiles

    const int g8 = tid & 7, rb = tid >> 3;
    const size_t bhN = (size_t)bh * N_;
    const uint32_t ONESH = 0x3C003C00u;          // half2(1,1)

    // ---- prologue: (Q + stage0) | stage1 ----
    #pragma unroll
    for (int i = 0; i < 4; i++) {
        const int r = rb + 32 * i;
        const uint32_t d = SWZ((uint32_t)(r * 128 + g8 * 16));
        cpa16(QH + d, g_qh + (bhN + qt * 128 + r) * HD + g8 * 8);
        const size_t src = (bhN + r) * HD + g8 * 8;
        cpa16(ST0 + 0*16384 + d, g_kh + src);
        cpa16(ST0 + 1*16384 + d, g_vh + src);
    }
    if (tid < 16) cpa16(PK0 + tid * 16, g_polh + b * N_ + tid * 8);
    CP_COMMIT();
    #pragma unroll
    for (int i = 0; i < 4; i++) {
        const int r = rb + 32 * i;
        const uint32_t d = SWZ((uint32_t)(r * 128 + g8 * 16));
        const size_t src = (bhN + 128 + r) * HD + g8 * 8;
        cpa16(ST0 + AST + 0*16384 + d, g_kh + src);
        cpa16(ST0 + AST + 1*16384 + d, g_vh + src);
    }
    if (tid < 16) cpa16(PK0 + 256 + tid * 16, g_polh + b * N_ + 128 + tid * 8);
    CP_COMMIT();
    CP_WAIT1();
    __syncthreads();

    // Q fragments (register-resident)
    uint32_t qh[4][4];
    #pragma unroll
    for (int ks = 0; ks < 4; ks++) {
        const uint32_t off = SWZ((uint32_t)((w*16 + lrow) * 128 + ks*32 + lkb));
        LDM4(qh[ks], QH + off);
    }

    const int nq0 = qt * 128 + w * 16 + r0;
    const int nq1 = nq0 + 8;
    const float polq0 = policy[b * N_ + nq0];
    const float polq1 = policy[b * N_ + nq1];
    const uint32_t pq0h = pack2h(polq0, polq0);
    const uint32_t pq1h = pack2h(polq1, polq1);

    float m0 = -1e30f, m1 = -1e30f;
    float lacc[4] = {};
    float O[8][4] = {};

    int sidx = 0;
    for (int kt = 0; kt < 8; kt++) {
        const uint32_t ST = ST0 + sidx * AST;
        const uint32_t* polKs = (const uint32_t*)(sbp + (PK0 - sb0) + sidx * 256);
        const bool diag = (kt == qt);

        #pragma unroll
        for (int half = 0; half < 2; half++) {
            // ---- S = Q K^T for this 64-key half ----
            float Sf[8][4] = {};
            #pragma unroll
            for (int ks = 0; ks < 4; ks++) {
                #pragma unroll
                for (int ng = 0; ng < 4; ng++) {
                    uint32_t kh4[4];
                    const int row = half*64 + ng*16 + lrow;
                    const uint32_t off = SWZ((uint32_t)(row * 128 + ks*32 + lkb));
                    LDM4(kh4, ST + off);
                    #pragma unroll
                    for (int hl = 0; hl < 2; hl++)
                        MMAH(Sf[2*ng+hl], qh[ks], kh4[hl], kh4[2+hl]);
                }
            }

            // ---- online softmax update (log2 domain) ----
            float t0 = -1e30f, t1 = -1e30f;
            #pragma unroll
            for (int nf = 0; nf < 8; nf++) {
                t0 = fmaxf(t0, fmaxf(Sf[nf][0], Sf[nf][1]));
                t1 = fmaxf(t1, fmaxf(Sf[nf][2], Sf[nf][3]));
            }
            t0 = fmaxf(t0, __shfl_xor_sync(0xffffffffu, t0, 1));
            t0 = fmaxf(t0, __shfl_xor_sync(0xffffffffu, t0, 2));
            t1 = fmaxf(t1, __shfl_xor_sync(0xffffffffu, t1, 1));
            t1 = fmaxf(t1, __shfl_xor_sync(0xffffffffu, t1, 2));
            const float mn0 = fmaxf(m0, t0), mn1 = fmaxf(m1, t1);
            const bool upd = (mn0 > m0) || (mn1 > m1);
            if (__ballot_sync(0xffffffffu, upd)) {
                const float rs0 = ex2(m0 - mn0), rs1 = ex2(m1 - mn1);
                lacc[0] *= rs0; lacc[1] *= rs0; lacc[2] *= rs1; lacc[3] *= rs1;
                #pragma unroll
                for (int nf = 0; nf < 8; nf++) {
                    O[nf][0] *= rs0; O[nf][1] *= rs0;
                    O[nf][2] *= rs1; O[nf][3] *= rs1;
                }
            }
            m0 = mn0; m1 = mn1;

            uint32_t ph[4][4];
            if (!diag) {
                // fast f16x2 path: p = ex2h2(S - m) * (polq * polK)
                #pragma unroll
                for (int nf = 0; nf < 8; nf++) {
                    const uint32_t pk = polKs[half*32 + nf*4 + (lane & 3)];
                    const uint32_t a0 = pack2h(Sf[nf][0] - m0, Sf[nf][1] - m0);
                    const uint32_t a1 = pack2h(Sf[nf][2] - m1, Sf[nf][3] - m1);
                    const int kc = nf >> 1, base = (nf & 1) * 2;
                    ph[kc][base]   = hmul2(ex2h2(a0), hmul2(pq0h, pk));
                    ph[kc][base+1] = hmul2(ex2h2(a1), hmul2(pq1h, pk));
                }
            } else {
                // exact fp32 path on the diagonal tile
                #pragma unroll
                for (int nf = 0; nf < 8; nf++) {
                    const uint32_t pkbits = polKs[half*32 + nf*4 + (lane & 3)];
                    __half2 pkh = *reinterpret_cast<const __half2*>(&pkbits);
                    const float pk0 = __low2float(pkh), pk1 = __high2float(pkh);
                    float mk00 = polq0 * pk0, mk01 = polq0 * pk1;
                    float mk10 = polq1 * pk0, mk11 = polq1 * pk1;
                    const int col = kt * 128 + half*64 + nf * 8 + c2;
                    if (col     == nq0) mk00 = 1.f;
                    if (col + 1 == nq0) mk01 = 1.f;
                    if (col     == nq1) mk10 = 1.f;
                    if (col + 1 == nq1) mk11 = 1.f;
                    const float p00 = ex2(Sf[nf][0] - m0) * mk00;
                    const float p01 = ex2(Sf[nf][1] - m0) * mk01;
                    const float p10 = ex2(Sf[nf][2] - m1) * mk10;
                    const float p11 = ex2(Sf[nf][3] - m1) * mk11;
                    const int kc = nf >> 1, base = (nf & 1) * 2;
                    ph[kc][base]   = pack2h(p00, p01);
                    ph[kc][base+1] = pack2h(p10, p11);
                }
            }

            // ---- O += P V ; l += P * ones ----
            #pragma unroll
            for (int kc = 0; kc < 4; kc++) {
                MMAH(lacc, ph[kc], ONESH, ONESH);
                #pragma unroll
                for (int ng = 0; ng < 4; ng++) {
                    uint32_t vh4[4];
                    const int vrow = half*64 + kc*16 + lrow;
                    const uint32_t off = SWZ((uint32_t)(vrow * 128 + ng*32 + lkb));
                    LDM4T(vh4, ST + 16384 + off);
                    #pragma unroll
                    for (int hl = 0; hl < 2; hl++)
                        MMAH(O[2*ng+hl], ph[kc], vh4[2*hl], vh4[2*hl+1]);
                }
            }
        }

        __syncthreads();    // stage consumed
        if (kt + 2 < 8) {
            const int kt2 = kt + 2;
            #pragma unroll
            for (int i = 0; i < 4; i++) {
                const int r = rb + 32 * i;
                const uint32_t d = SWZ((uint32_t)(r * 128 + g8 * 16));
                const size_t src = (bhN + kt2 * 128 + r) * HD + g8 * 8;
                cpa16(ST + 0*16384 + d, g_kh + src);
                cpa16(ST + 1*16384 + d, g_vh + src);
            }
            if (tid < 16) cpa16(PK0 + sidx * 256 + tid * 16,
                                g_polh + b * N_ + kt2 * 128 + tid * 8);
        }
        CP_COMMIT();
        if (kt + 1 < 8) { CP_WAIT1(); __syncthreads(); }
        sidx ^= 1;
    }

    // ---- epilogue: (O + eps/N * vsum) / (l + eps) -> fp16 aout ----
    const float inv0 = 1.f / (lacc[0] + EPS);
    const float inv1 = 1.f / (lacc[2] + EPS);
    #pragma unroll
    for (int nf = 0; nf < 8; nf++) {
        const int col = nf * 8 + c2;
        const float vs0 = g_vsum[bh * HD + col];
        const float vs1 = g_vsum[bh * HD + col + 1];
        const float o00 = (O[nf][0] + EPSN * vs0) * inv0;
        const float o01 = (O[nf][1] + EPSN * vs1) * inv0;
        const float o10 = (O[nf][2] + EPSN * vs0) * inv1;
        const float o11 = (O[nf][3] + EPSN * vs1) * inv1;
        const size_t i0 = (((size_t)(b * N_ + nq0)) * C_ + h * HD + col) >> 1;
        ((uint32_t*)g_ah)[i0] = pack2h(o00, o01);
        const size_t i1 = (((size_t)(b * N_ + nq1)) * C_ + h * HD + col) >> 1;
        ((uint32_t*)g_ah)[i1] = pack2h(o10, o11);
    }
}

// ---------------------------------------------------------------------------
extern "C" void kernel_launch(void* const* d_in, const int* in_sizes, int n_in,
                              void* d_out, int out_size) {
    const float* x      = (const float*)d_in[0];
    const float* policy = (const float*)d_in[1];
    const float* Wqkv   = (const float*)d_in[2];
    const float* Wproj  = (const float*)d_in[3];
    const float* bproj  = (const float*)d_in[4];
    float* out = (float*)d_out;

    __half *xh, *wqh, *wph, *ah;
    cudaGetSymbolAddress((void**)&xh,  g_xh);
    cudaGetSymbolAddress((void**)&wqh, g_wqh);
    cudaGetSymbolAddress((void**)&wph, g_wph);
    cudaGetSymbolAddress((void**)&ah,  g_ah);

    cudaFuncSetAttribute(mma_gemm_kernel,
                         cudaFuncAttributeMaxDynamicSharedMemorySize, 99328);
    cudaFuncSetAttribute(attn_mma_kernel,
                         cudaFuncAttributeMaxDynamicSharedMemorySize, 83968);

    const int qtotal = NX4 + NWQ4 + NWP4 + NP4;
    quant_all_kernel<<<(qtotal + 255)/256, 256>>>(x, Wqkv, Wproj, policy);

    mma_gemm_kernel<<<dim3(QKV_N/128, M_TOT/128), 256, 99328>>>(
        xh, wqh, nullptr, nullptr, 0);

    vsum_kernel<<<B_*H_, 256>>>();

    attn_mma_kernel<<<dim3(8, 96), 256, 83968>>>(policy);

    mma_gemm_kernel<<<dim3(C_/128, M_TOT/128), 256, 99328>>>(
        ah, wph, bproj, out, 1);
}

// round 16
// speedup vs baseline: 7.4917x; 1.0112x over previous
#include <cuda_runtime.h>
#include <cuda_fp16.h>
#include <cstdint>

#define B_ 8
#define N_ 1024
#define C_ 768
#define H_ 12
#define HD 64
#define M_TOT (B_*N_)
#define QKV_N (3*C_)
#define EPS 1e-6f
#define EPSN (1e-6f/1024.0f)
#define SC2E 0.18033688011112042f
#define SWZ(b) ((b) ^ (((b) >> 3) & 0x70))

__device__ __forceinline__ uint32_t smem_to_u32(const void* p) {
    uint32_t a;
    asm("{ .reg .u64 t; cvta.to.shared.u64 t, %1; cvt.u32.u64 %0, t; }" : "=r"(a) : "l"(p));
    return a;
}
__device__ __forceinline__ void cpa16(uint32_t dst, const void* src) {
    asm volatile("cp.async.cg.shared.global [%0], [%1], 16;" :: "r"(dst), "l"(src));
}
#define CP_COMMIT() asm volatile("cp.async.commit_group;" ::: "memory")
#define CP_WAIT1()  asm volatile("cp.async.wait_group 1;" ::: "memory")
#define CP_WAIT2()  asm volatile("cp.async.wait_group 2;" ::: "memory")
#define LDM4(r, a) \
    asm volatile("ldmatrix.sync.aligned.m8n8.x4.shared.b16 {%0,%1,%2,%3}, [%4];" \
        : "=r"((r)[0]), "=r"((r)[1]), "=r"((r)[2]), "=r"((r)[3]) : "r"(a))
#define LDM4T(r, a) \
    asm volatile("ldmatrix.sync.aligned.m8n8.x4.trans.shared.b16 {%0,%1,%2,%3}, [%4];" \
        : "=r"((r)[0]), "=r"((r)[1]), "=r"((r)[2]), "=r"((r)[3]) : "r"(a))
#define MMAH(d, a, b0, b1) \
    asm volatile("mma.sync.aligned.m16n8k16.row.col.f32.f16.f16.f32 " \
        "{%0,%1,%2,%3}, {%4,%5,%6,%7}, {%8,%9}, {%0,%1,%2,%3};" \
        : "+f"((d)[0]), "+f"((d)[1]), "+f"((d)[2]), "+f"((d)[3]) \
        : "r"((a)[0]), "r"((a)[1]), "r"((a)[2]), "r"((a)[3]), "r"(b0), "r"(b1))

__device__ __forceinline__ uint32_t pack2h(float e0, float e1) {
    uint32_t r;
    asm("cvt.rn.f16x2.f32 %0, %1, %2;" : "=r"(r) : "f"(e1), "f"(e0));
    return r;
}
__device__ __forceinline__ float ex2(float x) {
    float y; asm("ex2.approx.f32 %0, %1;" : "=f"(y) : "f"(x)); return y;
}
__device__ __forceinline__ uint32_t ex2h2(uint32_t x) {
    uint32_t y; asm("ex2.approx.f16x2 %0, %1;" : "=r"(y) : "r"(x)); return y;
}
__device__ __forceinline__ uint32_t hmul2(uint32_t a, uint32_t b) {
    uint32_t y; asm("mul.f16x2 %0, %1, %2;" : "=r"(y) : "r"(a), "r"(b)); return y;
}

// --------------------------- scratch ---------------------------------------
__device__ __half g_xh[M_TOT*C_];
__device__ __half g_wqh[QKV_N*C_];
__device__ __half g_wph[C_*C_];
__device__ __half g_polh[B_*N_];                           // policy fp16
__device__ __half g_qh[B_*H_*N_*HD];                       // Q pre-scaled fp16
__device__ __half g_kh[B_*H_*N_*HD];                       // K fp16
__device__ __half g_vh[B_*H_*N_*HD];                       // V fp16
__device__ __half g_ah[M_TOT*C_];                          // aout fp16
__device__ float g_vsum[B_*H_*HD];

// -------- fused fp32 -> fp16 quant (x | Wqkv | Wproj | policy) --------------
#define NX4  (M_TOT*C_/4)
#define NWQ4 (QKV_N*C_/4)
#define NWP4 (C_*C_/4)
#define NP4  (B_*N_/4)
__global__ __launch_bounds__(256) void quant_all_kernel(const float* __restrict__ x,
                                                        const float* __restrict__ wq,
                                                        const float* __restrict__ wp,
                                                        const float* __restrict__ pol) {
    int i = blockIdx.x * 256 + threadIdx.x;
    const float* in; __half* outp; int j = i;
    if (j < NX4) { in = x; outp = g_xh; }
    else if ((j -= NX4) < NWQ4) { in = wq; outp = g_wqh; }
    else if ((j -= NWQ4) < NWP4) { in = wp; outp = g_wph; }
    else if ((j -= NWP4) < NP4) { in = pol; outp = g_polh; }
    else return;
    float4 v = ((const float4*)in)[j];
    ((uint32_t*)outp)[2*j]   = pack2h(v.x, v.y);
    ((uint32_t*)outp)[2*j+1] = pack2h(v.z, v.w);
}

// --------------- fp16 tensor-core GEMM (qkv / proj) -------------------------
// D = A * B^T. 12 K-chunks of 64, 3-stage pipeline, 2 CTAs/SM.
#define GST 32768
__device__ __forceinline__ void load_chunk(uint32_t sb,
    const __half* __restrict__ Ah, const __half* __restrict__ Bh,
    int bm, int bn, int kc, int tid)
{
    const int g = tid & 7;
    const int rb = tid >> 3;
    const int koff = kc * 64 + g * 8;
    #pragma unroll
    for (int i = 0; i < 4; i++) {
        const int r = rb + 32 * i;
        const uint32_t d = SWZ((uint32_t)(r * 128 + g * 16));
        cpa16(sb + 0*16384 + d, Ah + (size_t)(bm + r) * C_ + koff);
        cpa16(sb + 1*16384 + d, Bh + (size_t)(bn + r) * C_ + koff);
    }
}

__global__ __launch_bounds__(256, 2) void mma_gemm_kernel(
    const __half* __restrict__ Ah, const __half* __restrict__ Bh,
    const float* __restrict__ bias, float* __restrict__ outp, int mode)
{
    extern __shared__ char dsmem[];
    const int tid = threadIdx.x, wid = tid >> 5, lane = tid & 31;
    const int wm = wid >> 2, wn = wid & 3;
    const uint32_t sb0 = (smem_to_u32(dsmem) + 1023u) & ~1023u;

    const int bm = blockIdx.y * 128, bn = blockIdx.x * 128;
    const int lrow = (lane & 7) + ((lane >> 3) & 1) * 8;
    const int lkb  = (lane >> 4) * 16;

    float acc[4][4][4] = {};

    load_chunk(sb0,         Ah, Bh, bm, bn, 0, tid); CP_COMMIT();
    load_chunk(sb0 + GST,   Ah, Bh, bm, bn, 1, tid); CP_COMMIT();
    load_chunk(sb0 + 2*GST, Ah, Bh, bm, bn, 2, tid); CP_COMMIT();

    int sidx = 0;
    for (int i = 0; i < 12; i++) {
        CP_WAIT2();
        __syncthreads();
        const uint32_t sb = sb0 + sidx * GST;
        #pragma unroll
        for (int ks = 0; ks < 4; ks++) {
            uint32_t ah[4][4];
            #pragma unroll
            for (int mi = 0; mi < 4; mi++) {
                const uint32_t off =
                    SWZ((uint32_t)((wm*64 + mi*16 + lrow) * 128 + ks*32 + lkb));
                LDM4(ah[mi], sb + 0*16384 + off);
            }
            uint32_t bh[2][4];
            #pragma unroll
            for (int nb = 0; nb < 2; nb++) {
                const uint32_t off =
                    SWZ((uint32_t)((wn*32 + nb*16 + lrow) * 128 + ks*32 + lkb));
                LDM4(bh[nb], sb + 1*16384 + off);
            }
            #pragma unroll
            for (int mi = 0; mi < 4; mi++)
                #pragma unroll
                for (int ni = 0; ni < 4; ni++) {
                    const int nb = ni >> 1, hl = ni & 1;
                    MMAH(acc[mi][ni], ah[mi], bh[nb][hl], bh[nb][2+hl]);
                }
        }
        __syncthreads();
        if (i + 3 < 12) load_chunk(sb, Ah, Bh, bm, bn, i + 3, tid);
        CP_COMMIT();
        sidx = (sidx == 2) ? 0 : sidx + 1;
    }

    const int g = lane >> 2, c2 = (lane & 3) * 2;
    #pragma unroll
    for (int mi = 0; mi < 4; mi++)
        #pragma unroll
        for (int ni = 0; ni < 4; ni++) {
            const int col = bn + wn*32 + ni*8 + c2;
            #pragma unroll
            for (int half = 0; half < 2; half++) {
                const int m = bm + wm*64 + mi*16 + g + half*8;
                float d0 = acc[mi][ni][half*2], d1 = acc[mi][ni][half*2+1];
                if (mode == 0) {
                    const int which = col / C_;
                    const int rest = col - which * C_;
                    const int h = rest >> 6, dd = rest & 63;
                    const int b = m >> 10, tok = m & 1023;
                    const size_t idx = (((size_t)(b * H_ + h) * N_ + tok) * HD + dd) >> 1;
                    if (which == 0) {        // Q: scaled single fp16
                        ((uint32_t*)g_qh)[idx] = pack2h(d0 * SC2E, d1 * SC2E);
                    } else if (which == 1) { // K
                        ((uint32_t*)g_kh)[idx] = pack2h(d0, d1);
                    } else {                 // V
                        ((uint32_t*)g_vh)[idx] = pack2h(d0, d1);
                    }
                } else {
                    float* p = outp + (size_t)m * C_ + col;
                    p[0] = d0 + bias[col];
                    p[1] = d1 + bias[col + 1];
                }
            }
        }
}

// --------------------- V row-sum per (b,h) ----------------------------------
__global__ __launch_bounds__(256) void vsum_kernel() {
    const int bh = blockIdx.x;
    const int wid = threadIdx.x >> 5, lane = threadIdx.x & 31;
    __shared__ float sm[8][64];
    float a0 = 0.f, a1 = 0.f;
    for (int n = wid * 128; n < wid * 128 + 128; n++) {
        const size_t idx = (((size_t)bh * N_ + n) * HD >> 1) + lane;
        uint32_t hv = ((const uint32_t*)g_vh)[idx];
        __half2 h = *reinterpret_cast<__half2*>(&hv);
        a0 += __low2float(h);
        a1 += __high2float(h);
    }
    sm[wid][lane*2] = a0; sm[wid][lane*2+1] = a1;
    __syncthreads();
    if (threadIdx.x < 64) {
        float s = 0.f;
        #pragma unroll
        for (int w = 0; w < 8; w++) s += sm[w][threadIdx.x];
        g_vsum[bh * HD + threadIdx.x] = s;
    }
}

// ------------------ tensor-core flash attention -----------------------------
// CTA = (128-q tile, b*h). 128-key tiles, 2-stage pipeline, 2 CTAs/SM.
// Fixed-base softmax: base mb = row max of tile 0 (one shuffle reduction);
// no in-loop rescale. True max tracked thread-locally, reduced once in the
// epilogue, and folded EXACTLY into the eps terms.
#define AST 32768
__global__ __launch_bounds__(256, 2) void attn_mma_kernel(const float* __restrict__ policy) {
    extern __shared__ char dsmem[];
    const uint32_t dbase = smem_to_u32(dsmem);
    const uint32_t sb0 = (dbase + 1023u) & ~1023u;
    char* sbp = dsmem + (sb0 - dbase);

    const int qt = blockIdx.x;          // 0..7
    const int bh = blockIdx.y;          // 0..95
    const int b  = bh / H_;
    const int h  = bh - b * H_;
    const int tid = threadIdx.x, w = tid >> 5, lane = tid & 31;
    const int lrow = (lane & 7) + ((lane >> 3) & 1) * 8;
    const int lkb  = (lane >> 4) * 16;
    const int c2   = (lane & 3) * 2;
    const int r0   = lane >> 2;

    const uint32_t QH = sb0;
    const uint32_t ST0 = sb0 + 16384;            // 2 stages x 32 KB
    const uint32_t PK0 = sb0 + 16384 + 2*AST;    // 2 x 256 B fp16 policy tiles

    const int g8 = tid & 7, rb = tid >> 3;
    const size_t bhN = (size_t)bh * N_;
    const uint32_t ONESH = 0x3C003C00u;          // half2(1,1)

    // ---- prologue: (Q + stage0) | stage1 ----
    #pragma unroll
    for (int i = 0; i < 4; i++) {
        const int r = rb + 32 * i;
        const uint32_t d = SWZ((uint32_t)(r * 128 + g8 * 16));
        cpa16(QH + d, g_qh + (bhN + qt * 128 + r) * HD + g8 * 8);
        const size_t src = (bhN + r) * HD + g8 * 8;
        cpa16(ST0 + 0*16384 + d, g_kh + src);
        cpa16(ST0 + 1*16384 + d, g_vh + src);
    }
    if (tid < 16) cpa16(PK0 + tid * 16, g_polh + b * N_ + tid * 8);
    CP_COMMIT();
    #pragma unroll
    for (int i = 0; i < 4; i++) {
        const int r = rb + 32 * i;
        const uint32_t d = SWZ((uint32_t)(r * 128 + g8 * 16));
        const size_t src = (bhN + 128 + r) * HD + g8 * 8;
        cpa16(ST0 + AST + 0*16384 + d, g_kh + src);
        cpa16(ST0 + AST + 1*16384 + d, g_vh + src);
    }
    if (tid < 16) cpa16(PK0 + 256 + tid * 16, g_polh + b * N_ + 128 + tid * 8);
    CP_COMMIT();
    CP_WAIT1();
    __syncthreads();

    // Q fragments (register-resident)
    uint32_t qh[4][4];
    #pragma unroll
    for (int ks = 0; ks < 4; ks++) {
        const uint32_t off = SWZ((uint32_t)((w*16 + lrow) * 128 + ks*32 + lkb));
        LDM4(qh[ks], QH + off);
    }

    const int nq0 = qt * 128 + w * 16 + r0;
    const int nq1 = nq0 + 8;
    const float polq0 = policy[b * N_ + nq0];
    const float polq1 = policy[b * N_ + nq1];
    const uint32_t pq0h = pack2h(polq0, polq0);
    const uint32_t pq1h = pack2h(polq1, polq1);

    float mb0 = 0.f, mb1 = 0.f;          // fixed exponent base (set at kt==0)
    float pm0 = -1e30f, pm1 = -1e30f;    // thread-local running max
    float lacc[4] = {};
    float O[8][4] = {};

    int sidx = 0;
    for (int kt = 0; kt < 8; kt++) {
        const uint32_t ST = ST0 + sidx * AST;
        const uint32_t* polKs = (const uint32_t*)(sbp + (PK0 - sb0) + sidx * 256);
        const bool diag = (kt == qt);

        #pragma unroll
        for (int half = 0; half < 2; half++) {
            // ---- S = Q K^T for this 64-key half ----
            float Sf[8][4] = {};
            #pragma unroll
            for (int ks = 0; ks < 4; ks++) {
                #pragma unroll
                for (int ng = 0; ng < 4; ng++) {
                    uint32_t kh4[4];
                    const int row = half*64 + ng*16 + lrow;
                    const uint32_t off = SWZ((uint32_t)(row * 128 + ks*32 + lkb));
                    LDM4(kh4, ST + off);
                    #pragma unroll
                    for (int hl = 0; hl < 2; hl++)
                        MMAH(Sf[2*ng+hl], qh[ks], kh4[hl], kh4[2+hl]);
                }
            }

            // ---- thread-local max update (no shuffles in steady state) ----
            float t0 = -1e30f, t1 = -1e30f;
            #pragma unroll
            for (int nf = 0; nf < 8; nf++) {
                t0 = fmaxf(t0, fmaxf(Sf[nf][0], Sf[nf][1]));
                t1 = fmaxf(t1, fmaxf(Sf[nf][2], Sf[nf][3]));
            }
            pm0 = fmaxf(pm0, t0);
            pm1 = fmaxf(pm1, t1);
            if (kt == 0 && half == 0) {
                // one-time base: exact row max of the first tile
                t0 = fmaxf(t0, __shfl_xor_sync(0xffffffffu, t0, 1));
                t0 = fmaxf(t0, __shfl_xor_sync(0xffffffffu, t0, 2));
                t1 = fmaxf(t1, __shfl_xor_sync(0xffffffffu, t1, 1));
                t1 = fmaxf(t1, __shfl_xor_sync(0xffffffffu, t1, 2));
                mb0 = t0; mb1 = t1;
            }

            uint32_t ph[4][4];
            if (!diag) {
                // fast f16x2 path: p = ex2h2(S - mb) * (polq * polK)
                #pragma unroll
                for (int nf = 0; nf < 8; nf++) {
                    const uint32_t pk = polKs[half*32 + nf*4 + (lane & 3)];
                    const uint32_t a0 = pack2h(Sf[nf][0] - mb0, Sf[nf][1] - mb0);
                    const uint32_t a1 = pack2h(Sf[nf][2] - mb1, Sf[nf][3] - mb1);
                    const int kc = nf >> 1, base = (nf & 1) * 2;
                    ph[kc][base]   = hmul2(ex2h2(a0), hmul2(pq0h, pk));
                    ph[kc][base+1] = hmul2(ex2h2(a1), hmul2(pq1h, pk));
                }
            } else {
                // exact fp32 path on the diagonal tile
                #pragma unroll
                for (int nf = 0; nf < 8; nf++) {
                    const uint32_t pkbits = polKs[half*32 + nf*4 + (lane & 3)];
                    __half2 pkh = *reinterpret_cast<const __half2*>(&pkbits);
                    const float pk0 = __low2float(pkh), pk1 = __high2float(pkh);
                    float mk00 = polq0 * pk0, mk01 = polq0 * pk1;
                    float mk10 = polq1 * pk0, mk11 = polq1 * pk1;
                    const int col = kt * 128 + half*64 + nf * 8 + c2;
                    if (col     == nq0) mk00 = 1.f;
                    if (col + 1 == nq0) mk01 = 1.f;
                    if (col     == nq1) mk10 = 1.f;
                    if (col + 1 == nq1) mk11 = 1.f;
                    const float p00 = ex2(Sf[nf][0] - mb0) * mk00;
                    const float p01 = ex2(Sf[nf][1] - mb0) * mk01;
                    const float p10 = ex2(Sf[nf][2] - mb1) * mk10;
                    const float p11 = ex2(Sf[nf][3] - mb1) * mk11;
                    const int kc = nf >> 1, base = (nf & 1) * 2;
                    ph[kc][base]   = pack2h(p00, p01);
                    ph[kc][base+1] = pack2h(p10, p11);
                }
            }

            // ---- O += P V ; l += P * ones ----
            #pragma unroll
            for (int kc = 0; kc < 4; kc++) {
                MMAH(lacc, ph[kc], ONESH, ONESH);
                #pragma unroll
                for (int ng = 0; ng < 4; ng++) {
                    uint32_t vh4[4];
                    const int vrow = half*64 + kc*16 + lrow;
                    const uint32_t off = SWZ((uint32_t)(vrow * 128 + ng*32 + lkb));
                    LDM4T(vh4, ST + 16384 + off);
                    #pragma unroll
                    for (int hl = 0; hl < 2; hl++)
                        MMAH(O[2*ng+hl], ph[kc], vh4[2*hl], vh4[2*hl+1]);
                }
            }
        }

        __syncthreads();    // stage consumed
        if (kt + 2 < 8) {
            const int kt2 = kt + 2;
            #pragma unroll
            for (int i = 0; i < 4; i++) {
                const int r = rb + 32 * i;
                const uint32_t d = SWZ((uint32_t)(r * 128 + g8 * 16));
                const size_t src = (bhN + kt2 * 128 + r) * HD + g8 * 8;
                cpa16(ST + 0*16384 + d, g_kh + src);
                cpa16(ST + 1*16384 + d, g_vh + src);
            }
            if (tid < 16) cpa16(PK0 + sidx * 256 + tid * 16,
                                g_polh + b * N_ + kt2 * 128 + tid * 8);
        }
        CP_COMMIT();
        if (kt + 1 < 8) { CP_WAIT1(); __syncthreads(); }
        sidx ^= 1;
    }

    // ---- epilogue: exact eps correction for the base shift ----
    // A = a_ref * 2^(mt-mb)  =>  out = (O + EPSN*2^(mt-mb)*vsum)/(l + EPS*2^(mt-mb))
    pm0 = fmaxf(pm0, __shfl_xor_sync(0xffffffffu, pm0, 1));
    pm0 = fmaxf(pm0, __shfl_xor_sync(0xffffffffu, pm0, 2));
    pm1 = fmaxf(pm1, __shfl_xor_sync(0xffffffffu, pm1, 1));
    pm1 = fmaxf(pm1, __shfl_xor_sync(0xffffffffu, pm1, 2));
    const float c0 = ex2(pm0 - mb0);
    const float c1 = ex2(pm1 - mb1);
    const float e0 = EPSN * c0, e1 = EPSN * c1;
    const float inv0 = 1.f / (lacc[0] + EPS * c0);
    const float inv1 = 1.f / (lacc[2] + EPS * c1);
    #pragma unroll
    for (int nf = 0; nf < 8; nf++) {
        const int col = nf * 8 + c2;
        const float vs0 = g_vsum[bh * HD + col];
        const float vs1 = g_vsum[bh * HD + col + 1];
        const float o00 = (O[nf][0] + e0 * vs0) * inv0;
        const float o01 = (O[nf][1] + e0 * vs1) * inv0;
        const float o10 = (O[nf][2] + e1 * vs0) * inv1;
        const float o11 = (O[nf][3] + e1 * vs1) * inv1;
        const size_t i0 = (((size_t)(b * N_ + nq0)) * C_ + h * HD + col) >> 1;
        ((uint32_t*)g_ah)[i0] = pack2h(o00, o01);
        const size_t i1 = (((size_t)(b * N_ + nq1)) * C_ + h * HD + col) >> 1;
        ((uint32_t*)g_ah)[i1] = pack2h(o10, o11);
    }
}

// ---------------------------------------------------------------------------
extern "C" void kernel_launch(void* const* d_in, const int* in_sizes, int n_in,
                              void* d_out, int out_size) {
    const float* x      = (const float*)d_in[0];
    const float* policy = (const float*)d_in[1];
    const float* Wqkv   = (const float*)d_in[2];
    const float* Wproj  = (const float*)d_in[3];
    const float* bproj  = (const float*)d_in[4];
    float* out = (float*)d_out;

    __half *xh, *wqh, *wph, *ah;
    cudaGetSymbolAddress((void**)&xh,  g_xh);
    cudaGetSymbolAddress((void**)&wqh, g_wqh);
    cudaGetSymbolAddress((void**)&wph, g_wph);
    cudaGetSymbolAddress((void**)&ah,  g_ah);

    cudaFuncSetAttribute(mma_gemm_kernel,
                         cudaFuncAttributeMaxDynamicSharedMemorySize, 99328);
    cudaFuncSetAttribute(attn_mma_kernel,
                         cudaFuncAttributeMaxDynamicSharedMemorySize, 83968);

    const int qtotal = NX4 + NWQ4 + NWP4 + NP4;
    quant_all_kernel<<<(qtotal + 255)/256, 256>>>(x, Wqkv, Wproj, policy);

    mma_gemm_kernel<<<dim3(QKV_N/128, M_TOT/128), 256, 99328>>>(
        xh, wqh, nullptr, nullptr, 0);

    vsum_kernel<<<B_*H_, 256>>>();

    attn_mma_kernel<<<dim3(8, 96), 256, 83968>>>(policy);

    mma_gemm_kernel<<<dim3(C_/128, M_TOT/128), 256, 99328>>>(
        ah, wph, bproj, out, 1);
}